// round 4
// baseline (speedup 1.0000x reference)
#include <cuda_runtime.h>
#include <math.h>

#define FN   1024
#define NB   4
#define FNN  (FN*FN)
#define TOT  (NB*FNN)
#define WD   518
#define SLL  (NB*WD*WD)
#define SLW  (NB*FN*WD)
#define PIF  3.14159265358979323846f

// ---------------- static device scratch ----------------
__device__ float2 g_CA[TOT];
__device__ float2 g_CB[TOT];
__device__ float2 g_UKER[TOT];
__device__ float2 g_F0[TOT];
__device__ float2 g_MURF[TOT];

__device__ float g_U[TOT];
__device__ float g_DX[TOT];
__device__ float g_DY[TOT];
__device__ float g_BX[TOT];
__device__ float g_BY[TOT];
__device__ float g_IDWT[TOT];

__device__ float g_WL[SLL];
__device__ float g_BWL[SLL];
__device__ float g_UL[SLL];
__device__ float g_WH[3*SLL];
__device__ float g_BWH[3*SLL];
__device__ float g_UH[3*SLL];
__device__ float g_LOT[SLW];
__device__ float g_HIT[SLW];
__device__ float g_LOS[SLW];
__device__ float g_HIS[SLW];

// ---------------- wavelet filters (db7, L=14) ----------------
__constant__ float cH0A[14] = {
    0.010268176708511255f, 0.004010244871533663f, -0.10780823770381774f,
   -0.14004724044296152f, 0.2886296317515146f, 0.767764317003164f,
    0.5361019170917628f, 0.017441255086855827f, -0.049552834937127255f,
    0.0678926935013727f, 0.03051551316596357f, -0.01263630340325193f,
   -0.0010473848886829163f, 0.002681814568257878f };
__constant__ float cH1A[14] = {
    0.002681814568257878f, 0.0010473848886829163f, -0.01263630340325193f,
   -0.03051551316596357f, 0.0678926935013727f, 0.049552834937127255f,
    0.017441255086855827f, -0.5361019170917628f, 0.767764317003164f,
   -0.2886296317515146f, -0.14004724044296152f, 0.10780823770381774f,
    0.004010244871533663f, -0.010268176708511255f };
__constant__ float cG0[14] = {
    0.002681814568257878f, -0.0010473848886829163f, -0.01263630340325193f,
    0.03051551316596357f, 0.0678926935013727f, -0.049552834937127255f,
    0.017441255086855827f, 0.5361019170917628f, 0.767764317003164f,
    0.2886296317515146f, -0.14004724044296152f, -0.10780823770381774f,
    0.004010244871533663f, 0.010268176708511255f };
__constant__ float cG1[14] = {
   -0.010268176708511255f, 0.004010244871533663f, 0.10780823770381774f,
   -0.14004724044296152f, -0.2886296317515146f, 0.767764317003164f,
   -0.5361019170917628f, 0.017441255086855827f, 0.049552834937127255f,
    0.0678926935013727f, -0.03051551316596357f, -0.01263630340325193f,
    0.0010473848886829163f, 0.002681814568257878f };

__device__ __forceinline__ float2 cmulf(float2 a, float2 b) {
    return make_float2(a.x*b.x - a.y*b.y, a.x*b.y + a.y*b.x);
}

// ---------------- 1024-pt Stockham FFT over rows ----------------
__global__ __launch_bounds__(512) void k_fft(const void* __restrict__ srcv,
                                             void* __restrict__ dstv,
                                             int inReal, int outReal, int inverse,
                                             float scale,
                                             const float* __restrict__ prelu)
{
    __shared__ float2 sA[FN];
    __shared__ float2 sB[FN];
    __shared__ float2 tw[FN/2];
    int t = threadIdx.x;
    int row = blockIdx.x;
    float sv, cv;
    sincosf(-2.f*PIF*(float)t/(float)FN, &sv, &cv);
    tw[t] = make_float2(cv, inverse ? -sv : sv);
    if (inReal) {
        const float* src = (const float*)srcv + (size_t)row*FN;
        sA[t]     = make_float2(src[t], 0.f);
        sA[t+512] = make_float2(src[t+512], 0.f);
    } else {
        const float2* src = (const float2*)srcv + (size_t)row*FN;
        sA[t]     = src[t];
        sA[t+512] = src[t+512];
    }
    __syncthreads();
    float2* X = sA; float2* Y = sB;
#pragma unroll
    for (int s = 0; s < 10; ++s) {
        int ns = 1 << s;
        int k  = t & (ns - 1);
        float2 a = X[t];
        float2 b = X[t + 512];
        float2 w = tw[k << (9 - s)];
        float2 wb = cmulf(w, b);
        int j = ((t - k) << 1) + k;
        Y[j]      = make_float2(a.x + wb.x, a.y + wb.y);
        Y[j + ns] = make_float2(a.x - wb.x, a.y - wb.y);
        __syncthreads();
        float2* tmp = X; X = Y; Y = tmp;
    }
    if (!outReal) {
        float2* dst = (float2*)dstv + (size_t)row*FN;
        float2 v0 = X[t], v1 = X[t+512];
        dst[t]     = make_float2(v0.x*scale, v0.y*scale);
        dst[t+512] = make_float2(v1.x*scale, v1.y*scale);
    } else {
        float a = prelu[0];
        float* dst = (float*)dstv + (size_t)row*FN;
        float v = X[t].x * scale;
        dst[t]     = (v >= 0.f) ? v : a*v;
        v = X[t+512].x * scale;
        dst[t+512] = (v >= 0.f) ? v : a*v;
    }
}

// ---------------- complex transpose ----------------
__global__ void k_transpose_c(const float2* __restrict__ src, float2* __restrict__ dst)
{
    __shared__ float2 tile[32][33];
    int b = blockIdx.z;
    const float2* s = src + (size_t)b*FNN;
    float2* d = dst + (size_t)b*FNN;
    int x  = blockIdx.x*32 + threadIdx.x;
    int y0 = blockIdx.y*32 + threadIdx.y;
#pragma unroll
    for (int i = 0; i < 32; i += 8)
        tile[threadIdx.y+i][threadIdx.x] = s[(size_t)(y0+i)*FN + x];
    __syncthreads();
    int x2 = blockIdx.y*32 + threadIdx.x;
    int y2 = blockIdx.x*32 + threadIdx.y;
#pragma unroll
    for (int i = 0; i < 32; i += 8)
        d[(size_t)(y2+i)*FN + x2] = tile[threadIdx.x][threadIdx.y+i];
}

// ---------------- small init kernels ----------------
__global__ void k_pack_f0(const float* __restrict__ fr, const float* __restrict__ fi)
{
    int i = blockIdx.x*blockDim.x + threadIdx.x;
    if (i >= TOT) return;
    g_F0[i] = make_float2(fr[i], fi[i]);
}

__global__ void k_sten()   // write 5-point stencil into g_U (zeroed beforehand)
{
    int t = threadIdx.x;
    if (t >= NB*5) return;
    int b = t / 5, p = t % 5;
    size_t base = (size_t)b*FNN;
    const int yy[5] = {1, 1, 2, FN-1, 1};
    const int xx[5] = {1, 2, 1, 1, FN-1};
    const float vv[5] = {4.f, -1.f, -1.f, -1.f, -1.f};
    g_U[base + (size_t)yy[p]*FN + xx[p]] = vv[p];
}

// UKER = mmu*mask^2 + gama + lam*STEN_FFT   (STEN_FFT in g_CB, normal layout)
__global__ void k_uker2(const float* __restrict__ mask,
                        const float* __restrict__ lam, const float* __restrict__ gama,
                        const float* __restrict__ mmu)
{
    int i = blockIdx.x*blockDim.x + threadIdx.x;
    if (i >= TOT) return;
    float m = mask[i];
    float2 sf = g_CB[i];
    float lv = lam[0];
    g_UKER[i] = make_float2(mmu[0]*m*m + gama[0] + lv*sf.x, lv*sf.y);
}

__global__ void k_maskf(const float* __restrict__ mask)   // CA = mask * F0
{
    int i = blockIdx.x*blockDim.x + threadIdx.x;
    if (i >= TOT) return;
    float m = mask[i];
    float2 f0 = g_F0[i];
    g_CA[i] = make_float2(m*f0.x, m*f0.y);
}

__global__ void k_div_uker(float2* __restrict__ Z)
{
    int i = blockIdx.x*blockDim.x + threadIdx.x;
    if (i >= TOT) return;
    float2 z = Z[i], w = g_UKER[i];
    float d = 1.f/(w.x*w.x + w.y*w.y);
    Z[i] = make_float2((z.x*w.x + z.y*w.y)*d, (z.y*w.x - z.x*w.y)*d);
}

// CA = mask*(2*F0 - mask*FU)   with FU in g_CB (normal layout)
__global__ void k_fupd(const float* __restrict__ mask)
{
    int i = blockIdx.x*blockDim.x + threadIdx.x;
    if (i >= TOT) return;
    float m = mask[i];
    float2 f0 = g_F0[i];
    float2 fu = g_CB[i];
    g_CA[i] = make_float2(m*(2.f*f0.x - m*fu.x), m*(2.f*f0.y - m*fu.y));
}

// ---------------- spatial elementwise ----------------
__global__ void k_rhs(const float* __restrict__ lam, const float* __restrict__ gama,
                      const float* __restrict__ mmu)
{
    int i = blockIdx.x*blockDim.x + threadIdx.x;
    if (i >= TOT) return;
    int x = i & (FN-1);
    int y = (i >> 10) & (FN-1);
    int rowb = i - x;
    float dxt = 0.f;
    if (x >= 1) {
        int xn = (x == FN-1) ? 1 : x+1;
        float v0 = g_DX[i] - g_BX[i];
        float v1 = g_DX[rowb + xn] - g_BX[rowb + xn];
        dxt = v0 - v1;
    }
    float dyt = 0.f;
    if (y >= 1) {
        int yn = (y == FN-1) ? 1 : y+1;
        int j = i + (yn - y)*FN;
        float v0 = g_DY[i] - g_BY[i];
        float v1 = g_DY[j] - g_BY[j];
        dyt = v0 - v1;
    }
    float2 mu = g_MURF[i];
    float mv = mmu[0];
    g_CA[i] = make_float2(mv*mu.x + lam[0]*(dxt + dyt) + gama[0]*g_IDWT[i], mv*mu.y);
}

__global__ void k_shrink(const float* __restrict__ lam, const float* __restrict__ prelu)
{
    int i = blockIdx.x*blockDim.x + threadIdx.x;
    if (i >= TOT) return;
    float a  = prelu[0];
    float il = 1.f/lam[0];
    float vx = g_DX[i] + g_BX[i];
    float vy = g_DY[i] + g_BY[i];
    float s = sqrtf(vx*vx + vy*vy);
    float nx = vx - s*il;
    float ny = vy - s*il;
    g_DX[i] = (nx >= 0.f) ? nx : a*nx;
    g_DY[i] = (ny >= 0.f) ? ny : a*ny;
}

__global__ void k_bxy()
{
    int i = blockIdx.x*blockDim.x + threadIdx.x;
    if (i >= TOT) return;
    int x = i & (FN-1);
    int y = (i >> 10) & (FN-1);
    int rowb = i - x;
    float dxu = 0.f;
    if (x >= 1) {
        int xm = (x == 1) ? FN-1 : x-1;
        dxu = g_U[i] - g_U[rowb + xm];
    }
    g_BX[i] += dxu - g_DX[i];
    float dyu = 0.f;
    if (y >= 1) {
        int ym = (y == 1) ? FN-1 : y-1;
        dyu = g_U[i] - g_U[i + (ym - y)*FN];
    }
    g_BY[i] += dyu - g_DY[i];
}

__global__ void k_wupd(const float* __restrict__ uarr, float* __restrict__ bw,
                       float* __restrict__ w, int n,
                       const float* __restrict__ gama, const float* __restrict__ prelu)
{
    int i = blockIdx.x*blockDim.x + threadIdx.x;
    if (i >= n) return;
    float a  = prelu[0];
    float ig = 1.f/gama[0];
    float uv = uarr[i], bv = bw[i];
    float t = uv + bv - ig;
    float wv = (t >= 0.f) ? t : a*t;
    w[i]  = wv;
    bw[i] = bv + uv - wv;
}

// ---------------- DWT analysis ----------------
__global__ void k_afb_w(const float* __restrict__ src, float* __restrict__ lo,
                        float* __restrict__ hi)
{
    int i = blockIdx.x*blockDim.x + threadIdx.x;
    if (i >= NB*FN*WD) return;
    int o = i % WD;
    int r = i / WD;
    const float* row = src + (size_t)r*FN;
    float l = 0.f, h = 0.f;
#pragma unroll
    for (int k = 0; k < 14; ++k) {
        int j = 2*o + k - 12;
        j = (j < 0) ? -j : ((j >= FN) ? (2*FN - 2 - j) : j);
        float v = row[j];
        l += v * cH0A[k];
        h += v * cH1A[k];
    }
    lo[i] = l;
    hi[i] = h;
}

__global__ void k_afb_h(const float* __restrict__ src, float* __restrict__ lo,
                        float* __restrict__ hi)
{
    int i = blockIdx.x*blockDim.x + threadIdx.x;
    if (i >= SLL) return;
    int w = i % WD;
    int o = (i / WD) % WD;
    int b = i / (WD*WD);
    const float* base = src + (size_t)b*FN*WD;
    float l = 0.f, h = 0.f;
#pragma unroll
    for (int k = 0; k < 14; ++k) {
        int j = 2*o + k - 12;
        j = (j < 0) ? -j : ((j >= FN) ? (2*FN - 2 - j) : j);
        float v = base[(size_t)j*WD + w];
        l += v * cH0A[k];
        h += v * cH1A[k];
    }
    lo[i] = l;
    hi[i] = h;
}

// ---------------- IDWT synthesis ----------------
__global__ void k_sfb_h(const float* __restrict__ loA, const float* __restrict__ loB,
                        const float* __restrict__ hiA, const float* __restrict__ hiB,
                        float* __restrict__ out)
{
    int i = blockIdx.x*blockDim.x + threadIdx.x;
    if (i >= NB*FN*WD) return;
    int w = i % WD;
    int o = (i / WD) % FN;
    int b = i / (FN*WD);
    size_t bb = (size_t)b*WD*WD;
    float acc = 0.f;
    int k0 = (o + 1) & 1;
#pragma unroll
    for (int kk = 0; kk < 7; ++kk) {
        int k = k0 + 2*kk;
        int m = (o + k - 1) >> 1;
        size_t idx = bb + (size_t)m*WD + w;
        float lo = loA[idx] - loB[idx];
        float hi = hiA[idx] - hiB[idx];
        acc += lo * cG0[k] + hi * cG1[k];
    }
    out[i] = acc;
}

__global__ void k_sfb_w(const float* __restrict__ lo, const float* __restrict__ hi,
                        float* __restrict__ out)
{
    int i = blockIdx.x*blockDim.x + threadIdx.x;
    if (i >= TOT) return;
    int x = i & (FN-1);
    int r = i >> 10;
    const float* lrow = lo + (size_t)r*WD;
    const float* hrow = hi + (size_t)r*WD;
    float acc = 0.f;
    int k0 = (x + 1) & 1;
#pragma unroll
    for (int kk = 0; kk < 7; ++kk) {
        int k = k0 + 2*kk;
        int m = (x + k - 1) >> 1;
        acc += lrow[m] * cG0[k] + hrow[m] * cG1[k];
    }
    out[i] = acc;
}

// ---------------- host orchestration ----------------
static inline int eb(int n) { return (n + 255) / 256; }

extern "C" void kernel_launch(void* const* d_in, const int* in_sizes, int n_in,
                              void* d_out, int out_size)
{
    const float* u_in   = (const float*)d_in[0];
    const float* uvMask = (const float*)d_in[1];
    const float* f_real = (const float*)d_in[3];
    const float* f_imag = (const float*)d_in[4];
    const float* lam    = (const float*)d_in[5];
    const float* gama   = (const float*)d_in[6];
    const float* mmu    = (const float*)d_in[7];
    const float* prelu  = (const float*)d_in[8];
    float* out = (float*)d_out;

    void *pCA, *pCB, *pMURF, *pU, *pIDWT;
    void *pDX, *pDY, *pBX, *pBY;
    void *pWL, *pBWL, *pUL, *pWH, *pBWH, *pUH;
    void *pLOT, *pHIT, *pLOS, *pHIS;
    cudaGetSymbolAddress(&pCA, g_CA);       cudaGetSymbolAddress(&pCB, g_CB);
    cudaGetSymbolAddress(&pMURF, g_MURF);   cudaGetSymbolAddress(&pU, g_U);
    cudaGetSymbolAddress(&pIDWT, g_IDWT);
    cudaGetSymbolAddress(&pDX, g_DX);       cudaGetSymbolAddress(&pDY, g_DY);
    cudaGetSymbolAddress(&pBX, g_BX);       cudaGetSymbolAddress(&pBY, g_BY);
    cudaGetSymbolAddress(&pWL, g_WL);       cudaGetSymbolAddress(&pBWL, g_BWL);
    cudaGetSymbolAddress(&pUL, g_UL);       cudaGetSymbolAddress(&pWH, g_WH);
    cudaGetSymbolAddress(&pBWH, g_BWH);     cudaGetSymbolAddress(&pUH, g_UH);
    cudaGetSymbolAddress(&pLOT, g_LOT);     cudaGetSymbolAddress(&pHIT, g_HIT);
    cudaGetSymbolAddress(&pLOS, g_LOS);     cudaGetSymbolAddress(&pHIS, g_HIS);

    dim3 tb(32, 8), tg(32, 32, NB);
    const int FFTG = NB*FN;

    // ----- init state -----
    k_pack_f0<<<eb(TOT), 256>>>(f_real, f_imag);
    cudaMemsetAsync(pDX, 0, (size_t)TOT*4, 0);
    cudaMemsetAsync(pDY, 0, (size_t)TOT*4, 0);
    cudaMemsetAsync(pBX, 0, (size_t)TOT*4, 0);
    cudaMemsetAsync(pBY, 0, (size_t)TOT*4, 0);
    cudaMemsetAsync(pBWL, 0, (size_t)SLL*4, 0);
    cudaMemsetAsync(pBWH, 0, (size_t)(3*SLL)*4, 0);

    // ----- uker: numeric fft2 of stencil image (built in g_U, normal layout) -----
    cudaMemsetAsync(pU, 0, (size_t)TOT*4, 0);
    k_sten<<<1, 32>>>();
    k_fft<<<FFTG, 512>>>(pU, pCA, 1, 0, 0, 1.f, prelu);   // [y][p]
    k_transpose_c<<<tg, tb>>>((float2*)pCA, (float2*)pCB);// [p][y]
    k_fft<<<FFTG, 512>>>(pCB, pCA, 0, 0, 0, 1.f, prelu);  // [p][q]
    k_transpose_c<<<tg, tb>>>((float2*)pCA, (float2*)pCB);// [q][p] normal spectrum
    k_uker2<<<eb(TOT), 256>>>(uvMask, lam, gama, mmu);

    // ----- dwt2(u_in) -> WL, WH -----
    k_afb_w<<<eb(NB*FN*WD), 256>>>(u_in, (float*)pLOT, (float*)pHIT);
    k_afb_h<<<eb(SLL), 256>>>((float*)pLOT, (float*)pWL, (float*)pWH);
    k_afb_h<<<eb(SLL), 256>>>((float*)pHIT, (float*)pWH + (size_t)SLL,
                              (float*)pWH + (size_t)2*SLL);

    // ----- murf = ifft2(mask * f0)  (mmu folded into rhs) -----
    k_maskf<<<eb(TOT), 256>>>(uvMask);                    // CA normal
    k_transpose_c<<<tg, tb>>>((float2*)pCA, (float2*)pCB);
    k_fft<<<FFTG, 512>>>(pCB, pCA, 0, 0, 1, 1.f/FN, prelu);
    k_transpose_c<<<tg, tb>>>((float2*)pCA, (float2*)pCB);
    k_fft<<<FFTG, 512>>>(pCB, pMURF, 0, 0, 1, 1.f/FN, prelu);  // normal

    // ----- iterations -----
    for (int it = 0; it < 2; ++it) {
        // idwt2(wl-bwl, wh-bwh) -> IDWT
        k_sfb_h<<<eb(NB*FN*WD), 256>>>((float*)pWL, (float*)pBWL,
                                       (float*)pWH, (float*)pBWH, (float*)pLOS);
        k_sfb_h<<<eb(NB*FN*WD), 256>>>((float*)pWH + (size_t)SLL,
                                       (float*)pBWH + (size_t)SLL,
                                       (float*)pWH + (size_t)2*SLL,
                                       (float*)pBWH + (size_t)2*SLL, (float*)pHIS);
        k_sfb_w<<<eb(TOT), 256>>>((float*)pLOS, (float*)pHIS, (float*)pIDWT);

        // rhs -> CA (normal)
        k_rhs<<<eb(TOT), 256>>>(lam, gama, mmu);
        // fft2(rhs): CA -> spectrum in CA (normal)
        k_fft<<<FFTG, 512>>>(pCA, pCB, 0, 0, 0, 1.f, prelu);
        k_transpose_c<<<tg, tb>>>((float2*)pCB, (float2*)pCA);
        k_fft<<<FFTG, 512>>>(pCA, pCB, 0, 0, 0, 1.f, prelu);
        k_transpose_c<<<tg, tb>>>((float2*)pCB, (float2*)pCA);
        k_div_uker<<<eb(TOT), 256>>>((float2*)pCA);
        // ifft2 with fused real+srelu on last pass
        k_transpose_c<<<tg, tb>>>((float2*)pCA, (float2*)pCB);
        k_fft<<<FFTG, 512>>>(pCB, pCA, 0, 0, 1, 1.f/FN, prelu);
        k_transpose_c<<<tg, tb>>>((float2*)pCA, (float2*)pCB);
        void* udst = (it == 0) ? pU : (void*)out;
        k_fft<<<FFTG, 512>>>(pCB, udst, 0, 1, 1, 1.f/FN, prelu);

        if (it == 0) {
            k_shrink<<<eb(TOT), 256>>>(lam, prelu);
            // dwt2(u) -> UL, UH
            k_afb_w<<<eb(NB*FN*WD), 256>>>((float*)pU, (float*)pLOT, (float*)pHIT);
            k_afb_h<<<eb(SLL), 256>>>((float*)pLOT, (float*)pUL, (float*)pUH);
            k_afb_h<<<eb(SLL), 256>>>((float*)pHIT, (float*)pUH + (size_t)SLL,
                                      (float*)pUH + (size_t)2*SLL);
            k_wupd<<<eb(SLL), 256>>>((float*)pUL, (float*)pBWL, (float*)pWL,
                                     SLL, gama, prelu);
            k_wupd<<<eb(3*SLL), 256>>>((float*)pUH, (float*)pBWH, (float*)pWH,
                                       3*SLL, gama, prelu);
            k_bxy<<<eb(TOT), 256>>>();
            // FU = fft2(u) -> CB (normal)
            k_fft<<<FFTG, 512>>>(pU, pCA, 1, 0, 0, 1.f, prelu);
            k_transpose_c<<<tg, tb>>>((float2*)pCA, (float2*)pCB);
            k_fft<<<FFTG, 512>>>(pCB, pCA, 0, 0, 0, 1.f, prelu);
            k_transpose_c<<<tg, tb>>>((float2*)pCA, (float2*)pCB);
            // CA = mask*(2*F0 - mask*FU) ; murf = ifft2(CA)
            k_fupd<<<eb(TOT), 256>>>(uvMask);
            k_transpose_c<<<tg, tb>>>((float2*)pCA, (float2*)pCB);
            k_fft<<<FFTG, 512>>>(pCB, pCA, 0, 0, 1, 1.f/FN, prelu);
            k_transpose_c<<<tg, tb>>>((float2*)pCA, (float2*)pCB);
            k_fft<<<FFTG, 512>>>(pCB, pMURF, 0, 0, 1, 1.f/FN, prelu);
        }
    }
    (void)in_sizes; (void)n_in; (void)out_size;
}

// round 5
// speedup vs baseline: 1.3337x; 1.3337x over previous
#include <cuda_runtime.h>
#include <math.h>

#define FN   1024
#define NB   4
#define FNN  (FN*FN)
#define TOT  (NB*FNN)
#define WD   518
#define SLL  (NB*WD*WD)
#define SLW  (NB*FN*WD)
#define PIF  3.14159265358979323846f

// ---------------- static device scratch ----------------
__device__ float2 g_CA[TOT];
__device__ float2 g_CB[TOT];
__device__ float2 g_UKER[TOT];   // [p][q] transposed layout
__device__ float2 g_F0T[TOT];    // [p][q] transposed layout
__device__ float2 g_MURF[TOT];   // normal layout

__device__ float g_U[TOT];
__device__ float g_DX[TOT];
__device__ float g_DY[TOT];
__device__ float g_BX[TOT];
__device__ float g_BY[TOT];
__device__ float g_MASKT[TOT];   // transposed mask
__device__ float g_IDWT[TOT];

__device__ float g_WL[SLL];
__device__ float g_BWL[SLL];
__device__ float g_UL[SLL];
__device__ float g_WH[3*SLL];
__device__ float g_BWH[3*SLL];
__device__ float g_UH[3*SLL];
__device__ float g_LOT[SLW];
__device__ float g_HIT[SLW];
__device__ float g_LOS[SLW];
__device__ float g_HIS[SLW];

// ---------------- wavelet filters (db7, L=14) ----------------
__constant__ float cH0A[14] = {
    0.010268176708511255f, 0.004010244871533663f, -0.10780823770381774f,
   -0.14004724044296152f, 0.2886296317515146f, 0.767764317003164f,
    0.5361019170917628f, 0.017441255086855827f, -0.049552834937127255f,
    0.0678926935013727f, 0.03051551316596357f, -0.01263630340325193f,
   -0.0010473848886829163f, 0.002681814568257878f };
__constant__ float cH1A[14] = {
    0.002681814568257878f, 0.0010473848886829163f, -0.01263630340325193f,
   -0.03051551316596357f, 0.0678926935013727f, 0.049552834937127255f,
    0.017441255086855827f, -0.5361019170917628f, 0.767764317003164f,
   -0.2886296317515146f, -0.14004724044296152f, 0.10780823770381774f,
    0.004010244871533663f, -0.010268176708511255f };
__constant__ float cG0[14] = {
    0.002681814568257878f, -0.0010473848886829163f, -0.01263630340325193f,
    0.03051551316596357f, 0.0678926935013727f, -0.049552834937127255f,
    0.017441255086855827f, 0.5361019170917628f, 0.767764317003164f,
    0.2886296317515146f, -0.14004724044296152f, -0.10780823770381774f,
    0.004010244871533663f, 0.010268176708511255f };
__constant__ float cG1[14] = {
   -0.010268176708511255f, 0.004010244871533663f, 0.10780823770381774f,
   -0.14004724044296152f, -0.2886296317515146f, 0.767764317003164f,
   -0.5361019170917628f, 0.017441255086855827f, 0.049552834937127255f,
    0.0678926935013727f, -0.03051551316596357f, -0.01263630340325193f,
    0.0010473848886829163f, 0.002681814568257878f };

__device__ __forceinline__ float2 cmulf(float2 a, float2 b) {
    return make_float2(a.x*b.x - a.y*b.y, a.x*b.y + a.y*b.x);
}

// ---------------- 1024-pt radix-4 Stockham FFT over rows ----------------
// preOp (complex input only): 0 none; 1 divide by g_UKER; 2 fupd = m*(2*f0T - m*v);
// 3 load = maskT * f0T (src ignored element-wise, still pass valid ptr)
__global__ __launch_bounds__(256) void k_fft4(const void* __restrict__ srcv,
                                              void* __restrict__ dstv,
                                              int inReal, int outReal, int inverse,
                                              float scale,
                                              const float* __restrict__ prelu,
                                              int preOp)
{
    __shared__ float2 sA[FN];
    __shared__ float2 sB[FN];
    __shared__ float2 tw[FN];
    int t = threadIdx.x;
    int row = blockIdx.x;
    size_t base = (size_t)row*FN;
    for (int j = t; j < FN; j += 256) {
        float sv, cv; sincosf(-2.f*PIF*(float)j/(float)FN, &sv, &cv);
        tw[j] = make_float2(cv, inverse ? -sv : sv);
    }
    if (inReal) {
        const float* s = (const float*)srcv + base;
#pragma unroll
        for (int m = 0; m < 4; ++m) sA[t+256*m] = make_float2(s[t+256*m], 0.f);
    } else {
        const float2* s = (const float2*)srcv + base;
#pragma unroll
        for (int m = 0; m < 4; ++m) {
            int idx = t + 256*m;
            float2 v = s[idx];
            if (preOp == 1) {
                float2 w = g_UKER[base + idx];
                float d = 1.f/(w.x*w.x + w.y*w.y);
                v = make_float2((v.x*w.x + v.y*w.y)*d, (v.y*w.x - v.x*w.y)*d);
            } else if (preOp == 2) {
                float mk = g_MASKT[base + idx];
                float2 f0 = g_F0T[base + idx];
                v = make_float2(mk*(2.f*f0.x - mk*v.x), mk*(2.f*f0.y - mk*v.y));
            } else if (preOp == 3) {
                float mk = g_MASKT[base + idx];
                float2 f0 = g_F0T[base + idx];
                v = make_float2(mk*f0.x, mk*f0.y);
            }
            sA[idx] = v;
        }
    }
    __syncthreads();
    float2* X = sA; float2* Y = sB;
#pragma unroll
    for (int s = 0; s < 5; ++s) {
        int ns = 1 << (2*s);
        int k  = t & (ns - 1);
        int j  = ((t - k) << 2) + k;
        float2 c0 = X[t], c1 = X[t+256], c2 = X[t+512], c3 = X[t+768];
        int sh = 8 - 2*s;
        c1 = cmulf(c1, tw[k << sh]);
        c2 = cmulf(c2, tw[(2*k) << sh]);
        c3 = cmulf(c3, tw[(3*k) << sh]);
        float2 t0 = make_float2(c0.x+c2.x, c0.y+c2.y);
        float2 t1 = make_float2(c0.x-c2.x, c0.y-c2.y);
        float2 t2 = make_float2(c1.x+c3.x, c1.y+c3.y);
        float2 dd = make_float2(c1.x-c3.x, c1.y-c3.y);
        float2 t3 = inverse ? make_float2(-dd.y, dd.x)     // +i*dd
                            : make_float2( dd.y, -dd.x);   // -i*dd
        Y[j]        = make_float2(t0.x+t2.x, t0.y+t2.y);
        Y[j+ns]     = make_float2(t1.x+t3.x, t1.y+t3.y);
        Y[j+2*ns]   = make_float2(t0.x-t2.x, t0.y-t2.y);
        Y[j+3*ns]   = make_float2(t1.x-t3.x, t1.y-t3.y);
        __syncthreads();
        float2* tmp = X; X = Y; Y = tmp;
    }
    if (!outReal) {
        float2* d = (float2*)dstv + base;
#pragma unroll
        for (int m = 0; m < 4; ++m) {
            float2 v = X[t+256*m];
            d[t+256*m] = make_float2(v.x*scale, v.y*scale);
        }
    } else {
        float a = prelu[0];
        float* d = (float*)dstv + base;
#pragma unroll
        for (int m = 0; m < 4; ++m) {
            float v = X[t+256*m].x * scale;
            d[t+256*m] = (v >= 0.f) ? v : a*v;
        }
    }
}

// ---------------- transposes ----------------
__global__ void k_transpose_c(const float2* __restrict__ src, float2* __restrict__ dst)
{
    __shared__ float2 tile[32][33];
    int b = blockIdx.z;
    const float2* s = src + (size_t)b*FNN;
    float2* d = dst + (size_t)b*FNN;
    int x  = blockIdx.x*32 + threadIdx.x;
    int y0 = blockIdx.y*32 + threadIdx.y;
#pragma unroll
    for (int i = 0; i < 32; i += 8)
        tile[threadIdx.y+i][threadIdx.x] = s[(size_t)(y0+i)*FN + x];
    __syncthreads();
    int x2 = blockIdx.y*32 + threadIdx.x;
    int y2 = blockIdx.x*32 + threadIdx.y;
#pragma unroll
    for (int i = 0; i < 32; i += 8)
        d[(size_t)(y2+i)*FN + x2] = tile[threadIdx.x][threadIdx.y+i];
}

__global__ void k_transpose_r(const float* __restrict__ src, float* __restrict__ dst)
{
    __shared__ float tile[32][33];
    int b = blockIdx.z;
    const float* s = src + (size_t)b*FNN;
    float* d = dst + (size_t)b*FNN;
    int x  = blockIdx.x*32 + threadIdx.x;
    int y0 = blockIdx.y*32 + threadIdx.y;
#pragma unroll
    for (int i = 0; i < 32; i += 8)
        tile[threadIdx.y+i][threadIdx.x] = s[(size_t)(y0+i)*FN + x];
    __syncthreads();
    int x2 = blockIdx.y*32 + threadIdx.x;
    int y2 = blockIdx.x*32 + threadIdx.y;
#pragma unroll
    for (int i = 0; i < 32; i += 8)
        d[(size_t)(y2+i)*FN + x2] = tile[threadIdx.x][threadIdx.y+i];
}

__global__ void k_make_f0T(const float* __restrict__ fr, const float* __restrict__ fi,
                           float2* __restrict__ dst)
{
    __shared__ float tr[32][33];
    __shared__ float ti[32][33];
    int b = blockIdx.z;
    const float* sr = fr + (size_t)b*FNN;
    const float* si = fi + (size_t)b*FNN;
    float2* d = dst + (size_t)b*FNN;
    int x  = blockIdx.x*32 + threadIdx.x;
    int y0 = blockIdx.y*32 + threadIdx.y;
#pragma unroll
    for (int i = 0; i < 32; i += 8) {
        tr[threadIdx.y+i][threadIdx.x] = sr[(size_t)(y0+i)*FN + x];
        ti[threadIdx.y+i][threadIdx.x] = si[(size_t)(y0+i)*FN + x];
    }
    __syncthreads();
    int x2 = blockIdx.y*32 + threadIdx.x;
    int y2 = blockIdx.x*32 + threadIdx.y;
#pragma unroll
    for (int i = 0; i < 32; i += 8)
        d[(size_t)(y2+i)*FN + x2] =
            make_float2(tr[threadIdx.x][threadIdx.y+i], ti[threadIdx.x][threadIdx.y+i]);
}

// ---------------- small init kernels ----------------
__global__ void k_sten()   // stencil into g_U (zeroed beforehand)
{
    int t = threadIdx.x;
    if (t >= NB*5) return;
    int b = t / 5, p = t % 5;
    size_t base = (size_t)b*FNN;
    const int yy[5] = {1, 1, 2, FN-1, 1};
    const int xx[5] = {1, 2, 1, 1, FN-1};
    const float vv[5] = {4.f, -1.f, -1.f, -1.f, -1.f};
    g_U[base + (size_t)yy[p]*FN + xx[p]] = vv[p];
}

// UKER = mmu*maskT^2 + gama + lam*STEN_FFT  -- all in [p][q] layout; spectrum in g_CA
__global__ void k_uker2(const float* __restrict__ maskT,
                        const float* __restrict__ lam, const float* __restrict__ gama,
                        const float* __restrict__ mmu)
{
    int i = blockIdx.x*blockDim.x + threadIdx.x;
    if (i >= TOT) return;
    float m = maskT[i];
    float2 sf = g_CA[i];
    float lv = lam[0];
    g_UKER[i] = make_float2(mmu[0]*m*m + gama[0] + lv*sf.x, lv*sf.y);
}

// ---------------- spatial elementwise ----------------
__global__ void k_rhs(const float* __restrict__ lam, const float* __restrict__ gama,
                      const float* __restrict__ mmu)
{
    int i = blockIdx.x*blockDim.x + threadIdx.x;
    if (i >= TOT) return;
    int x = i & (FN-1);
    int y = (i >> 10) & (FN-1);
    int rowb = i - x;
    float dxt = 0.f;
    if (x >= 1) {
        int xn = (x == FN-1) ? 1 : x+1;
        float v0 = g_DX[i] - g_BX[i];
        float v1 = g_DX[rowb + xn] - g_BX[rowb + xn];
        dxt = v0 - v1;
    }
    float dyt = 0.f;
    if (y >= 1) {
        int yn = (y == FN-1) ? 1 : y+1;
        int j = i + (yn - y)*FN;
        float v0 = g_DY[i] - g_BY[i];
        float v1 = g_DY[j] - g_BY[j];
        dyt = v0 - v1;
    }
    float2 mu = g_MURF[i];
    float mv = mmu[0];
    g_CA[i] = make_float2(mv*mu.x + lam[0]*(dxt + dyt) + gama[0]*g_IDWT[i], mv*mu.y);
}

__global__ void k_shrink(const float* __restrict__ lam, const float* __restrict__ prelu)
{
    int i = blockIdx.x*blockDim.x + threadIdx.x;
    if (i >= TOT) return;
    float a  = prelu[0];
    float il = 1.f/lam[0];
    float vx = g_DX[i] + g_BX[i];
    float vy = g_DY[i] + g_BY[i];
    float s = sqrtf(vx*vx + vy*vy);
    float nx = vx - s*il;
    float ny = vy - s*il;
    g_DX[i] = (nx >= 0.f) ? nx : a*nx;
    g_DY[i] = (ny >= 0.f) ? ny : a*ny;
}

__global__ void k_bxy()
{
    int i = blockIdx.x*blockDim.x + threadIdx.x;
    if (i >= TOT) return;
    int x = i & (FN-1);
    int y = (i >> 10) & (FN-1);
    int rowb = i - x;
    float dxu = 0.f;
    if (x >= 1) {
        int xm = (x == 1) ? FN-1 : x-1;
        dxu = g_U[i] - g_U[rowb + xm];
    }
    g_BX[i] += dxu - g_DX[i];
    float dyu = 0.f;
    if (y >= 1) {
        int ym = (y == 1) ? FN-1 : y-1;
        dyu = g_U[i] - g_U[i + (ym - y)*FN];
    }
    g_BY[i] += dyu - g_DY[i];
}

__global__ void k_wupd(const float* __restrict__ uarr, float* __restrict__ bw,
                       float* __restrict__ w, int n,
                       const float* __restrict__ gama, const float* __restrict__ prelu)
{
    int i = blockIdx.x*blockDim.x + threadIdx.x;
    if (i >= n) return;
    float a  = prelu[0];
    float ig = 1.f/gama[0];
    float uv = uarr[i], bv = bw[i];
    float t = uv + bv - ig;
    float wv = (t >= 0.f) ? t : a*t;
    w[i]  = wv;
    bw[i] = bv + uv - wv;
}

// ---------------- DWT analysis ----------------
__global__ void k_afb_w(const float* __restrict__ src, float* __restrict__ lo,
                        float* __restrict__ hi)
{
    int i = blockIdx.x*blockDim.x + threadIdx.x;
    if (i >= NB*FN*WD) return;
    int o = i % WD;
    int r = i / WD;
    const float* row = src + (size_t)r*FN;
    float l = 0.f, h = 0.f;
#pragma unroll
    for (int k = 0; k < 14; ++k) {
        int j = 2*o + k - 12;
        j = (j < 0) ? -j : ((j >= FN) ? (2*FN - 2 - j) : j);
        float v = row[j];
        l += v * cH0A[k];
        h += v * cH1A[k];
    }
    lo[i] = l;
    hi[i] = h;
}

__global__ void k_afb_h(const float* __restrict__ src, float* __restrict__ lo,
                        float* __restrict__ hi)
{
    int i = blockIdx.x*blockDim.x + threadIdx.x;
    if (i >= SLL) return;
    int w = i % WD;
    int o = (i / WD) % WD;
    int b = i / (WD*WD);
    const float* base = src + (size_t)b*FN*WD;
    float l = 0.f, h = 0.f;
#pragma unroll
    for (int k = 0; k < 14; ++k) {
        int j = 2*o + k - 12;
        j = (j < 0) ? -j : ((j >= FN) ? (2*FN - 2 - j) : j);
        float v = base[(size_t)j*WD + w];
        l += v * cH0A[k];
        h += v * cH1A[k];
    }
    lo[i] = l;
    hi[i] = h;
}

// ---------------- IDWT synthesis ----------------
__global__ void k_sfb_h(const float* __restrict__ loA, const float* __restrict__ loB,
                        const float* __restrict__ hiA, const float* __restrict__ hiB,
                        float* __restrict__ out)
{
    int i = blockIdx.x*blockDim.x + threadIdx.x;
    if (i >= NB*FN*WD) return;
    int w = i % WD;
    int o = (i / WD) % FN;
    int b = i / (FN*WD);
    size_t bb = (size_t)b*WD*WD;
    float acc = 0.f;
    int k0 = (o + 1) & 1;
#pragma unroll
    for (int kk = 0; kk < 7; ++kk) {
        int k = k0 + 2*kk;
        int m = (o + k - 1) >> 1;
        size_t idx = bb + (size_t)m*WD + w;
        float lo = loA[idx] - loB[idx];
        float hi = hiA[idx] - hiB[idx];
        acc += lo * cG0[k] + hi * cG1[k];
    }
    out[i] = acc;
}

__global__ void k_sfb_w(const float* __restrict__ lo, const float* __restrict__ hi,
                        float* __restrict__ out)
{
    int i = blockIdx.x*blockDim.x + threadIdx.x;
    if (i >= TOT) return;
    int x = i & (FN-1);
    int r = i >> 10;
    const float* lrow = lo + (size_t)r*WD;
    const float* hrow = hi + (size_t)r*WD;
    float acc = 0.f;
    int k0 = (x + 1) & 1;
#pragma unroll
    for (int kk = 0; kk < 7; ++kk) {
        int k = k0 + 2*kk;
        int m = (x + k - 1) >> 1;
        acc += lrow[m] * cG0[k] + hrow[m] * cG1[k];
    }
    out[i] = acc;
}

// ---------------- host orchestration ----------------
static inline int eb(int n) { return (n + 255) / 256; }

extern "C" void kernel_launch(void* const* d_in, const int* in_sizes, int n_in,
                              void* d_out, int out_size)
{
    const float* u_in   = (const float*)d_in[0];
    const float* uvMask = (const float*)d_in[1];
    const float* f_real = (const float*)d_in[3];
    const float* f_imag = (const float*)d_in[4];
    const float* lam    = (const float*)d_in[5];
    const float* gama   = (const float*)d_in[6];
    const float* mmu    = (const float*)d_in[7];
    const float* prelu  = (const float*)d_in[8];
    float* out = (float*)d_out;

    void *pCA, *pCB, *pMURF, *pU, *pIDWT, *pMASKT, *pF0T;
    void *pDX, *pDY, *pBX, *pBY;
    void *pWL, *pBWL, *pUL, *pWH, *pBWH, *pUH;
    void *pLOT, *pHIT, *pLOS, *pHIS;
    cudaGetSymbolAddress(&pCA, g_CA);       cudaGetSymbolAddress(&pCB, g_CB);
    cudaGetSymbolAddress(&pMURF, g_MURF);   cudaGetSymbolAddress(&pU, g_U);
    cudaGetSymbolAddress(&pIDWT, g_IDWT);   cudaGetSymbolAddress(&pMASKT, g_MASKT);
    cudaGetSymbolAddress(&pF0T, g_F0T);
    cudaGetSymbolAddress(&pDX, g_DX);       cudaGetSymbolAddress(&pDY, g_DY);
    cudaGetSymbolAddress(&pBX, g_BX);       cudaGetSymbolAddress(&pBY, g_BY);
    cudaGetSymbolAddress(&pWL, g_WL);       cudaGetSymbolAddress(&pBWL, g_BWL);
    cudaGetSymbolAddress(&pUL, g_UL);       cudaGetSymbolAddress(&pWH, g_WH);
    cudaGetSymbolAddress(&pBWH, g_BWH);     cudaGetSymbolAddress(&pUH, g_UH);
    cudaGetSymbolAddress(&pLOT, g_LOT);     cudaGetSymbolAddress(&pHIT, g_HIT);
    cudaGetSymbolAddress(&pLOS, g_LOS);     cudaGetSymbolAddress(&pHIS, g_HIS);

    dim3 tb(32, 8), tg(32, 32, NB);
    const int FFTG = NB*FN;

    // ----- init state -----
    k_transpose_r<<<tg, tb>>>(uvMask, (float*)pMASKT);
    k_make_f0T<<<tg, tb>>>(f_real, f_imag, (float2*)pF0T);
    cudaMemsetAsync(pDX, 0, (size_t)TOT*4, 0);
    cudaMemsetAsync(pDY, 0, (size_t)TOT*4, 0);
    cudaMemsetAsync(pBX, 0, (size_t)TOT*4, 0);
    cudaMemsetAsync(pBY, 0, (size_t)TOT*4, 0);
    cudaMemsetAsync(pBWL, 0, (size_t)SLL*4, 0);
    cudaMemsetAsync(pBWH, 0, (size_t)(3*SLL)*4, 0);

    // ----- uker: numeric fft2 of stencil, kept in [p][q] layout -----
    cudaMemsetAsync(pU, 0, (size_t)TOT*4, 0);
    k_sten<<<1, 32>>>();
    k_fft4<<<FFTG, 256>>>(pU, pCA, 1, 0, 0, 1.f, prelu, 0);   // [y][p]
    k_transpose_c<<<tg, tb>>>((float2*)pCA, (float2*)pCB);    // [p][y]
    k_fft4<<<FFTG, 256>>>(pCB, pCA, 0, 0, 0, 1.f, prelu, 0);  // [p][q]
    k_uker2<<<eb(TOT), 256>>>((float*)pMASKT, lam, gama, mmu);

    // ----- dwt2(u_in) -> WL, WH -----
    k_afb_w<<<eb(NB*FN*WD), 256>>>(u_in, (float*)pLOT, (float*)pHIT);
    k_afb_h<<<eb(SLL), 256>>>((float*)pLOT, (float*)pWL, (float*)pWH);
    k_afb_h<<<eb(SLL), 256>>>((float*)pHIT, (float*)pWH + (size_t)SLL,
                              (float*)pWH + (size_t)2*SLL);

    // ----- murf = ifft2(mask * f0): preOp=3 loads maskT*F0T in [p][q] -----
    k_fft4<<<FFTG, 256>>>(pF0T, pCB, 0, 0, 1, 1.f/FN, prelu, 3);  // [p][y]
    k_transpose_c<<<tg, tb>>>((float2*)pCB, (float2*)pCA);        // [y][p]
    k_fft4<<<FFTG, 256>>>(pCA, pMURF, 0, 0, 1, 1.f/FN, prelu, 0); // normal

    // ----- iterations -----
    for (int it = 0; it < 2; ++it) {
        // idwt2(wl-bwl, wh-bwh) -> IDWT
        k_sfb_h<<<eb(NB*FN*WD), 256>>>((float*)pWL, (float*)pBWL,
                                       (float*)pWH, (float*)pBWH, (float*)pLOS);
        k_sfb_h<<<eb(NB*FN*WD), 256>>>((float*)pWH + (size_t)SLL,
                                       (float*)pBWH + (size_t)SLL,
                                       (float*)pWH + (size_t)2*SLL,
                                       (float*)pBWH + (size_t)2*SLL, (float*)pHIS);
        k_sfb_w<<<eb(TOT), 256>>>((float*)pLOS, (float*)pHIS, (float*)pIDWT);

        // rhs -> CA (normal)
        k_rhs<<<eb(TOT), 256>>>(lam, gama, mmu);
        // fft2(rhs) to [p][q]; divide by UKER fused into inverse load; back out
        k_fft4<<<FFTG, 256>>>(pCA, pCB, 0, 0, 0, 1.f, prelu, 0);       // [y][p]
        k_transpose_c<<<tg, tb>>>((float2*)pCB, (float2*)pCA);         // [p][y]
        k_fft4<<<FFTG, 256>>>(pCA, pCB, 0, 0, 0, 1.f, prelu, 0);       // [p][q]
        k_fft4<<<FFTG, 256>>>(pCB, pCA, 0, 0, 1, 1.f/FN, prelu, 1);    // div + [p][y]
        k_transpose_c<<<tg, tb>>>((float2*)pCA, (float2*)pCB);         // [y][p]
        void* udst = (it == 0) ? pU : (void*)out;
        k_fft4<<<FFTG, 256>>>(pCB, udst, 0, 1, 1, 1.f/FN, prelu, 0);   // u + srelu

        if (it == 0) {
            k_shrink<<<eb(TOT), 256>>>(lam, prelu);
            // dwt2(u) -> UL, UH
            k_afb_w<<<eb(NB*FN*WD), 256>>>((float*)pU, (float*)pLOT, (float*)pHIT);
            k_afb_h<<<eb(SLL), 256>>>((float*)pLOT, (float*)pUL, (float*)pUH);
            k_afb_h<<<eb(SLL), 256>>>((float*)pHIT, (float*)pUH + (size_t)SLL,
                                      (float*)pUH + (size_t)2*SLL);
            k_wupd<<<eb(SLL), 256>>>((float*)pUL, (float*)pBWL, (float*)pWL,
                                     SLL, gama, prelu);
            k_wupd<<<eb(3*SLL), 256>>>((float*)pUH, (float*)pBWH, (float*)pWH,
                                       3*SLL, gama, prelu);
            k_bxy<<<eb(TOT), 256>>>();
            // FU = fft2(u) in [p][q]; fupd fused into inverse load; murf normal
            k_fft4<<<FFTG, 256>>>(pU, pCB, 1, 0, 0, 1.f, prelu, 0);        // [y][p]
            k_transpose_c<<<tg, tb>>>((float2*)pCB, (float2*)pCA);         // [p][y]
            k_fft4<<<FFTG, 256>>>(pCA, pCB, 0, 0, 0, 1.f, prelu, 0);       // [p][q] FU
            k_fft4<<<FFTG, 256>>>(pCB, pCA, 0, 0, 1, 1.f/FN, prelu, 2);    // fupd + inv
            k_transpose_c<<<tg, tb>>>((float2*)pCA, (float2*)pCB);         // [y][p]
            k_fft4<<<FFTG, 256>>>(pCB, pMURF, 0, 0, 1, 1.f/FN, prelu, 0);  // normal
        }
    }
    (void)in_sizes; (void)n_in; (void)out_size;
}

// round 6
// speedup vs baseline: 1.5955x; 1.1962x over previous
#include <cuda_runtime.h>
#include <math.h>

#define FN   1024
#define NB   4
#define FNN  (FN*FN)
#define TOT  (NB*FNN)
#define WD   518
#define SLL  (NB*WD*WD)
#define SLW  (NB*FN*WD)
#define PIF  3.14159265358979323846f

// smem padding: kill 4-way bank conflicts in radix-4 scatter writes
#define DP(i) ((i) + ((i)>>2))     // data buffers (max 1278)
#define TP(i) ((i) + ((i)>>4))     // twiddle table (max 1086)

// ---------------- static device scratch ----------------
__device__ float2 g_CA[TOT];
__device__ float2 g_CB[TOT];
__device__ float2 g_UKER[TOT];   // [p][q]
__device__ float2 g_F0T[TOT];    // [p][q]
__device__ float2 g_MURF[TOT];   // normal

__device__ float g_U[TOT];
__device__ float g_DX[TOT];
__device__ float g_DY[TOT];
__device__ float g_BX[TOT];
__device__ float g_BY[TOT];
__device__ float g_MASKT[TOT];
__device__ float g_IDWT[TOT];

__device__ float g_WL[SLL];
__device__ float g_BWL[SLL];
__device__ float g_UL[SLL];
__device__ float g_WH[3*SLL];
__device__ float g_BWH[3*SLL];
__device__ float g_UH[3*SLL];
__device__ float g_LOT[SLW];
__device__ float g_HIT[SLW];
__device__ float g_LOS[SLW];
__device__ float g_HIS[SLW];

// ---------------- wavelet filters (db7, L=14) ----------------
__constant__ float cH0A[14] = {
    0.010268176708511255f, 0.004010244871533663f, -0.10780823770381774f,
   -0.14004724044296152f, 0.2886296317515146f, 0.767764317003164f,
    0.5361019170917628f, 0.017441255086855827f, -0.049552834937127255f,
    0.0678926935013727f, 0.03051551316596357f, -0.01263630340325193f,
   -0.0010473848886829163f, 0.002681814568257878f };
__constant__ float cH1A[14] = {
    0.002681814568257878f, 0.0010473848886829163f, -0.01263630340325193f,
   -0.03051551316596357f, 0.0678926935013727f, 0.049552834937127255f,
    0.017441255086855827f, -0.5361019170917628f, 0.767764317003164f,
   -0.2886296317515146f, -0.14004724044296152f, 0.10780823770381774f,
    0.004010244871533663f, -0.010268176708511255f };
__constant__ float cG0[14] = {
    0.002681814568257878f, -0.0010473848886829163f, -0.01263630340325193f,
    0.03051551316596357f, 0.0678926935013727f, -0.049552834937127255f,
    0.017441255086855827f, 0.5361019170917628f, 0.767764317003164f,
    0.2886296317515146f, -0.14004724044296152f, -0.10780823770381774f,
    0.004010244871533663f, 0.010268176708511255f };
__constant__ float cG1[14] = {
   -0.010268176708511255f, 0.004010244871533663f, 0.10780823770381774f,
   -0.14004724044296152f, -0.2886296317515146f, 0.767764317003164f,
   -0.5361019170917628f, 0.017441255086855827f, 0.049552834937127255f,
    0.0678926935013727f, -0.03051551316596357f, -0.01263630340325193f,
    0.0010473848886829163f, 0.002681814568257878f };

__device__ __forceinline__ float2 cmulf(float2 a, float2 b) {
    return make_float2(a.x*b.x - a.y*b.y, a.x*b.y + a.y*b.x);
}

// one radix-4 Stockham stage; tw is the FORWARD table; conjugate applied if INV
template<int INV>
__device__ __forceinline__ void r4stage(const float2* __restrict__ X,
                                        float2* __restrict__ Y,
                                        const float2* __restrict__ tw,
                                        int t, int s)
{
    int ns = 1 << (2*s);
    int k  = t & (ns - 1);
    int j  = ((t - k) << 2) + k;
    int sh = 8 - 2*s;
    float2 c0 = X[DP(t)], c1 = X[DP(t+256)], c2 = X[DP(t+512)], c3 = X[DP(t+768)];
    float2 w1 = tw[TP(k << sh)];
    float2 w2 = tw[TP((2*k) << sh)];
    float2 w3 = tw[TP((3*k) << sh)];
    if (INV) { w1.y = -w1.y; w2.y = -w2.y; w3.y = -w3.y; }
    c1 = cmulf(c1, w1); c2 = cmulf(c2, w2); c3 = cmulf(c3, w3);
    float2 t0 = make_float2(c0.x+c2.x, c0.y+c2.y);
    float2 t1 = make_float2(c0.x-c2.x, c0.y-c2.y);
    float2 t2 = make_float2(c1.x+c3.x, c1.y+c3.y);
    float2 dd = make_float2(c1.x-c3.x, c1.y-c3.y);
    float2 t3 = INV ? make_float2(-dd.y, dd.x) : make_float2(dd.y, -dd.x);
    Y[DP(j)]      = make_float2(t0.x+t2.x, t0.y+t2.y);
    Y[DP(j+ns)]   = make_float2(t1.x+t3.x, t1.y+t3.y);
    Y[DP(j+2*ns)] = make_float2(t0.x-t2.x, t0.y-t2.y);
    Y[DP(j+3*ns)] = make_float2(t1.x-t3.x, t1.y-t3.y);
}

// ---------------- single-direction 1024-pt radix-4 FFT over rows ----------------
// preOp: 0 none; 3 load = maskT * f0T
template<int INV>
__global__ __launch_bounds__(256) void k_fft4(const void* __restrict__ srcv,
                                              void* __restrict__ dstv,
                                              int inReal, int outReal,
                                              float scale,
                                              const float* __restrict__ prelu,
                                              int preOp)
{
    __shared__ float2 sA[1280];
    __shared__ float2 sB[1280];
    __shared__ float2 tw[1088];
    int t = threadIdx.x;
    size_t base = (size_t)blockIdx.x*FN;
    for (int j = t; j < FN; j += 256) {
        float sv, cv; sincosf(-2.f*PIF*(float)j/(float)FN, &sv, &cv);
        tw[TP(j)] = make_float2(cv, sv);
    }
    if (inReal) {
        const float* s = (const float*)srcv + base;
#pragma unroll
        for (int m = 0; m < 4; ++m) sA[DP(t+256*m)] = make_float2(s[t+256*m], 0.f);
    } else {
        const float2* s = (const float2*)srcv + base;
#pragma unroll
        for (int m = 0; m < 4; ++m) {
            int idx = t + 256*m;
            float2 v = s[idx];
            if (preOp == 3) {
                float mk = g_MASKT[base + idx];
                float2 f0 = g_F0T[base + idx];
                v = make_float2(mk*f0.x, mk*f0.y);
            }
            sA[DP(idx)] = v;
        }
    }
    __syncthreads();
    float2* X = sA; float2* Y = sB;
#pragma unroll
    for (int s = 0; s < 5; ++s) {
        r4stage<INV>(X, Y, tw, t, s);
        __syncthreads();
        float2* tmp = X; X = Y; Y = tmp;
    }
    if (!outReal) {
        float2* d = (float2*)dstv + base;
#pragma unroll
        for (int m = 0; m < 4; ++m) {
            float2 v = X[DP(t+256*m)];
            d[t+256*m] = make_float2(v.x*scale, v.y*scale);
        }
    } else {
        float a = prelu[0];
        float* d = (float*)dstv + base;
#pragma unroll
        for (int m = 0; m < 4; ++m) {
            float v = X[DP(t+256*m)].x * scale;
            d[t+256*m] = (v >= 0.f) ? v : a*v;
        }
    }
}

// ---------------- fused fwd-FFT -> pointwise -> inv-FFT (row stays in smem) ----
// MODE 1: v /= UKER[p][q];  MODE 2: v = m*(2*f0T - m*v)
template<int MODE>
__global__ __launch_bounds__(256) void k_fftpair(const float2* __restrict__ src,
                                                 float2* __restrict__ dst,
                                                 float scale)
{
    __shared__ float2 sA[1280];
    __shared__ float2 sB[1280];
    __shared__ float2 tw[1088];
    int t = threadIdx.x;
    size_t base = (size_t)blockIdx.x*FN;
    for (int j = t; j < FN; j += 256) {
        float sv, cv; sincosf(-2.f*PIF*(float)j/(float)FN, &sv, &cv);
        tw[TP(j)] = make_float2(cv, sv);
    }
    const float2* s = src + base;
#pragma unroll
    for (int m = 0; m < 4; ++m) sA[DP(t+256*m)] = s[t+256*m];
    __syncthreads();
    float2* X = sA; float2* Y = sB;
#pragma unroll
    for (int st = 0; st < 5; ++st) {
        r4stage<0>(X, Y, tw, t, st);
        __syncthreads();
        float2* tmp = X; X = Y; Y = tmp;
    }
    // pointwise on natural-order spectrum
#pragma unroll
    for (int m = 0; m < 4; ++m) {
        int idx = t + 256*m;
        float2 v = X[DP(idx)];
        if (MODE == 1) {
            float2 w = g_UKER[base + idx];
            float d = 1.f/(w.x*w.x + w.y*w.y);
            v = make_float2((v.x*w.x + v.y*w.y)*d, (v.y*w.x - v.x*w.y)*d);
        } else {
            float mk = g_MASKT[base + idx];
            float2 f0 = g_F0T[base + idx];
            v = make_float2(mk*(2.f*f0.x - mk*v.x), mk*(2.f*f0.y - mk*v.y));
        }
        X[DP(idx)] = v;
    }
    __syncthreads();
#pragma unroll
    for (int st = 0; st < 5; ++st) {
        r4stage<1>(X, Y, tw, t, st);
        __syncthreads();
        float2* tmp = X; X = Y; Y = tmp;
    }
    float2* d = dst + base;
#pragma unroll
    for (int m = 0; m < 4; ++m) {
        float2 v = X[DP(t+256*m)];
        d[t+256*m] = make_float2(v.x*scale, v.y*scale);
    }
}

// ---------------- transposes ----------------
__global__ void k_transpose_c(const float2* __restrict__ src, float2* __restrict__ dst)
{
    __shared__ float2 tile[32][33];
    int b = blockIdx.z;
    const float2* s = src + (size_t)b*FNN;
    float2* d = dst + (size_t)b*FNN;
    int x  = blockIdx.x*32 + threadIdx.x;
    int y0 = blockIdx.y*32 + threadIdx.y;
#pragma unroll
    for (int i = 0; i < 32; i += 8)
        tile[threadIdx.y+i][threadIdx.x] = s[(size_t)(y0+i)*FN + x];
    __syncthreads();
    int x2 = blockIdx.y*32 + threadIdx.x;
    int y2 = blockIdx.x*32 + threadIdx.y;
#pragma unroll
    for (int i = 0; i < 32; i += 8)
        d[(size_t)(y2+i)*FN + x2] = tile[threadIdx.x][threadIdx.y+i];
}

__global__ void k_transpose_r(const float* __restrict__ src, float* __restrict__ dst)
{
    __shared__ float tile[32][33];
    int b = blockIdx.z;
    const float* s = src + (size_t)b*FNN;
    float* d = dst + (size_t)b*FNN;
    int x  = blockIdx.x*32 + threadIdx.x;
    int y0 = blockIdx.y*32 + threadIdx.y;
#pragma unroll
    for (int i = 0; i < 32; i += 8)
        tile[threadIdx.y+i][threadIdx.x] = s[(size_t)(y0+i)*FN + x];
    __syncthreads();
    int x2 = blockIdx.y*32 + threadIdx.x;
    int y2 = blockIdx.x*32 + threadIdx.y;
#pragma unroll
    for (int i = 0; i < 32; i += 8)
        d[(size_t)(y2+i)*FN + x2] = tile[threadIdx.x][threadIdx.y+i];
}

__global__ void k_make_f0T(const float* __restrict__ fr, const float* __restrict__ fi,
                           float2* __restrict__ dst)
{
    __shared__ float tr[32][33];
    __shared__ float ti[32][33];
    int b = blockIdx.z;
    const float* sr = fr + (size_t)b*FNN;
    const float* si = fi + (size_t)b*FNN;
    float2* d = dst + (size_t)b*FNN;
    int x  = blockIdx.x*32 + threadIdx.x;
    int y0 = blockIdx.y*32 + threadIdx.y;
#pragma unroll
    for (int i = 0; i < 32; i += 8) {
        tr[threadIdx.y+i][threadIdx.x] = sr[(size_t)(y0+i)*FN + x];
        ti[threadIdx.y+i][threadIdx.x] = si[(size_t)(y0+i)*FN + x];
    }
    __syncthreads();
    int x2 = blockIdx.y*32 + threadIdx.x;
    int y2 = blockIdx.x*32 + threadIdx.y;
#pragma unroll
    for (int i = 0; i < 32; i += 8)
        d[(size_t)(y2+i)*FN + x2] =
            make_float2(tr[threadIdx.x][threadIdx.y+i], ti[threadIdx.x][threadIdx.y+i]);
}

// ---------------- small init kernels ----------------
__global__ void k_sten()
{
    int t = threadIdx.x;
    if (t >= NB*5) return;
    int b = t / 5, p = t % 5;
    size_t base = (size_t)b*FNN;
    const int yy[5] = {1, 1, 2, FN-1, 1};
    const int xx[5] = {1, 2, 1, 1, FN-1};
    const float vv[5] = {4.f, -1.f, -1.f, -1.f, -1.f};
    g_U[base + (size_t)yy[p]*FN + xx[p]] = vv[p];
}

__global__ void k_uker2(const float* __restrict__ maskT,
                        const float* __restrict__ lam, const float* __restrict__ gama,
                        const float* __restrict__ mmu)
{
    int i = blockIdx.x*blockDim.x + threadIdx.x;
    if (i >= TOT) return;
    float m = maskT[i];
    float2 sf = g_CA[i];
    float lv = lam[0];
    g_UKER[i] = make_float2(mmu[0]*m*m + gama[0] + lv*sf.x, lv*sf.y);
}

// ---------------- spatial elementwise ----------------
__global__ void k_rhs(const float* __restrict__ lam, const float* __restrict__ gama,
                      const float* __restrict__ mmu)
{
    int i = blockIdx.x*blockDim.x + threadIdx.x;
    if (i >= TOT) return;
    int x = i & (FN-1);
    int y = (i >> 10) & (FN-1);
    int rowb = i - x;
    float dxt = 0.f;
    if (x >= 1) {
        int xn = (x == FN-1) ? 1 : x+1;
        float v0 = g_DX[i] - g_BX[i];
        float v1 = g_DX[rowb + xn] - g_BX[rowb + xn];
        dxt = v0 - v1;
    }
    float dyt = 0.f;
    if (y >= 1) {
        int yn = (y == FN-1) ? 1 : y+1;
        int j = i + (yn - y)*FN;
        float v0 = g_DY[i] - g_BY[i];
        float v1 = g_DY[j] - g_BY[j];
        dyt = v0 - v1;
    }
    float2 mu = g_MURF[i];
    float mv = mmu[0];
    g_CA[i] = make_float2(mv*mu.x + lam[0]*(dxt + dyt) + gama[0]*g_IDWT[i], mv*mu.y);
}

__global__ void k_shrink(const float* __restrict__ lam, const float* __restrict__ prelu)
{
    int i = blockIdx.x*blockDim.x + threadIdx.x;
    if (i >= TOT) return;
    float a  = prelu[0];
    float il = 1.f/lam[0];
    float vx = g_DX[i] + g_BX[i];
    float vy = g_DY[i] + g_BY[i];
    float s = sqrtf(vx*vx + vy*vy);
    float nx = vx - s*il;
    float ny = vy - s*il;
    g_DX[i] = (nx >= 0.f) ? nx : a*nx;
    g_DY[i] = (ny >= 0.f) ? ny : a*ny;
}

__global__ void k_bxy()
{
    int i = blockIdx.x*blockDim.x + threadIdx.x;
    if (i >= TOT) return;
    int x = i & (FN-1);
    int y = (i >> 10) & (FN-1);
    int rowb = i - x;
    float dxu = 0.f;
    if (x >= 1) {
        int xm = (x == 1) ? FN-1 : x-1;
        dxu = g_U[i] - g_U[rowb + xm];
    }
    g_BX[i] += dxu - g_DX[i];
    float dyu = 0.f;
    if (y >= 1) {
        int ym = (y == 1) ? FN-1 : y-1;
        dyu = g_U[i] - g_U[i + (ym - y)*FN];
    }
    g_BY[i] += dyu - g_DY[i];
}

__global__ void k_wupd(const float* __restrict__ uarr, float* __restrict__ bw,
                       float* __restrict__ w, int n,
                       const float* __restrict__ gama, const float* __restrict__ prelu)
{
    int i = blockIdx.x*blockDim.x + threadIdx.x;
    if (i >= n) return;
    float a  = prelu[0];
    float ig = 1.f/gama[0];
    float uv = uarr[i], bv = bw[i];
    float t = uv + bv - ig;
    float wv = (t >= 0.f) ? t : a*t;
    w[i]  = wv;
    bw[i] = bv + uv - wv;
}

// ---------------- DWT analysis ----------------
__global__ void k_afb_w(const float* __restrict__ src, float* __restrict__ lo,
                        float* __restrict__ hi)
{
    int i = blockIdx.x*blockDim.x + threadIdx.x;
    if (i >= NB*FN*WD) return;
    int o = i % WD;
    int r = i / WD;
    const float* row = src + (size_t)r*FN;
    float l = 0.f, h = 0.f;
#pragma unroll
    for (int k = 0; k < 14; ++k) {
        int j = 2*o + k - 12;
        j = (j < 0) ? -j : ((j >= FN) ? (2*FN - 2 - j) : j);
        float v = row[j];
        l += v * cH0A[k];
        h += v * cH1A[k];
    }
    lo[i] = l;
    hi[i] = h;
}

__global__ void k_afb_h(const float* __restrict__ src, float* __restrict__ lo,
                        float* __restrict__ hi)
{
    int i = blockIdx.x*blockDim.x + threadIdx.x;
    if (i >= SLL) return;
    int w = i % WD;
    int o = (i / WD) % WD;
    int b = i / (WD*WD);
    const float* base = src + (size_t)b*FN*WD;
    float l = 0.f, h = 0.f;
#pragma unroll
    for (int k = 0; k < 14; ++k) {
        int j = 2*o + k - 12;
        j = (j < 0) ? -j : ((j >= FN) ? (2*FN - 2 - j) : j);
        float v = base[(size_t)j*WD + w];
        l += v * cH0A[k];
        h += v * cH1A[k];
    }
    lo[i] = l;
    hi[i] = h;
}

// ---------------- IDWT synthesis ----------------
__global__ void k_sfb_h(const float* __restrict__ loA, const float* __restrict__ loB,
                        const float* __restrict__ hiA, const float* __restrict__ hiB,
                        float* __restrict__ out)
{
    int i = blockIdx.x*blockDim.x + threadIdx.x;
    if (i >= NB*FN*WD) return;
    int w = i % WD;
    int o = (i / WD) % FN;
    int b = i / (FN*WD);
    size_t bb = (size_t)b*WD*WD;
    float acc = 0.f;
    int k0 = (o + 1) & 1;
#pragma unroll
    for (int kk = 0; kk < 7; ++kk) {
        int k = k0 + 2*kk;
        int m = (o + k - 1) >> 1;
        size_t idx = bb + (size_t)m*WD + w;
        float lo = loA[idx] - loB[idx];
        float hi = hiA[idx] - hiB[idx];
        acc += lo * cG0[k] + hi * cG1[k];
    }
    out[i] = acc;
}

__global__ void k_sfb_w(const float* __restrict__ lo, const float* __restrict__ hi,
                        float* __restrict__ out)
{
    int i = blockIdx.x*blockDim.x + threadIdx.x;
    if (i >= TOT) return;
    int x = i & (FN-1);
    int r = i >> 10;
    const float* lrow = lo + (size_t)r*WD;
    const float* hrow = hi + (size_t)r*WD;
    float acc = 0.f;
    int k0 = (x + 1) & 1;
#pragma unroll
    for (int kk = 0; kk < 7; ++kk) {
        int k = k0 + 2*kk;
        int m = (x + k - 1) >> 1;
        acc += lrow[m] * cG0[k] + hrow[m] * cG1[k];
    }
    out[i] = acc;
}

// ---------------- host orchestration ----------------
static inline int eb(int n) { return (n + 255) / 256; }

extern "C" void kernel_launch(void* const* d_in, const int* in_sizes, int n_in,
                              void* d_out, int out_size)
{
    const float* u_in   = (const float*)d_in[0];
    const float* uvMask = (const float*)d_in[1];
    const float* f_real = (const float*)d_in[3];
    const float* f_imag = (const float*)d_in[4];
    const float* lam    = (const float*)d_in[5];
    const float* gama   = (const float*)d_in[6];
    const float* mmu    = (const float*)d_in[7];
    const float* prelu  = (const float*)d_in[8];
    float* out = (float*)d_out;

    void *pCA, *pCB, *pMURF, *pU, *pIDWT, *pMASKT, *pF0T;
    void *pDX, *pDY, *pBX, *pBY;
    void *pWL, *pBWL, *pUL, *pWH, *pBWH, *pUH;
    void *pLOT, *pHIT, *pLOS, *pHIS;
    cudaGetSymbolAddress(&pCA, g_CA);       cudaGetSymbolAddress(&pCB, g_CB);
    cudaGetSymbolAddress(&pMURF, g_MURF);   cudaGetSymbolAddress(&pU, g_U);
    cudaGetSymbolAddress(&pIDWT, g_IDWT);   cudaGetSymbolAddress(&pMASKT, g_MASKT);
    cudaGetSymbolAddress(&pF0T, g_F0T);
    cudaGetSymbolAddress(&pDX, g_DX);       cudaGetSymbolAddress(&pDY, g_DY);
    cudaGetSymbolAddress(&pBX, g_BX);       cudaGetSymbolAddress(&pBY, g_BY);
    cudaGetSymbolAddress(&pWL, g_WL);       cudaGetSymbolAddress(&pBWL, g_BWL);
    cudaGetSymbolAddress(&pUL, g_UL);       cudaGetSymbolAddress(&pWH, g_WH);
    cudaGetSymbolAddress(&pBWH, g_BWH);     cudaGetSymbolAddress(&pUH, g_UH);
    cudaGetSymbolAddress(&pLOT, g_LOT);     cudaGetSymbolAddress(&pHIT, g_HIT);
    cudaGetSymbolAddress(&pLOS, g_LOS);     cudaGetSymbolAddress(&pHIS, g_HIS);

    dim3 tb(32, 8), tg(32, 32, NB);
    const int FFTG = NB*FN;

    // ----- init -----
    k_transpose_r<<<tg, tb>>>(uvMask, (float*)pMASKT);
    k_make_f0T<<<tg, tb>>>(f_real, f_imag, (float2*)pF0T);
    cudaMemsetAsync(pDX, 0, (size_t)TOT*4, 0);
    cudaMemsetAsync(pDY, 0, (size_t)TOT*4, 0);
    cudaMemsetAsync(pBX, 0, (size_t)TOT*4, 0);
    cudaMemsetAsync(pBY, 0, (size_t)TOT*4, 0);
    cudaMemsetAsync(pBWL, 0, (size_t)SLL*4, 0);
    cudaMemsetAsync(pBWH, 0, (size_t)(3*SLL)*4, 0);

    // ----- uker: numeric fft2 of stencil, kept in [p][q] -----
    cudaMemsetAsync(pU, 0, (size_t)TOT*4, 0);
    k_sten<<<1, 32>>>();
    k_fft4<0><<<FFTG, 256>>>(pU, pCA, 1, 0, 1.f, prelu, 0);     // [y][p]
    k_transpose_c<<<tg, tb>>>((float2*)pCA, (float2*)pCB);      // [p][y]
    k_fft4<0><<<FFTG, 256>>>(pCB, pCA, 0, 0, 1.f, prelu, 0);    // [p][q]
    k_uker2<<<eb(TOT), 256>>>((float*)pMASKT, lam, gama, mmu);

    // ----- dwt2(u_in) -----
    k_afb_w<<<eb(NB*FN*WD), 256>>>(u_in, (float*)pLOT, (float*)pHIT);
    k_afb_h<<<eb(SLL), 256>>>((float*)pLOT, (float*)pWL, (float*)pWH);
    k_afb_h<<<eb(SLL), 256>>>((float*)pHIT, (float*)pWH + (size_t)SLL,
                              (float*)pWH + (size_t)2*SLL);

    // ----- murf = ifft2(mask*f0): preOp=3 -----
    k_fft4<1><<<FFTG, 256>>>(pF0T, pCB, 0, 0, 1.f/FN, prelu, 3);  // [p][y]
    k_transpose_c<<<tg, tb>>>((float2*)pCB, (float2*)pCA);        // [y][p]
    k_fft4<1><<<FFTG, 256>>>(pCA, pMURF, 0, 0, 1.f/FN, prelu, 0); // normal

    // ----- iterations -----
    for (int it = 0; it < 2; ++it) {
        k_sfb_h<<<eb(NB*FN*WD), 256>>>((float*)pWL, (float*)pBWL,
                                       (float*)pWH, (float*)pBWH, (float*)pLOS);
        k_sfb_h<<<eb(NB*FN*WD), 256>>>((float*)pWH + (size_t)SLL,
                                       (float*)pBWH + (size_t)SLL,
                                       (float*)pWH + (size_t)2*SLL,
                                       (float*)pBWH + (size_t)2*SLL, (float*)pHIS);
        k_sfb_w<<<eb(TOT), 256>>>((float*)pLOS, (float*)pHIS, (float*)pIDWT);

        k_rhs<<<eb(TOT), 256>>>(lam, gama, mmu);
        k_fft4<0><<<FFTG, 256>>>(pCA, pCB, 0, 0, 1.f, prelu, 0);      // [y][p]
        k_transpose_c<<<tg, tb>>>((float2*)pCB, (float2*)pCA);        // [p][y]
        k_fftpair<1><<<FFTG, 256>>>((float2*)pCA, (float2*)pCB, 1.f/FN); // fwd+div+inv
        k_transpose_c<<<tg, tb>>>((float2*)pCB, (float2*)pCA);        // [y][p]
        void* udst = (it == 0) ? pU : (void*)out;
        k_fft4<1><<<FFTG, 256>>>(pCA, udst, 0, 1, 1.f/FN, prelu, 0);  // u + srelu

        if (it == 0) {
            k_shrink<<<eb(TOT), 256>>>(lam, prelu);
            k_afb_w<<<eb(NB*FN*WD), 256>>>((float*)pU, (float*)pLOT, (float*)pHIT);
            k_afb_h<<<eb(SLL), 256>>>((float*)pLOT, (float*)pUL, (float*)pUH);
            k_afb_h<<<eb(SLL), 256>>>((float*)pHIT, (float*)pUH + (size_t)SLL,
                                      (float*)pUH + (size_t)2*SLL);
            k_wupd<<<eb(SLL), 256>>>((float*)pUL, (float*)pBWL, (float*)pWL,
                                     SLL, gama, prelu);
            k_wupd<<<eb(3*SLL), 256>>>((float*)pUH, (float*)pBWH, (float*)pWH,
                                       3*SLL, gama, prelu);
            k_bxy<<<eb(TOT), 256>>>();
            k_fft4<0><<<FFTG, 256>>>(pU, pCA, 1, 0, 1.f, prelu, 0);       // [y][p]
            k_transpose_c<<<tg, tb>>>((float2*)pCA, (float2*)pCB);        // [p][y]
            k_fftpair<2><<<FFTG, 256>>>((float2*)pCB, (float2*)pCA, 1.f/FN); // fwd+fupd+inv
            k_transpose_c<<<tg, tb>>>((float2*)pCA, (float2*)pCB);        // [y][p]
            k_fft4<1><<<FFTG, 256>>>(pCB, pMURF, 0, 0, 1.f/FN, prelu, 0); // normal
        }
    }
    (void)in_sizes; (void)n_in; (void)out_size;
}

// round 8
// speedup vs baseline: 1.7229x; 1.0799x over previous
#include <cuda_runtime.h>
#include <math.h>

#define FN   1024
#define NB   4
#define FNN  (FN*FN)
#define TOT  (NB*FNN)
#define WD   518
#define SLL  (NB*WD*WD)
#define SLW  (NB*FN*WD)
#define PIF  3.14159265358979323846f

#define DP(i) ((i) + ((i)>>2))
#define TP(i) ((i) + ((i)>>4))

// ---------------- static device scratch ----------------
__device__ float2 g_CA[TOT];
__device__ float2 g_CB[TOT];
__device__ float2 g_UKER[TOT];   // [p][q]
__device__ float2 g_F0T[TOT];    // [p][q]
__device__ float2 g_MURF[TOT];   // normal
__device__ float2 g_TW[FN];

__device__ float g_U[TOT];
__device__ float g_DX[TOT];
__device__ float g_DY[TOT];
__device__ float g_BX[TOT];
__device__ float g_BY[TOT];
__device__ float g_MASKT[TOT];
__device__ float g_IDWT[TOT];

__device__ float g_WL[SLL];
__device__ float g_BWL[SLL];
__device__ float g_UL[SLL];
__device__ float g_WH[3*SLL];
__device__ float g_BWH[3*SLL];
__device__ float g_UH[3*SLL];
__device__ float g_LOT[SLW];
__device__ float g_HIT[SLW];
__device__ float g_LOS[SLW];
__device__ float g_HIS[SLW];

// ---------------- wavelet filters (db7, L=14) ----------------
__constant__ float cH0A[14] = {
    0.010268176708511255f, 0.004010244871533663f, -0.10780823770381774f,
   -0.14004724044296152f, 0.2886296317515146f, 0.767764317003164f,
    0.5361019170917628f, 0.017441255086855827f, -0.049552834937127255f,
    0.0678926935013727f, 0.03051551316596357f, -0.01263630340325193f,
   -0.0010473848886829163f, 0.002681814568257878f };
__constant__ float cH1A[14] = {
    0.002681814568257878f, 0.0010473848886829163f, -0.01263630340325193f,
   -0.03051551316596357f, 0.0678926935013727f, 0.049552834937127255f,
    0.017441255086855827f, -0.5361019170917628f, 0.767764317003164f,
   -0.2886296317515146f, -0.14004724044296152f, 0.10780823770381774f,
    0.004010244871533663f, -0.010268176708511255f };
__constant__ float cG0[14] = {
    0.002681814568257878f, -0.0010473848886829163f, -0.01263630340325193f,
    0.03051551316596357f, 0.0678926935013727f, -0.049552834937127255f,
    0.017441255086855827f, 0.5361019170917628f, 0.767764317003164f,
    0.2886296317515146f, -0.14004724044296152f, -0.10780823770381774f,
    0.004010244871533663f, 0.010268176708511255f };
__constant__ float cG1[14] = {
   -0.010268176708511255f, 0.004010244871533663f, 0.10780823770381774f,
   -0.14004724044296152f, -0.2886296317515146f, 0.767764317003164f,
   -0.5361019170917628f, 0.017441255086855827f, 0.049552834937127255f,
    0.0678926935013727f, -0.03051551316596357f, -0.01263630340325193f,
    0.0010473848886829163f, 0.002681814568257878f };

__device__ __forceinline__ float2 cmulf(float2 a, float2 b) {
    return make_float2(a.x*b.x - a.y*b.y, a.x*b.y + a.y*b.x);
}

__global__ void k_twinit()
{
    int j = blockIdx.x*blockDim.x + threadIdx.x;
    if (j >= FN) return;
    float sv, cv; sincosf(-2.f*PIF*(float)j/(float)FN, &sv, &cv);
    g_TW[j] = make_float2(cv, sv);
}

template<int INV>
__device__ __forceinline__ void r4stage(const float2* __restrict__ X,
                                        float2* __restrict__ Y,
                                        const float2* __restrict__ tw,
                                        int t, int s)
{
    int ns = 1 << (2*s);
    int k  = t & (ns - 1);
    int j  = ((t - k) << 2) + k;
    int sh = 8 - 2*s;
    float2 c0 = X[DP(t)], c1 = X[DP(t+256)], c2 = X[DP(t+512)], c3 = X[DP(t+768)];
    float2 w1 = tw[TP(k << sh)];
    float2 w2 = tw[TP((2*k) << sh)];
    float2 w3 = tw[TP((3*k) << sh)];
    if (INV) { w1.y = -w1.y; w2.y = -w2.y; w3.y = -w3.y; }
    c1 = cmulf(c1, w1); c2 = cmulf(c2, w2); c3 = cmulf(c3, w3);
    float2 t0 = make_float2(c0.x+c2.x, c0.y+c2.y);
    float2 t1 = make_float2(c0.x-c2.x, c0.y-c2.y);
    float2 t2 = make_float2(c1.x+c3.x, c1.y+c3.y);
    float2 dd = make_float2(c1.x-c3.x, c1.y-c3.y);
    float2 t3 = INV ? make_float2(-dd.y, dd.x) : make_float2(dd.y, -dd.x);
    Y[DP(j)]      = make_float2(t0.x+t2.x, t0.y+t2.y);
    Y[DP(j+ns)]   = make_float2(t1.x+t3.x, t1.y+t3.y);
    Y[DP(j+2*ns)] = make_float2(t0.x-t2.x, t0.y-t2.y);
    Y[DP(j+3*ns)] = make_float2(t1.x-t3.x, t1.y-t3.y);
}

// preOp: 0 none; 3 load = maskT*f0T; 4 load = rhs (src ignored)
template<int INV>
__global__ __launch_bounds__(256) void k_fft4(const void* __restrict__ srcv,
                                              void* __restrict__ dstv,
                                              int inReal, int outReal,
                                              float scale,
                                              const float* __restrict__ prelu,
                                              int preOp,
                                              const float* __restrict__ lam,
                                              const float* __restrict__ gama,
                                              const float* __restrict__ mmu)
{
    __shared__ float2 sA[1280];
    __shared__ float2 sB[1280];
    __shared__ float2 tw[1088];
    int t = threadIdx.x;
    size_t base = (size_t)blockIdx.x*FN;
    for (int j = t; j < FN; j += 256) tw[TP(j)] = g_TW[j];
    if (inReal) {
        const float* s = (const float*)srcv + base;
#pragma unroll
        for (int m = 0; m < 4; ++m) sA[DP(t+256*m)] = make_float2(s[t+256*m], 0.f);
    } else if (preOp == 4) {
        int y = blockIdx.x & (FN-1);
        float lv = lam[0], gv = gama[0], mv = mmu[0];
#pragma unroll
        for (int m = 0; m < 4; ++m) {
            int x = t + 256*m;
            size_t i = base + x;
            float dxt = 0.f;
            if (x >= 1) {
                int xn = (x == FN-1) ? 1 : x+1;
                dxt = (g_DX[i] - g_BX[i]) - (g_DX[base+xn] - g_BX[base+xn]);
            }
            float dyt = 0.f;
            if (y >= 1) {
                int yn = (y == FN-1) ? 1 : y+1;
                size_t jj = i + (size_t)(yn - y)*FN;
                dyt = (g_DY[i] - g_BY[i]) - (g_DY[jj] - g_BY[jj]);
            }
            float2 mu = g_MURF[i];
            sA[DP(x)] = make_float2(mv*mu.x + lv*(dxt + dyt) + gv*g_IDWT[i],
                                    mv*mu.y);
        }
    } else {
        const float2* s = (const float2*)srcv + base;
#pragma unroll
        for (int m = 0; m < 4; ++m) {
            int idx = t + 256*m;
            float2 v = s[idx];
            if (preOp == 3) {
                float mk = g_MASKT[base + idx];
                float2 f0 = g_F0T[base + idx];
                v = make_float2(mk*f0.x, mk*f0.y);
            }
            sA[DP(idx)] = v;
        }
    }
    __syncthreads();
    float2* X = sA; float2* Y = sB;
#pragma unroll
    for (int s = 0; s < 5; ++s) {
        r4stage<INV>(X, Y, tw, t, s);
        __syncthreads();
        float2* tmp = X; X = Y; Y = tmp;
    }
    if (!outReal) {
        float2* d = (float2*)dstv + base;
#pragma unroll
        for (int m = 0; m < 4; ++m) {
            float2 v = X[DP(t+256*m)];
            d[t+256*m] = make_float2(v.x*scale, v.y*scale);
        }
    } else {
        float a = prelu[0];
        float* d = (float*)dstv + base;
#pragma unroll
        for (int m = 0; m < 4; ++m) {
            float v = X[DP(t+256*m)].x * scale;
            d[t+256*m] = (v >= 0.f) ? v : a*v;
        }
    }
}

// MODE 1: v /= UKER[p][q];  MODE 2: v = m*(2*f0T - m*v)
template<int MODE>
__global__ __launch_bounds__(256) void k_fftpair(const float2* __restrict__ src,
                                                 float2* __restrict__ dst,
                                                 float scale)
{
    __shared__ float2 sA[1280];
    __shared__ float2 sB[1280];
    __shared__ float2 tw[1088];
    int t = threadIdx.x;
    size_t base = (size_t)blockIdx.x*FN;
    for (int j = t; j < FN; j += 256) tw[TP(j)] = g_TW[j];
    const float2* s = src + base;
#pragma unroll
    for (int m = 0; m < 4; ++m) sA[DP(t+256*m)] = s[t+256*m];
    __syncthreads();
    float2* X = sA; float2* Y = sB;
#pragma unroll
    for (int st = 0; st < 5; ++st) {
        r4stage<0>(X, Y, tw, t, st);
        __syncthreads();
        float2* tmp = X; X = Y; Y = tmp;
    }
#pragma unroll
    for (int m = 0; m < 4; ++m) {
        int idx = t + 256*m;
        float2 v = X[DP(idx)];
        if (MODE == 1) {
            float2 w = g_UKER[base + idx];
            float d = 1.f/(w.x*w.x + w.y*w.y);
            v = make_float2((v.x*w.x + v.y*w.y)*d, (v.y*w.x - v.x*w.y)*d);
        } else {
            float mk = g_MASKT[base + idx];
            float2 f0 = g_F0T[base + idx];
            v = make_float2(mk*(2.f*f0.x - mk*v.x), mk*(2.f*f0.y - mk*v.y));
        }
        X[DP(idx)] = v;
    }
    __syncthreads();
#pragma unroll
    for (int st = 0; st < 5; ++st) {
        r4stage<1>(X, Y, tw, t, st);
        __syncthreads();
        float2* tmp = X; X = Y; Y = tmp;
    }
    float2* d = dst + base;
#pragma unroll
    for (int m = 0; m < 4; ++m) {
        float2 v = X[DP(t+256*m)];
        d[t+256*m] = make_float2(v.x*scale, v.y*scale);
    }
}

// ---------------- transposes ----------------
__global__ void k_transpose_c(const float2* __restrict__ src, float2* __restrict__ dst)
{
    __shared__ float2 tile[32][33];
    int b = blockIdx.z;
    const float2* s = src + (size_t)b*FNN;
    float2* d = dst + (size_t)b*FNN;
    int x  = blockIdx.x*32 + threadIdx.x;
    int y0 = blockIdx.y*32 + threadIdx.y;
#pragma unroll
    for (int i = 0; i < 32; i += 8)
        tile[threadIdx.y+i][threadIdx.x] = s[(size_t)(y0+i)*FN + x];
    __syncthreads();
    int x2 = blockIdx.y*32 + threadIdx.x;
    int y2 = blockIdx.x*32 + threadIdx.y;
#pragma unroll
    for (int i = 0; i < 32; i += 8)
        d[(size_t)(y2+i)*FN + x2] = tile[threadIdx.x][threadIdx.y+i];
}

__global__ void k_transpose_r(const float* __restrict__ src, float* __restrict__ dst)
{
    __shared__ float tile[32][33];
    int b = blockIdx.z;
    const float* s = src + (size_t)b*FNN;
    float* d = dst + (size_t)b*FNN;
    int x  = blockIdx.x*32 + threadIdx.x;
    int y0 = blockIdx.y*32 + threadIdx.y;
#pragma unroll
    for (int i = 0; i < 32; i += 8)
        tile[threadIdx.y+i][threadIdx.x] = s[(size_t)(y0+i)*FN + x];
    __syncthreads();
    int x2 = blockIdx.y*32 + threadIdx.x;
    int y2 = blockIdx.x*32 + threadIdx.y;
#pragma unroll
    for (int i = 0; i < 32; i += 8)
        d[(size_t)(y2+i)*FN + x2] = tile[threadIdx.x][threadIdx.y+i];
}

__global__ void k_make_f0T(const float* __restrict__ fr, const float* __restrict__ fi,
                           float2* __restrict__ dst)
{
    __shared__ float tr[32][33];
    __shared__ float ti[32][33];
    int b = blockIdx.z;
    const float* sr = fr + (size_t)b*FNN;
    const float* si = fi + (size_t)b*FNN;
    float2* d = dst + (size_t)b*FNN;
    int x  = blockIdx.x*32 + threadIdx.x;
    int y0 = blockIdx.y*32 + threadIdx.y;
#pragma unroll
    for (int i = 0; i < 32; i += 8) {
        tr[threadIdx.y+i][threadIdx.x] = sr[(size_t)(y0+i)*FN + x];
        ti[threadIdx.y+i][threadIdx.x] = si[(size_t)(y0+i)*FN + x];
    }
    __syncthreads();
    int x2 = blockIdx.y*32 + threadIdx.x;
    int y2 = blockIdx.x*32 + threadIdx.y;
#pragma unroll
    for (int i = 0; i < 32; i += 8)
        d[(size_t)(y2+i)*FN + x2] =
            make_float2(tr[threadIdx.x][threadIdx.y+i], ti[threadIdx.x][threadIdx.y+i]);
}

// ---------------- analytic UKER (corrected) ----------------
// stencil taps at offsets (0,+1),(+1,0),(0,-2),(-2,0) from (1,1):
// F = e^{-i(th_p+th_q)} * B,  B = 4 - E(p) - E(q) - E(-2p) - E(-2q)
// Br = 4 - cos th_p - cos th_q - cos 2th_p - cos 2th_q
// Bi = sin th_p + sin th_q - sin 2th_p - sin 2th_q
__global__ void k_ukerA(const float* __restrict__ lam, const float* __restrict__ gama,
                        const float* __restrict__ mmu)
{
    int i = blockIdx.x*blockDim.x + threadIdx.x;
    if (i >= TOT) return;
    int q = i & (FN-1);
    int p = (i >> 10) & (FN-1);
    float m = g_MASKT[i];
    float thp = 2.f*PIF*(float)p/(float)FN;
    float thq = 2.f*PIF*(float)q/(float)FN;
    float sp, cp, sq, cq, sp2, cp2, sq2, cq2;
    sincosf(thp, &sp, &cp);
    sincosf(thq, &sq, &cq);
    sincosf(2.f*thp, &sp2, &cp2);
    sincosf(2.f*thq, &sq2, &cq2);
    float Br = 4.f - cp - cq - cp2 - cq2;
    float Bi = sp + sq - sp2 - sq2;
    float sf, cf; sincosf(thp + thq, &sf, &cf);
    float Fr = Br*cf + Bi*sf;
    float Fi = Bi*cf - Br*sf;
    float lv = lam[0];
    g_UKER[i] = make_float2(mmu[0]*m*m + gama[0] + lv*Fr, lv*Fi);
}

// ---------------- fused shrink + b-update ----------------
__global__ void k_shrinkbxy(const float* __restrict__ lam,
                            const float* __restrict__ prelu)
{
    int i = blockIdx.x*blockDim.x + threadIdx.x;
    if (i >= TOT) return;
    float a  = prelu[0];
    float il = 1.f/lam[0];
    float dx = g_DX[i], dy = g_DY[i], bx = g_BX[i], by = g_BY[i];
    float vx = dx + bx;
    float vy = dy + by;
    float s = sqrtf(vx*vx + vy*vy);
    float nx = vx - s*il;
    float ny = vy - s*il;
    nx = (nx >= 0.f) ? nx : a*nx;
    ny = (ny >= 0.f) ? ny : a*ny;
    int x = i & (FN-1);
    int y = (i >> 10) & (FN-1);
    int rowb = i - x;
    float dxu = 0.f;
    if (x >= 1) {
        int xm = (x == 1) ? FN-1 : x-1;
        dxu = g_U[i] - g_U[rowb + xm];
    }
    float dyu = 0.f;
    if (y >= 1) {
        int ym = (y == 1) ? FN-1 : y-1;
        dyu = g_U[i] - g_U[i + (ym - y)*FN];
    }
    g_DX[i] = nx;  g_DY[i] = ny;
    g_BX[i] = bx + dxu - nx;
    g_BY[i] = by + dyu - ny;
}

__global__ void k_wupd(const float* __restrict__ uarr, float* __restrict__ bw,
                       float* __restrict__ w, int n,
                       const float* __restrict__ gama, const float* __restrict__ prelu)
{
    int i = blockIdx.x*blockDim.x + threadIdx.x;
    if (i >= n) return;
    float a  = prelu[0];
    float ig = 1.f/gama[0];
    float uv = uarr[i], bv = bw[i];
    float t = uv + bv - ig;
    float wv = (t >= 0.f) ? t : a*t;
    w[i]  = wv;
    bw[i] = bv + uv - wv;
}

// ---------------- DWT analysis ----------------
__global__ void k_afb_w(const float* __restrict__ src, float* __restrict__ lo,
                        float* __restrict__ hi)
{
    int i = blockIdx.x*blockDim.x + threadIdx.x;
    if (i >= NB*FN*WD) return;
    int o = i % WD;
    int r = i / WD;
    const float* row = src + (size_t)r*FN;
    float l = 0.f, h = 0.f;
#pragma unroll
    for (int k = 0; k < 14; ++k) {
        int j = 2*o + k - 12;
        j = (j < 0) ? -j : ((j >= FN) ? (2*FN - 2 - j) : j);
        float v = row[j];
        l += v * cH0A[k];
        h += v * cH1A[k];
    }
    lo[i] = l;
    hi[i] = h;
}

__global__ void k_afb_h(const float* __restrict__ src, float* __restrict__ lo,
                        float* __restrict__ hi)
{
    int i = blockIdx.x*blockDim.x + threadIdx.x;
    if (i >= SLL) return;
    int w = i % WD;
    int o = (i / WD) % WD;
    int b = i / (WD*WD);
    const float* base = src + (size_t)b*FN*WD;
    float l = 0.f, h = 0.f;
#pragma unroll
    for (int k = 0; k < 14; ++k) {
        int j = 2*o + k - 12;
        j = (j < 0) ? -j : ((j >= FN) ? (2*FN - 2 - j) : j);
        float v = base[(size_t)j*WD + w];
        l += v * cH0A[k];
        h += v * cH1A[k];
    }
    lo[i] = l;
    hi[i] = h;
}

// ---------------- IDWT synthesis ----------------
__global__ void k_sfb_h(const float* __restrict__ loA, const float* __restrict__ loB,
                        const float* __restrict__ hiA, const float* __restrict__ hiB,
                        float* __restrict__ out)
{
    int i = blockIdx.x*blockDim.x + threadIdx.x;
    if (i >= NB*FN*WD) return;
    int w = i % WD;
    int o = (i / WD) % FN;
    int b = i / (FN*WD);
    size_t bb = (size_t)b*WD*WD;
    float acc = 0.f;
    int k0 = (o + 1) & 1;
#pragma unroll
    for (int kk = 0; kk < 7; ++kk) {
        int k = k0 + 2*kk;
        int m = (o + k - 1) >> 1;
        size_t idx = bb + (size_t)m*WD + w;
        float lo = loA[idx] - loB[idx];
        float hi = hiA[idx] - hiB[idx];
        acc += lo * cG0[k] + hi * cG1[k];
    }
    out[i] = acc;
}

__global__ void k_sfb_w(const float* __restrict__ lo, const float* __restrict__ hi,
                        float* __restrict__ out)
{
    int i = blockIdx.x*blockDim.x + threadIdx.x;
    if (i >= TOT) return;
    int x = i & (FN-1);
    int r = i >> 10;
    const float* lrow = lo + (size_t)r*WD;
    const float* hrow = hi + (size_t)r*WD;
    float acc = 0.f;
    int k0 = (x + 1) & 1;
#pragma unroll
    for (int kk = 0; kk < 7; ++kk) {
        int k = k0 + 2*kk;
        int m = (x + k - 1) >> 1;
        acc += lrow[m] * cG0[k] + hrow[m] * cG1[k];
    }
    out[i] = acc;
}

// ---------------- host orchestration ----------------
static inline int eb(int n) { return (n + 255) / 256; }

extern "C" void kernel_launch(void* const* d_in, const int* in_sizes, int n_in,
                              void* d_out, int out_size)
{
    const float* u_in   = (const float*)d_in[0];
    const float* uvMask = (const float*)d_in[1];
    const float* f_real = (const float*)d_in[3];
    const float* f_imag = (const float*)d_in[4];
    const float* lam    = (const float*)d_in[5];
    const float* gama   = (const float*)d_in[6];
    const float* mmu    = (const float*)d_in[7];
    const float* prelu  = (const float*)d_in[8];
    float* out = (float*)d_out;

    void *pCA, *pCB, *pMURF, *pU, *pIDWT, *pMASKT, *pF0T;
    void *pDX, *pDY, *pBX, *pBY;
    void *pWL, *pBWL, *pUL, *pWH, *pBWH, *pUH;
    void *pLOT, *pHIT, *pLOS, *pHIS;
    cudaGetSymbolAddress(&pCA, g_CA);       cudaGetSymbolAddress(&pCB, g_CB);
    cudaGetSymbolAddress(&pMURF, g_MURF);   cudaGetSymbolAddress(&pU, g_U);
    cudaGetSymbolAddress(&pIDWT, g_IDWT);   cudaGetSymbolAddress(&pMASKT, g_MASKT);
    cudaGetSymbolAddress(&pF0T, g_F0T);
    cudaGetSymbolAddress(&pDX, g_DX);       cudaGetSymbolAddress(&pDY, g_DY);
    cudaGetSymbolAddress(&pBX, g_BX);       cudaGetSymbolAddress(&pBY, g_BY);
    cudaGetSymbolAddress(&pWL, g_WL);       cudaGetSymbolAddress(&pBWL, g_BWL);
    cudaGetSymbolAddress(&pUL, g_UL);       cudaGetSymbolAddress(&pWH, g_WH);
    cudaGetSymbolAddress(&pBWH, g_BWH);     cudaGetSymbolAddress(&pUH, g_UH);
    cudaGetSymbolAddress(&pLOT, g_LOT);     cudaGetSymbolAddress(&pHIT, g_HIT);
    cudaGetSymbolAddress(&pLOS, g_LOS);     cudaGetSymbolAddress(&pHIS, g_HIS);

    dim3 tb(32, 8), tg(32, 32, NB);
    const int FFTG = NB*FN;

    // ----- init -----
    k_twinit<<<4, 256>>>();
    k_transpose_r<<<tg, tb>>>(uvMask, (float*)pMASKT);
    k_make_f0T<<<tg, tb>>>(f_real, f_imag, (float2*)pF0T);
    cudaMemsetAsync(pDX, 0, (size_t)TOT*4, 0);
    cudaMemsetAsync(pDY, 0, (size_t)TOT*4, 0);
    cudaMemsetAsync(pBX, 0, (size_t)TOT*4, 0);
    cudaMemsetAsync(pBY, 0, (size_t)TOT*4, 0);
    cudaMemsetAsync(pBWL, 0, (size_t)SLL*4, 0);
    cudaMemsetAsync(pBWH, 0, (size_t)(3*SLL)*4, 0);

    // ----- analytic uker (needs MASKT) -----
    k_ukerA<<<eb(TOT), 256>>>(lam, gama, mmu);

    // ----- dwt2(u_in) -----
    k_afb_w<<<eb(NB*FN*WD), 256>>>(u_in, (float*)pLOT, (float*)pHIT);
    k_afb_h<<<eb(SLL), 256>>>((float*)pLOT, (float*)pWL, (float*)pWH);
    k_afb_h<<<eb(SLL), 256>>>((float*)pHIT, (float*)pWH + (size_t)SLL,
                              (float*)pWH + (size_t)2*SLL);

    // ----- murf = ifft2(mask*f0): preOp=3 -----
    k_fft4<1><<<FFTG, 256>>>(pF0T, pCB, 0, 0, 1.f/FN, prelu, 3, lam, gama, mmu);
    k_transpose_c<<<tg, tb>>>((float2*)pCB, (float2*)pCA);
    k_fft4<1><<<FFTG, 256>>>(pCA, pMURF, 0, 0, 1.f/FN, prelu, 0, lam, gama, mmu);

    // ----- iterations -----
    for (int it = 0; it < 2; ++it) {
        k_sfb_h<<<eb(NB*FN*WD), 256>>>((float*)pWL, (float*)pBWL,
                                       (float*)pWH, (float*)pBWH, (float*)pLOS);
        k_sfb_h<<<eb(NB*FN*WD), 256>>>((float*)pWH + (size_t)SLL,
                                       (float*)pBWH + (size_t)SLL,
                                       (float*)pWH + (size_t)2*SLL,
                                       (float*)pBWH + (size_t)2*SLL, (float*)pHIS);
        k_sfb_w<<<eb(TOT), 256>>>((float*)pLOS, (float*)pHIS, (float*)pIDWT);

        k_fft4<0><<<FFTG, 256>>>(pCA, pCB, 0, 0, 1.f, prelu, 4, lam, gama, mmu);
        k_transpose_c<<<tg, tb>>>((float2*)pCB, (float2*)pCA);        // [p][y]
        k_fftpair<1><<<FFTG, 256>>>((float2*)pCA, (float2*)pCB, 1.f/FN);
        k_transpose_c<<<tg, tb>>>((float2*)pCB, (float2*)pCA);        // [y][p]
        void* udst = (it == 0) ? pU : (void*)out;
        k_fft4<1><<<FFTG, 256>>>(pCA, udst, 0, 1, 1.f/FN, prelu, 0, lam, gama, mmu);

        if (it == 0) {
            k_shrinkbxy<<<eb(TOT), 256>>>(lam, prelu);
            k_afb_w<<<eb(NB*FN*WD), 256>>>((float*)pU, (float*)pLOT, (float*)pHIT);
            k_afb_h<<<eb(SLL), 256>>>((float*)pLOT, (float*)pUL, (float*)pUH);
            k_afb_h<<<eb(SLL), 256>>>((float*)pHIT, (float*)pUH + (size_t)SLL,
                                      (float*)pUH + (size_t)2*SLL);
            k_wupd<<<eb(SLL), 256>>>((float*)pUL, (float*)pBWL, (float*)pWL,
                                     SLL, gama, prelu);
            k_wupd<<<eb(3*SLL), 256>>>((float*)pUH, (float*)pBWH, (float*)pWH,
                                       3*SLL, gama, prelu);
            k_fft4<0><<<FFTG, 256>>>(pU, pCA, 1, 0, 1.f, prelu, 0, lam, gama, mmu);
            k_transpose_c<<<tg, tb>>>((float2*)pCA, (float2*)pCB);
            k_fftpair<2><<<FFTG, 256>>>((float2*)pCB, (float2*)pCA, 1.f/FN);
            k_transpose_c<<<tg, tb>>>((float2*)pCA, (float2*)pCB);
            k_fft4<1><<<FFTG, 256>>>(pCB, pMURF, 0, 0, 1.f/FN, prelu, 0,
                                     lam, gama, mmu);
        }
    }
    (void)in_sizes; (void)n_in; (void)out_size;
}

// round 10
// speedup vs baseline: 2.0762x; 1.2050x over previous
#include <cuda_runtime.h>
#include <math.h>

#define FN   1024
#define NB   4
#define FNN  (FN*FN)
#define TOT  (NB*FNN)
#define WD   518
#define SLL  (NB*WD*WD)
#define SLW  (NB*FN*WD)
#define PIF  3.14159265358979323846f

#define DP(i) ((i) + ((i)>>2))
#define TP(i) ((i) + ((i)>>4))

// ---------------- static device scratch ----------------
__device__ float2 g_CA[TOT];
__device__ float2 g_CB[TOT];
__device__ float2 g_UKER[TOT];   // [p][q]
__device__ float2 g_F0T[TOT];    // [p][q]
__device__ float2 g_G[TOT];      // maskT * f  (spectral, [p][q])
__device__ float2 g_TW[FN];
__device__ float4 g_TRIG[FN];    // cos th, sin th, cos 2th, sin 2th

__device__ float g_U[TOT];
__device__ float g_DX[TOT];
__device__ float g_DY[TOT];
__device__ float g_BX[TOT];
__device__ float g_BY[TOT];
__device__ float g_MASKT[TOT];
__device__ float g_IDWT[TOT];

__device__ float g_WL[SLL];
__device__ float g_BWL[SLL];
__device__ float g_WH[3*SLL];
__device__ float g_BWH[3*SLL];
__device__ float g_LOT[SLW];
__device__ float g_HIT[SLW];
__device__ float g_LOS[SLW];
__device__ float g_HIS[SLW];

// ---------------- wavelet filters (db7, L=14) ----------------
__constant__ float cH0A[14] = {
    0.010268176708511255f, 0.004010244871533663f, -0.10780823770381774f,
   -0.14004724044296152f, 0.2886296317515146f, 0.767764317003164f,
    0.5361019170917628f, 0.017441255086855827f, -0.049552834937127255f,
    0.0678926935013727f, 0.03051551316596357f, -0.01263630340325193f,
   -0.0010473848886829163f, 0.002681814568257878f };
__constant__ float cH1A[14] = {
    0.002681814568257878f, 0.0010473848886829163f, -0.01263630340325193f,
   -0.03051551316596357f, 0.0678926935013727f, 0.049552834937127255f,
    0.017441255086855827f, -0.5361019170917628f, 0.767764317003164f,
   -0.2886296317515146f, -0.14004724044296152f, 0.10780823770381774f,
    0.004010244871533663f, -0.010268176708511255f };
__constant__ float cG0[14] = {
    0.002681814568257878f, -0.0010473848886829163f, -0.01263630340325193f,
    0.03051551316596357f, 0.0678926935013727f, -0.049552834937127255f,
    0.017441255086855827f, 0.5361019170917628f, 0.767764317003164f,
    0.2886296317515146f, -0.14004724044296152f, -0.10780823770381774f,
    0.004010244871533663f, 0.010268176708511255f };
__constant__ float cG1[14] = {
   -0.010268176708511255f, 0.004010244871533663f, 0.10780823770381774f,
   -0.14004724044296152f, -0.2886296317515146f, 0.767764317003164f,
   -0.5361019170917628f, 0.017441255086855827f, 0.049552834937127255f,
    0.0678926935013727f, -0.03051551316596357f, -0.01263630340325193f,
    0.0010473848886829163f, 0.002681814568257878f };

__device__ __forceinline__ float2 cmulf(float2 a, float2 b) {
    return make_float2(a.x*b.x - a.y*b.y, a.x*b.y + a.y*b.x);
}

__global__ void k_twinit()
{
    int j = blockIdx.x*blockDim.x + threadIdx.x;
    if (j >= FN) return;
    float th = 2.f*PIF*(float)j/(float)FN;
    float sv, cv; sincosf(-th, &sv, &cv);
    g_TW[j] = make_float2(cv, sv);
    float s1, c1, s2, c2;
    sincosf(th, &s1, &c1);
    sincosf(2.f*th, &s2, &c2);
    g_TRIG[j] = make_float4(c1, s1, c2, s2);
}

template<int INV>
__device__ __forceinline__ void r4stage(const float2* __restrict__ X,
                                        float2* __restrict__ Y,
                                        const float2* __restrict__ tw,
                                        int t, int s)
{
    int ns = 1 << (2*s);
    int k  = t & (ns - 1);
    int j  = ((t - k) << 2) + k;
    int sh = 8 - 2*s;
    float2 c0 = X[DP(t)], c1 = X[DP(t+256)], c2 = X[DP(t+512)], c3 = X[DP(t+768)];
    float2 w1 = tw[TP(k << sh)];
    float2 w2 = tw[TP((2*k) << sh)];
    float2 w3 = tw[TP((3*k) << sh)];
    if (INV) { w1.y = -w1.y; w2.y = -w2.y; w3.y = -w3.y; }
    c1 = cmulf(c1, w1); c2 = cmulf(c2, w2); c3 = cmulf(c3, w3);
    float2 t0 = make_float2(c0.x+c2.x, c0.y+c2.y);
    float2 t1 = make_float2(c0.x-c2.x, c0.y-c2.y);
    float2 t2 = make_float2(c1.x+c3.x, c1.y+c3.y);
    float2 dd = make_float2(c1.x-c3.x, c1.y-c3.y);
    float2 t3 = INV ? make_float2(-dd.y, dd.x) : make_float2(dd.y, -dd.x);
    Y[DP(j)]      = make_float2(t0.x+t2.x, t0.y+t2.y);
    Y[DP(j+ns)]   = make_float2(t1.x+t3.x, t1.y+t3.y);
    Y[DP(j+2*ns)] = make_float2(t0.x-t2.x, t0.y-t2.y);
    Y[DP(j+3*ns)] = make_float2(t1.x-t3.x, t1.y-t3.y);
}

// preOp: 0 none; 4 load = spatial rhs part (no murf; src ignored)
// postOp: 0 none; 2 store G' = m*(2*f0T - m*v)   (complex out only)
template<int INV>
__global__ __launch_bounds__(256) void k_fft4(const void* __restrict__ srcv,
                                              void* __restrict__ dstv,
                                              int inReal, int outReal,
                                              float scale,
                                              const float* __restrict__ prelu,
                                              int preOp, int postOp,
                                              const float* __restrict__ lam,
                                              const float* __restrict__ gama)
{
    __shared__ float2 sA[1280];
    __shared__ float2 sB[1280];
    __shared__ float2 tw[1088];
    int t = threadIdx.x;
    size_t base = (size_t)blockIdx.x*FN;
    for (int j = t; j < FN; j += 256) tw[TP(j)] = g_TW[j];
    if (inReal) {
        const float* s = (const float*)srcv + base;
#pragma unroll
        for (int m = 0; m < 4; ++m) sA[DP(t+256*m)] = make_float2(s[t+256*m], 0.f);
    } else if (preOp == 4) {
        int y = blockIdx.x & (FN-1);
        float lv = lam[0], gv = gama[0];
#pragma unroll
        for (int m = 0; m < 4; ++m) {
            int x = t + 256*m;
            size_t i = base + x;
            float dxt = 0.f;
            if (x >= 1) {
                int xn = (x == FN-1) ? 1 : x+1;
                dxt = (g_DX[i] - g_BX[i]) - (g_DX[base+xn] - g_BX[base+xn]);
            }
            float dyt = 0.f;
            if (y >= 1) {
                int yn = (y == FN-1) ? 1 : y+1;
                size_t jj = i + (size_t)(yn - y)*FN;
                dyt = (g_DY[i] - g_BY[i]) - (g_DY[jj] - g_BY[jj]);
            }
            sA[DP(x)] = make_float2(lv*(dxt + dyt) + gv*g_IDWT[i], 0.f);
        }
    } else {
        const float2* s = (const float2*)srcv + base;
#pragma unroll
        for (int m = 0; m < 4; ++m) sA[DP(t+256*m)] = s[t+256*m];
    }
    __syncthreads();
    float2* X = sA; float2* Y = sB;
#pragma unroll
    for (int s = 0; s < 5; ++s) {
        r4stage<INV>(X, Y, tw, t, s);
        __syncthreads();
        float2* tmp = X; X = Y; Y = tmp;
    }
    if (!outReal) {
        float2* d = (float2*)dstv + base;
#pragma unroll
        for (int m = 0; m < 4; ++m) {
            int idx = t + 256*m;
            float2 v = X[DP(idx)];
            v.x *= scale; v.y *= scale;
            if (postOp == 2) {
                float mk = g_MASKT[base + idx];
                float2 f0 = g_F0T[base + idx];
                v = make_float2(mk*(2.f*f0.x - mk*v.x), mk*(2.f*f0.y - mk*v.y));
            }
            d[idx] = v;
        }
    } else {
        float a = prelu[0];
        float* d = (float*)dstv + base;
#pragma unroll
        for (int m = 0; m < 4; ++m) {
            float v = X[DP(t+256*m)].x * scale;
            d[t+256*m] = (v >= 0.f) ? v : a*v;
        }
    }
}

// fused fwd FFT -> (v = mmu*G + v ; v /= UKER) -> inv FFT, row in smem
__global__ __launch_bounds__(256) void k_fftsolve(const float2* __restrict__ src,
                                                  float2* __restrict__ dst,
                                                  float scale,
                                                  const float* __restrict__ mmu)
{
    __shared__ float2 sA[1280];
    __shared__ float2 sB[1280];
    __shared__ float2 tw[1088];
    int t = threadIdx.x;
    size_t base = (size_t)blockIdx.x*FN;
    for (int j = t; j < FN; j += 256) tw[TP(j)] = g_TW[j];
    const float2* s = src + base;
#pragma unroll
    for (int m = 0; m < 4; ++m) sA[DP(t+256*m)] = s[t+256*m];
    __syncthreads();
    float2* X = sA; float2* Y = sB;
#pragma unroll
    for (int st = 0; st < 5; ++st) {
        r4stage<0>(X, Y, tw, t, st);
        __syncthreads();
        float2* tmp = X; X = Y; Y = tmp;
    }
    float mv = mmu[0];
#pragma unroll
    for (int m = 0; m < 4; ++m) {
        int idx = t + 256*m;
        float2 v = X[DP(idx)];
        float2 g = g_G[base + idx];
        v.x += mv*g.x;  v.y += mv*g.y;
        float2 w = g_UKER[base + idx];
        float d = 1.f/(w.x*w.x + w.y*w.y);
        X[DP(idx)] = make_float2((v.x*w.x + v.y*w.y)*d, (v.y*w.x - v.x*w.y)*d);
    }
    __syncthreads();
#pragma unroll
    for (int st = 0; st < 5; ++st) {
        r4stage<1>(X, Y, tw, t, st);
        __syncthreads();
        float2* tmp = X; X = Y; Y = tmp;
    }
    float2* d = dst + base;
#pragma unroll
    for (int m = 0; m < 4; ++m) {
        float2 v = X[DP(t+256*m)];
        d[t+256*m] = make_float2(v.x*scale, v.y*scale);
    }
}

// ---------------- transposes ----------------
__global__ void k_transpose_c(const float2* __restrict__ src, float2* __restrict__ dst)
{
    __shared__ float2 tile[32][33];
    int b = blockIdx.z;
    const float2* s = src + (size_t)b*FNN;
    float2* d = dst + (size_t)b*FNN;
    int x  = blockIdx.x*32 + threadIdx.x;
    int y0 = blockIdx.y*32 + threadIdx.y;
#pragma unroll
    for (int i = 0; i < 32; i += 8)
        tile[threadIdx.y+i][threadIdx.x] = s[(size_t)(y0+i)*FN + x];
    __syncthreads();
    int x2 = blockIdx.y*32 + threadIdx.x;
    int y2 = blockIdx.x*32 + threadIdx.y;
#pragma unroll
    for (int i = 0; i < 32; i += 8)
        d[(size_t)(y2+i)*FN + x2] = tile[threadIdx.x][threadIdx.y+i];
}

__global__ void k_transpose_r(const float* __restrict__ src, float* __restrict__ dst)
{
    __shared__ float tile[32][33];
    int b = blockIdx.z;
    const float* s = src + (size_t)b*FNN;
    float* d = dst + (size_t)b*FNN;
    int x  = blockIdx.x*32 + threadIdx.x;
    int y0 = blockIdx.y*32 + threadIdx.y;
#pragma unroll
    for (int i = 0; i < 32; i += 8)
        tile[threadIdx.y+i][threadIdx.x] = s[(size_t)(y0+i)*FN + x];
    __syncthreads();
    int x2 = blockIdx.y*32 + threadIdx.x;
    int y2 = blockIdx.x*32 + threadIdx.y;
#pragma unroll
    for (int i = 0; i < 32; i += 8)
        d[(size_t)(y2+i)*FN + x2] = tile[threadIdx.x][threadIdx.y+i];
}

__global__ void k_make_f0T(const float* __restrict__ fr, const float* __restrict__ fi,
                           float2* __restrict__ dst)
{
    __shared__ float tr[32][33];
    __shared__ float ti[32][33];
    int b = blockIdx.z;
    const float* sr = fr + (size_t)b*FNN;
    const float* si = fi + (size_t)b*FNN;
    float2* d = dst + (size_t)b*FNN;
    int x  = blockIdx.x*32 + threadIdx.x;
    int y0 = blockIdx.y*32 + threadIdx.y;
#pragma unroll
    for (int i = 0; i < 32; i += 8) {
        tr[threadIdx.y+i][threadIdx.x] = sr[(size_t)(y0+i)*FN + x];
        ti[threadIdx.y+i][threadIdx.x] = si[(size_t)(y0+i)*FN + x];
    }
    __syncthreads();
    int x2 = blockIdx.y*32 + threadIdx.x;
    int y2 = blockIdx.x*32 + threadIdx.y;
#pragma unroll
    for (int i = 0; i < 32; i += 8)
        d[(size_t)(y2+i)*FN + x2] =
            make_float2(tr[threadIdx.x][threadIdx.y+i], ti[threadIdx.x][threadIdx.y+i]);
}

// ---------------- analytic UKER (table-driven) + G0 = maskT*f0T ----------------
__global__ void k_ukerA(const float* __restrict__ lam, const float* __restrict__ gama,
                        const float* __restrict__ mmu)
{
    int i = blockIdx.x*blockDim.x + threadIdx.x;
    if (i >= TOT) return;
    int q = i & (FN-1);
    int p = (i >> 10) & (FN-1);
    float4 tp = g_TRIG[p];
    float4 tq = g_TRIG[q];
    float Br = 4.f - tp.x - tq.x - tp.z - tq.z;
    float Bi = tp.y + tq.y - tp.w - tq.w;
    float cf = tp.x*tq.x - tp.y*tq.y;
    float sf = tp.y*tq.x + tp.x*tq.y;
    float Fr = Br*cf + Bi*sf;
    float Fi = Bi*cf - Br*sf;
    float m = g_MASKT[i];
    float lv = lam[0];
    g_UKER[i] = make_float2(mmu[0]*m*m + gama[0] + lv*Fr, lv*Fi);
    float2 f0 = g_F0T[i];
    g_G[i] = make_float2(m*f0.x, m*f0.y);
}

// ---------------- fused shrink + b-update ----------------
__global__ void k_shrinkbxy(const float* __restrict__ lam,
                            const float* __restrict__ prelu)
{
    int i = blockIdx.x*blockDim.x + threadIdx.x;
    if (i >= TOT) return;
    float a  = prelu[0];
    float il = 1.f/lam[0];
    float dx = g_DX[i], dy = g_DY[i], bx = g_BX[i], by = g_BY[i];
    float vx = dx + bx;
    float vy = dy + by;
    float s = sqrtf(vx*vx + vy*vy);
    float nx = vx - s*il;
    float ny = vy - s*il;
    nx = (nx >= 0.f) ? nx : a*nx;
    ny = (ny >= 0.f) ? ny : a*ny;
    int x = i & (FN-1);
    int y = (i >> 10) & (FN-1);
    int rowb = i - x;
    float dxu = 0.f;
    if (x >= 1) {
        int xm = (x == 1) ? FN-1 : x-1;
        dxu = g_U[i] - g_U[rowb + xm];
    }
    float dyu = 0.f;
    if (y >= 1) {
        int ym = (y == 1) ? FN-1 : y-1;
        dyu = g_U[i] - g_U[i + (ym - y)*FN];
    }
    g_DX[i] = nx;  g_DY[i] = ny;
    g_BX[i] = bx + dxu - nx;
    g_BY[i] = by + dyu - ny;
}

// ---------------- DWT analysis ----------------
__global__ void k_afb_w(const float* __restrict__ src, float* __restrict__ lo,
                        float* __restrict__ hi)
{
    int i = blockIdx.x*blockDim.x + threadIdx.x;
    if (i >= NB*FN*WD) return;
    int o = i % WD;
    int r = i / WD;
    const float* row = src + (size_t)r*FN;
    float l = 0.f, h = 0.f;
#pragma unroll
    for (int k = 0; k < 14; ++k) {
        int j = 2*o + k - 12;
        j = (j < 0) ? -j : ((j >= FN) ? (2*FN - 2 - j) : j);
        float v = row[j];
        l += v * cH0A[k];
        h += v * cH1A[k];
    }
    lo[i] = l;
    hi[i] = h;
}

__global__ void k_afb_h(const float* __restrict__ src, float* __restrict__ lo,
                        float* __restrict__ hi)
{
    int i = blockIdx.x*blockDim.x + threadIdx.x;
    if (i >= SLL) return;
    int w = i % WD;
    int o = (i / WD) % WD;
    int b = i / (WD*WD);
    const float* base = src + (size_t)b*FN*WD;
    float l = 0.f, h = 0.f;
#pragma unroll
    for (int k = 0; k < 14; ++k) {
        int j = 2*o + k - 12;
        j = (j < 0) ? -j : ((j >= FN) ? (2*FN - 2 - j) : j);
        float v = base[(size_t)j*WD + w];
        l += v * cH0A[k];
        h += v * cH1A[k];
    }
    lo[i] = l;
    hi[i] = h;
}

// column DWT fused with w/b update: w = srelu(c + bw - 1/g); bw += c - w
__global__ void k_afb_h_w(const float* __restrict__ src,
                          float* __restrict__ bwLo, float* __restrict__ wLo,
                          float* __restrict__ bwHi, float* __restrict__ wHi,
                          const float* __restrict__ gama,
                          const float* __restrict__ prelu)
{
    int i = blockIdx.x*blockDim.x + threadIdx.x;
    if (i >= SLL) return;
    int w = i % WD;
    int o = (i / WD) % WD;
    int b = i / (WD*WD);
    const float* base = src + (size_t)b*FN*WD;
    float l = 0.f, h = 0.f;
#pragma unroll
    for (int k = 0; k < 14; ++k) {
        int j = 2*o + k - 12;
        j = (j < 0) ? -j : ((j >= FN) ? (2*FN - 2 - j) : j);
        float v = base[(size_t)j*WD + w];
        l += v * cH0A[k];
        h += v * cH1A[k];
    }
    float a  = prelu[0];
    float ig = 1.f/gama[0];
    float bv = bwLo[i];
    float t  = l + bv - ig;
    float wv = (t >= 0.f) ? t : a*t;
    wLo[i]  = wv;
    bwLo[i] = bv + l - wv;
    bv = bwHi[i];
    t  = h + bv - ig;
    wv = (t >= 0.f) ? t : a*t;
    wHi[i]  = wv;
    bwHi[i] = bv + h - wv;
}

// ---------------- IDWT synthesis ----------------
__global__ void k_sfb_h(const float* __restrict__ loA, const float* __restrict__ loB,
                        const float* __restrict__ hiA, const float* __restrict__ hiB,
                        float* __restrict__ out)
{
    int i = blockIdx.x*blockDim.x + threadIdx.x;
    if (i >= NB*FN*WD) return;
    int w = i % WD;
    int o = (i / WD) % FN;
    int b = i / (FN*WD);
    size_t bb = (size_t)b*WD*WD;
    float acc = 0.f;
    int k0 = (o + 1) & 1;
#pragma unroll
    for (int kk = 0; kk < 7; ++kk) {
        int k = k0 + 2*kk;
        int m = (o + k - 1) >> 1;
        size_t idx = bb + (size_t)m*WD + w;
        float lo = loA[idx] - loB[idx];
        float hi = hiA[idx] - hiB[idx];
        acc += lo * cG0[k] + hi * cG1[k];
    }
    out[i] = acc;
}

__global__ void k_sfb_w(const float* __restrict__ lo, const float* __restrict__ hi,
                        float* __restrict__ out)
{
    int i = blockIdx.x*blockDim.x + threadIdx.x;
    if (i >= TOT) return;
    int x = i & (FN-1);
    int r = i >> 10;
    const float* lrow = lo + (size_t)r*WD;
    const float* hrow = hi + (size_t)r*WD;
    float acc = 0.f;
    int k0 = (x + 1) & 1;
#pragma unroll
    for (int kk = 0; kk < 7; ++kk) {
        int k = k0 + 2*kk;
        int m = (x + k - 1) >> 1;
        acc += lrow[m] * cG0[k] + hrow[m] * cG1[k];
    }
    out[i] = acc;
}

// ---------------- host orchestration ----------------
static inline int eb(int n) { return (n + 255) / 256; }

extern "C" void kernel_launch(void* const* d_in, const int* in_sizes, int n_in,
                              void* d_out, int out_size)
{
    const float* u_in   = (const float*)d_in[0];
    const float* uvMask = (const float*)d_in[1];
    const float* f_real = (const float*)d_in[3];
    const float* f_imag = (const float*)d_in[4];
    const float* lam    = (const float*)d_in[5];
    const float* gama   = (const float*)d_in[6];
    const float* mmu    = (const float*)d_in[7];
    const float* prelu  = (const float*)d_in[8];
    float* out = (float*)d_out;

    void *pCA, *pCB, *pU, *pIDWT, *pMASKT, *pF0T, *pG;
    void *pDX, *pDY, *pBX, *pBY;
    void *pWL, *pBWL, *pWH, *pBWH;
    void *pLOT, *pHIT, *pLOS, *pHIS;
    cudaGetSymbolAddress(&pCA, g_CA);       cudaGetSymbolAddress(&pCB, g_CB);
    cudaGetSymbolAddress(&pU, g_U);         cudaGetSymbolAddress(&pG, g_G);
    cudaGetSymbolAddress(&pIDWT, g_IDWT);   cudaGetSymbolAddress(&pMASKT, g_MASKT);
    cudaGetSymbolAddress(&pF0T, g_F0T);
    cudaGetSymbolAddress(&pDX, g_DX);       cudaGetSymbolAddress(&pDY, g_DY);
    cudaGetSymbolAddress(&pBX, g_BX);       cudaGetSymbolAddress(&pBY, g_BY);
    cudaGetSymbolAddress(&pWL, g_WL);       cudaGetSymbolAddress(&pBWL, g_BWL);
    cudaGetSymbolAddress(&pWH, g_WH);       cudaGetSymbolAddress(&pBWH, g_BWH);
    cudaGetSymbolAddress(&pLOT, g_LOT);     cudaGetSymbolAddress(&pHIT, g_HIT);
    cudaGetSymbolAddress(&pLOS, g_LOS);     cudaGetSymbolAddress(&pHIS, g_HIS);

    dim3 tb(32, 8), tg(32, 32, NB);
    const int FFTG = NB*FN;

    // ----- init -----
    k_twinit<<<4, 256>>>();
    k_transpose_r<<<tg, tb>>>(uvMask, (float*)pMASKT);
    k_make_f0T<<<tg, tb>>>(f_real, f_imag, (float2*)pF0T);
    cudaMemsetAsync(pDX, 0, (size_t)TOT*4, 0);
    cudaMemsetAsync(pDY, 0, (size_t)TOT*4, 0);
    cudaMemsetAsync(pBX, 0, (size_t)TOT*4, 0);
    cudaMemsetAsync(pBY, 0, (size_t)TOT*4, 0);
    cudaMemsetAsync(pBWL, 0, (size_t)SLL*4, 0);
    cudaMemsetAsync(pBWH, 0, (size_t)(3*SLL)*4, 0);

    // uker + G0 (needs MASKT, F0T)
    k_ukerA<<<eb(TOT), 256>>>(lam, gama, mmu);

    // dwt2(u_in) -> WL, WH
    k_afb_w<<<eb(NB*FN*WD), 256>>>(u_in, (float*)pLOT, (float*)pHIT);
    k_afb_h<<<eb(SLL), 256>>>((float*)pLOT, (float*)pWL, (float*)pWH);
    k_afb_h<<<eb(SLL), 256>>>((float*)pHIT, (float*)pWH + (size_t)SLL,
                              (float*)pWH + (size_t)2*SLL);

    // ----- iterations (murf fully spectral via g_G) -----
    for (int it = 0; it < 2; ++it) {
        k_sfb_h<<<eb(NB*FN*WD), 256>>>((float*)pWL, (float*)pBWL,
                                       (float*)pWH, (float*)pBWH, (float*)pLOS);
        k_sfb_h<<<eb(NB*FN*WD), 256>>>((float*)pWH + (size_t)SLL,
                                       (float*)pBWH + (size_t)SLL,
                                       (float*)pWH + (size_t)2*SLL,
                                       (float*)pBWH + (size_t)2*SLL, (float*)pHIS);
        k_sfb_w<<<eb(TOT), 256>>>((float*)pLOS, (float*)pHIS, (float*)pIDWT);

        // spatial rhs part (no murf) -> fwd rows
        k_fft4<0><<<FFTG, 256>>>(pCA, pCB, 0, 0, 1.f, prelu, 4, 0, lam, gama);
        k_transpose_c<<<tg, tb>>>((float2*)pCB, (float2*)pCA);          // [p][y]
        k_fftsolve<<<FFTG, 256>>>((float2*)pCA, (float2*)pCB, 1.f/FN, mmu);
        k_transpose_c<<<tg, tb>>>((float2*)pCB, (float2*)pCA);          // [y][p]
        void* udst = (it == 0) ? pU : (void*)out;
        k_fft4<1><<<FFTG, 256>>>(pCA, udst, 0, 1, 1.f/FN, prelu, 0, 0, lam, gama);

        if (it == 0) {
            k_shrinkbxy<<<eb(TOT), 256>>>(lam, prelu);
            k_afb_w<<<eb(NB*FN*WD), 256>>>((float*)pU, (float*)pLOT, (float*)pHIT);
            k_afb_h_w<<<eb(SLL), 256>>>((float*)pLOT,
                                        (float*)pBWL, (float*)pWL,
                                        (float*)pBWH, (float*)pWH, gama, prelu);
            k_afb_h_w<<<eb(SLL), 256>>>((float*)pHIT,
                                        (float*)pBWH + (size_t)SLL,
                                        (float*)pWH + (size_t)SLL,
                                        (float*)pBWH + (size_t)2*SLL,
                                        (float*)pWH + (size_t)2*SLL, gama, prelu);
            // G' = maskT*(2*F0T - maskT*FU): fft2(u) with G' store epilogue
            k_fft4<0><<<FFTG, 256>>>(pU, pCA, 1, 0, 1.f, prelu, 0, 0, lam, gama);
            k_transpose_c<<<tg, tb>>>((float2*)pCA, (float2*)pCB);      // [p][y]
            k_fft4<0><<<FFTG, 256>>>(pCB, pG, 0, 0, 1.f, prelu, 0, 2, lam, gama);
        }
    }
    (void)in_sizes; (void)n_in; (void)out_size;
}

// round 11
// speedup vs baseline: 2.3233x; 1.1190x over previous
#include <cuda_runtime.h>
#include <math.h>

#define FN   1024
#define NB   4
#define FNN  (FN*FN)
#define TOT  (NB*FNN)
#define WD   518
#define SLL  (NB*WD*WD)
#define SLW  (NB*FN*WD)
#define PIF  3.14159265358979323846f

#define DP(i) ((i) + ((i)>>2))
#define TP(i) ((i) + ((i)>>4))

// ---------------- static device scratch ----------------
__device__ float2 g_CA[TOT];
__device__ float2 g_CB[TOT];
__device__ float2 g_F0T[TOT];    // [p][q]
__device__ float2 g_G[TOT];      // spectral mask*f, [p][q] (written by postOp2)
__device__ float2 g_TW[FN];
__device__ float4 g_TRIG[FN];    // cos th, sin th, cos 2th, sin 2th

__device__ float g_U[TOT];
__device__ float g_DX[TOT];
__device__ float g_DY[TOT];
__device__ float g_BX[TOT];
__device__ float g_BY[TOT];
__device__ float g_MASKT[TOT];

__device__ float g_WL[SLL];
__device__ float g_BWL[SLL];
__device__ float g_WH[3*SLL];
__device__ float g_BWH[3*SLL];
__device__ float g_LOT[SLW];
__device__ float g_HIT[SLW];
__device__ float g_LOS[SLW];
__device__ float g_HIS[SLW];

// ---------------- wavelet filters (db7, L=14) ----------------
__constant__ float cH0A[14] = {
    0.010268176708511255f, 0.004010244871533663f, -0.10780823770381774f,
   -0.14004724044296152f, 0.2886296317515146f, 0.767764317003164f,
    0.5361019170917628f, 0.017441255086855827f, -0.049552834937127255f,
    0.0678926935013727f, 0.03051551316596357f, -0.01263630340325193f,
   -0.0010473848886829163f, 0.002681814568257878f };
__constant__ float cH1A[14] = {
    0.002681814568257878f, 0.0010473848886829163f, -0.01263630340325193f,
   -0.03051551316596357f, 0.0678926935013727f, 0.049552834937127255f,
    0.017441255086855827f, -0.5361019170917628f, 0.767764317003164f,
   -0.2886296317515146f, -0.14004724044296152f, 0.10780823770381774f,
    0.004010244871533663f, -0.010268176708511255f };
__constant__ float cG0[14] = {
    0.002681814568257878f, -0.0010473848886829163f, -0.01263630340325193f,
    0.03051551316596357f, 0.0678926935013727f, -0.049552834937127255f,
    0.017441255086855827f, 0.5361019170917628f, 0.767764317003164f,
    0.2886296317515146f, -0.14004724044296152f, -0.10780823770381774f,
    0.004010244871533663f, 0.010268176708511255f };
__constant__ float cG1[14] = {
   -0.010268176708511255f, 0.004010244871533663f, 0.10780823770381774f,
   -0.14004724044296152f, -0.2886296317515146f, 0.767764317003164f,
   -0.5361019170917628f, 0.017441255086855827f, 0.049552834937127255f,
    0.0678926935013727f, -0.03051551316596357f, -0.01263630340325193f,
    0.0010473848886829163f, 0.002681814568257878f };

__device__ __forceinline__ float2 cmulf(float2 a, float2 b) {
    return make_float2(a.x*b.x - a.y*b.y, a.x*b.y + a.y*b.x);
}

__global__ void k_twinit()
{
    int j = blockIdx.x*blockDim.x + threadIdx.x;
    if (j >= FN) return;
    float th = 2.f*PIF*(float)j/(float)FN;
    float sv, cv; sincosf(-th, &sv, &cv);
    g_TW[j] = make_float2(cv, sv);
    float s1, c1, s2, c2;
    sincosf(th, &s1, &c1);
    sincosf(2.f*th, &s2, &c2);
    g_TRIG[j] = make_float4(c1, s1, c2, s2);
}

template<int INV>
__device__ __forceinline__ void r4stage(const float2* __restrict__ X,
                                        float2* __restrict__ Y,
                                        const float2* __restrict__ tw,
                                        int t, int s)
{
    int ns = 1 << (2*s);
    int k  = t & (ns - 1);
    int j  = ((t - k) << 2) + k;
    int sh = 8 - 2*s;
    float2 c0 = X[DP(t)], c1 = X[DP(t+256)], c2 = X[DP(t+512)], c3 = X[DP(t+768)];
    float2 w1 = tw[TP(k << sh)];
    float2 w2 = tw[TP((2*k) << sh)];
    float2 w3 = tw[TP((3*k) << sh)];
    if (INV) { w1.y = -w1.y; w2.y = -w2.y; w3.y = -w3.y; }
    c1 = cmulf(c1, w1); c2 = cmulf(c2, w2); c3 = cmulf(c3, w3);
    float2 t0 = make_float2(c0.x+c2.x, c0.y+c2.y);
    float2 t1 = make_float2(c0.x-c2.x, c0.y-c2.y);
    float2 t2 = make_float2(c1.x+c3.x, c1.y+c3.y);
    float2 dd = make_float2(c1.x-c3.x, c1.y-c3.y);
    float2 t3 = INV ? make_float2(-dd.y, dd.x) : make_float2(dd.y, -dd.x);
    Y[DP(j)]      = make_float2(t0.x+t2.x, t0.y+t2.y);
    Y[DP(j+ns)]   = make_float2(t1.x+t3.x, t1.y+t3.y);
    Y[DP(j+2*ns)] = make_float2(t0.x-t2.x, t0.y-t2.y);
    Y[DP(j+3*ns)] = make_float2(t1.x-t3.x, t1.y-t3.y);
}

// preOp: 0 none; 4 load = rhs spatial part with INLINE row-IDWT (src ignored)
// postOp: 0 none; 2 store G' = m*(2*f0T - m*v)   (complex out only)
template<int INV>
__global__ __launch_bounds__(256) void k_fft4(const void* __restrict__ srcv,
                                              void* __restrict__ dstv,
                                              int inReal, int outReal,
                                              float scale,
                                              const float* __restrict__ prelu,
                                              int preOp, int postOp,
                                              const float* __restrict__ lam,
                                              const float* __restrict__ gama)
{
    __shared__ float2 sA[1280];
    __shared__ float2 sB[1280];
    __shared__ float2 tw[1088];
    int t = threadIdx.x;
    size_t base = (size_t)blockIdx.x*FN;
    for (int j = t; j < FN; j += 256) tw[TP(j)] = g_TW[j];
    if (inReal) {
        const float* s = (const float*)srcv + base;
#pragma unroll
        for (int m = 0; m < 4; ++m) sA[DP(t+256*m)] = make_float2(s[t+256*m], 0.f);
    } else if (preOp == 4) {
        int y = blockIdx.x & (FN-1);
        float lv = lam[0], gv = gama[0];
        const float* lrow = g_LOS + (size_t)blockIdx.x*WD;
        const float* hrow = g_HIS + (size_t)blockIdx.x*WD;
#pragma unroll
        for (int m = 0; m < 4; ++m) {
            int x = t + 256*m;
            size_t i = base + x;
            float dxt = 0.f;
            if (x >= 1) {
                int xn = (x == FN-1) ? 1 : x+1;
                dxt = (g_DX[i] - g_BX[i]) - (g_DX[base+xn] - g_BX[base+xn]);
            }
            float dyt = 0.f;
            if (y >= 1) {
                int yn = (y == FN-1) ? 1 : y+1;
                size_t jj = i + (size_t)(yn - y)*FN;
                dyt = (g_DY[i] - g_BY[i]) - (g_DY[jj] - g_BY[jj]);
            }
            // inline row IDWT (sfb_w)
            float idwt = 0.f;
            int k0 = (x + 1) & 1;
#pragma unroll
            for (int kk = 0; kk < 7; ++kk) {
                int k = k0 + 2*kk;
                int mm = (x + k - 1) >> 1;
                idwt += lrow[mm] * cG0[k] + hrow[mm] * cG1[k];
            }
            sA[DP(x)] = make_float2(lv*(dxt + dyt) + gv*idwt, 0.f);
        }
    } else {
        const float2* s = (const float2*)srcv + base;
#pragma unroll
        for (int m = 0; m < 4; ++m) sA[DP(t+256*m)] = s[t+256*m];
    }
    __syncthreads();
    float2* X = sA; float2* Y = sB;
#pragma unroll
    for (int s = 0; s < 5; ++s) {
        r4stage<INV>(X, Y, tw, t, s);
        __syncthreads();
        float2* tmp = X; X = Y; Y = tmp;
    }
    if (!outReal) {
        float2* d = (float2*)dstv + base;
#pragma unroll
        for (int m = 0; m < 4; ++m) {
            int idx = t + 256*m;
            float2 v = X[DP(idx)];
            v.x *= scale; v.y *= scale;
            if (postOp == 2) {
                float mk = g_MASKT[base + idx];
                float2 f0 = g_F0T[base + idx];
                v = make_float2(mk*(2.f*f0.x - mk*v.x), mk*(2.f*f0.y - mk*v.y));
            }
            d[idx] = v;
        }
    } else {
        float a = prelu[0];
        float* d = (float*)dstv + base;
#pragma unroll
        for (int m = 0; m < 4; ++m) {
            float v = X[DP(t+256*m)].x * scale;
            d[t+256*m] = (v >= 0.f) ? v : a*v;
        }
    }
}

// fused fwd FFT -> (v += mmu*G ; v /= UKER[inline]) -> inv FFT
// IT0=1: G = maskT*F0T ; IT0=0: G = g_G (written by postOp2)
template<int IT0>
__global__ __launch_bounds__(256) void k_fftsolve(const float2* __restrict__ src,
                                                  float2* __restrict__ dst,
                                                  float scale,
                                                  const float* __restrict__ mmu,
                                                  const float* __restrict__ lam,
                                                  const float* __restrict__ gama)
{
    __shared__ float2 sA[1280];
    __shared__ float2 sB[1280];
    __shared__ float2 tw[1088];
    int t = threadIdx.x;
    size_t base = (size_t)blockIdx.x*FN;
    int p = blockIdx.x & (FN-1);
    for (int j = t; j < FN; j += 256) tw[TP(j)] = g_TW[j];
    const float2* s = src + base;
#pragma unroll
    for (int m = 0; m < 4; ++m) sA[DP(t+256*m)] = s[t+256*m];
    __syncthreads();
    float2* X = sA; float2* Y = sB;
#pragma unroll
    for (int st = 0; st < 5; ++st) {
        r4stage<0>(X, Y, tw, t, st);
        __syncthreads();
        float2* tmp = X; X = Y; Y = tmp;
    }
    float mv = mmu[0], lv = lam[0], gv = gama[0];
    float4 tp = g_TRIG[p];
#pragma unroll
    for (int m = 0; m < 4; ++m) {
        int q = t + 256*m;
        size_t i = base + q;
        float2 v = X[DP(q)];
        float mk = g_MASKT[i];
        float2 g;
        if (IT0) { float2 f0 = g_F0T[i]; g = make_float2(mk*f0.x, mk*f0.y); }
        else      g = g_G[i];
        v.x += mv*g.x;  v.y += mv*g.y;
        // inline UKER (identical math to ukerA)
        float4 tq = g_TRIG[q];
        float Br = 4.f - tp.x - tq.x - tp.z - tq.z;
        float Bi = tp.y + tq.y - tp.w - tq.w;
        float cf = tp.x*tq.x - tp.y*tq.y;
        float sf = tp.y*tq.x + tp.x*tq.y;
        float2 w = make_float2(mv*mk*mk + gv + lv*(Br*cf + Bi*sf),
                               lv*(Bi*cf - Br*sf));
        float d = 1.f/(w.x*w.x + w.y*w.y);
        X[DP(q)] = make_float2((v.x*w.x + v.y*w.y)*d, (v.y*w.x - v.x*w.y)*d);
    }
    __syncthreads();
#pragma unroll
    for (int st = 0; st < 5; ++st) {
        r4stage<1>(X, Y, tw, t, st);
        __syncthreads();
        float2* tmp = X; X = Y; Y = tmp;
    }
    float2* d = dst + base;
#pragma unroll
    for (int m = 0; m < 4; ++m) {
        float2 v = X[DP(t+256*m)];
        d[t+256*m] = make_float2(v.x*scale, v.y*scale);
    }
}

// ---------------- transposes ----------------
__global__ void k_transpose_c(const float2* __restrict__ src, float2* __restrict__ dst)
{
    __shared__ float2 tile[32][33];
    int b = blockIdx.z;
    const float2* s = src + (size_t)b*FNN;
    float2* d = dst + (size_t)b*FNN;
    int x  = blockIdx.x*32 + threadIdx.x;
    int y0 = blockIdx.y*32 + threadIdx.y;
#pragma unroll
    for (int i = 0; i < 32; i += 8)
        tile[threadIdx.y+i][threadIdx.x] = s[(size_t)(y0+i)*FN + x];
    __syncthreads();
    int x2 = blockIdx.y*32 + threadIdx.x;
    int y2 = blockIdx.x*32 + threadIdx.y;
#pragma unroll
    for (int i = 0; i < 32; i += 8)
        d[(size_t)(y2+i)*FN + x2] = tile[threadIdx.x][threadIdx.y+i];
}

__global__ void k_transpose_r(const float* __restrict__ src, float* __restrict__ dst)
{
    __shared__ float tile[32][33];
    int b = blockIdx.z;
    const float* s = src + (size_t)b*FNN;
    float* d = dst + (size_t)b*FNN;
    int x  = blockIdx.x*32 + threadIdx.x;
    int y0 = blockIdx.y*32 + threadIdx.y;
#pragma unroll
    for (int i = 0; i < 32; i += 8)
        tile[threadIdx.y+i][threadIdx.x] = s[(size_t)(y0+i)*FN + x];
    __syncthreads();
    int x2 = blockIdx.y*32 + threadIdx.x;
    int y2 = blockIdx.x*32 + threadIdx.y;
#pragma unroll
    for (int i = 0; i < 32; i += 8)
        d[(size_t)(y2+i)*FN + x2] = tile[threadIdx.x][threadIdx.y+i];
}

__global__ void k_make_f0T(const float* __restrict__ fr, const float* __restrict__ fi,
                           float2* __restrict__ dst)
{
    __shared__ float tr[32][33];
    __shared__ float ti[32][33];
    int b = blockIdx.z;
    const float* sr = fr + (size_t)b*FNN;
    const float* si = fi + (size_t)b*FNN;
    float2* d = dst + (size_t)b*FNN;
    int x  = blockIdx.x*32 + threadIdx.x;
    int y0 = blockIdx.y*32 + threadIdx.y;
#pragma unroll
    for (int i = 0; i < 32; i += 8) {
        tr[threadIdx.y+i][threadIdx.x] = sr[(size_t)(y0+i)*FN + x];
        ti[threadIdx.y+i][threadIdx.x] = si[(size_t)(y0+i)*FN + x];
    }
    __syncthreads();
    int x2 = blockIdx.y*32 + threadIdx.x;
    int y2 = blockIdx.x*32 + threadIdx.y;
#pragma unroll
    for (int i = 0; i < 32; i += 8)
        d[(size_t)(y2+i)*FN + x2] =
            make_float2(tr[threadIdx.x][threadIdx.y+i], ti[threadIdx.x][threadIdx.y+i]);
}

// ---------------- fused shrink + b-update ----------------
__global__ void k_shrinkbxy(const float* __restrict__ lam,
                            const float* __restrict__ prelu)
{
    int i = blockIdx.x*blockDim.x + threadIdx.x;
    if (i >= TOT) return;
    float a  = prelu[0];
    float il = 1.f/lam[0];
    float dx = g_DX[i], dy = g_DY[i], bx = g_BX[i], by = g_BY[i];
    float vx = dx + bx;
    float vy = dy + by;
    float s = sqrtf(vx*vx + vy*vy);
    float nx = vx - s*il;
    float ny = vy - s*il;
    nx = (nx >= 0.f) ? nx : a*nx;
    ny = (ny >= 0.f) ? ny : a*ny;
    int x = i & (FN-1);
    int y = (i >> 10) & (FN-1);
    int rowb = i - x;
    float dxu = 0.f;
    if (x >= 1) {
        int xm = (x == 1) ? FN-1 : x-1;
        dxu = g_U[i] - g_U[rowb + xm];
    }
    float dyu = 0.f;
    if (y >= 1) {
        int ym = (y == 1) ? FN-1 : y-1;
        dyu = g_U[i] - g_U[i + (ym - y)*FN];
    }
    g_DX[i] = nx;  g_DY[i] = ny;
    g_BX[i] = bx + dxu - nx;
    g_BY[i] = by + dyu - ny;
}

// ---------------- DWT analysis ----------------
__global__ void k_afb_w(const float* __restrict__ src, float* __restrict__ lo,
                        float* __restrict__ hi)
{
    int i = blockIdx.x*blockDim.x + threadIdx.x;
    if (i >= NB*FN*WD) return;
    int o = i % WD;
    int r = i / WD;
    const float* row = src + (size_t)r*FN;
    float l = 0.f, h = 0.f;
#pragma unroll
    for (int k = 0; k < 14; ++k) {
        int j = 2*o + k - 12;
        j = (j < 0) ? -j : ((j >= FN) ? (2*FN - 2 - j) : j);
        float v = row[j];
        l += v * cH0A[k];
        h += v * cH1A[k];
    }
    lo[i] = l;
    hi[i] = h;
}

__global__ void k_afb_h(const float* __restrict__ src, float* __restrict__ lo,
                        float* __restrict__ hi)
{
    int i = blockIdx.x*blockDim.x + threadIdx.x;
    if (i >= SLL) return;
    int w = i % WD;
    int o = (i / WD) % WD;
    int b = i / (WD*WD);
    const float* base = src + (size_t)b*FN*WD;
    float l = 0.f, h = 0.f;
#pragma unroll
    for (int k = 0; k < 14; ++k) {
        int j = 2*o + k - 12;
        j = (j < 0) ? -j : ((j >= FN) ? (2*FN - 2 - j) : j);
        float v = base[(size_t)j*WD + w];
        l += v * cH0A[k];
        h += v * cH1A[k];
    }
    lo[i] = l;
    hi[i] = h;
}

// column DWT fused with w/b update
__global__ void k_afb_h_w(const float* __restrict__ src,
                          float* __restrict__ bwLo, float* __restrict__ wLo,
                          float* __restrict__ bwHi, float* __restrict__ wHi,
                          const float* __restrict__ gama,
                          const float* __restrict__ prelu)
{
    int i = blockIdx.x*blockDim.x + threadIdx.x;
    if (i >= SLL) return;
    int w = i % WD;
    int o = (i / WD) % WD;
    int b = i / (WD*WD);
    const float* base = src + (size_t)b*FN*WD;
    float l = 0.f, h = 0.f;
#pragma unroll
    for (int k = 0; k < 14; ++k) {
        int j = 2*o + k - 12;
        j = (j < 0) ? -j : ((j >= FN) ? (2*FN - 2 - j) : j);
        float v = base[(size_t)j*WD + w];
        l += v * cH0A[k];
        h += v * cH1A[k];
    }
    float a  = prelu[0];
    float ig = 1.f/gama[0];
    float bv = bwLo[i];
    float t  = l + bv - ig;
    float wv = (t >= 0.f) ? t : a*t;
    wLo[i]  = wv;
    bwLo[i] = bv + l - wv;
    bv = bwHi[i];
    t  = h + bv - ig;
    wv = (t >= 0.f) ? t : a*t;
    wHi[i]  = wv;
    bwHi[i] = bv + h - wv;
}

// ---------------- IDWT column synthesis (both lo+hi halves in one launch) ----
__global__ void k_sfb_h2()
{
    int half = NB*FN*WD;
    int i = blockIdx.x*blockDim.x + threadIdx.x;
    if (i >= 2*half) return;
    const float *lA, *lB, *hA, *hB;
    float* out;
    int ii = i;
    if (i < half) {
        lA = g_WL;  lB = g_BWL;
        hA = g_WH;  hB = g_BWH;
        out = g_LOS;
    } else {
        ii -= half;
        lA = g_WH + (size_t)SLL;    lB = g_BWH + (size_t)SLL;
        hA = g_WH + (size_t)2*SLL;  hB = g_BWH + (size_t)2*SLL;
        out = g_HIS;
    }
    int w = ii % WD;
    int o = (ii / WD) % FN;
    int b = ii / (FN*WD);
    size_t bb = (size_t)b*WD*WD;
    float acc = 0.f;
    int k0 = (o + 1) & 1;
#pragma unroll
    for (int kk = 0; kk < 7; ++kk) {
        int k = k0 + 2*kk;
        int m = (o + k - 1) >> 1;
        size_t idx = bb + (size_t)m*WD + w;
        float lo = lA[idx] - lB[idx];
        float hi = hA[idx] - hB[idx];
        acc += lo * cG0[k] + hi * cG1[k];
    }
    out[ii] = acc;
}

// ---------------- host orchestration ----------------
static inline int eb(int n) { return (n + 255) / 256; }

extern "C" void kernel_launch(void* const* d_in, const int* in_sizes, int n_in,
                              void* d_out, int out_size)
{
    const float* u_in   = (const float*)d_in[0];
    const float* uvMask = (const float*)d_in[1];
    const float* f_real = (const float*)d_in[3];
    const float* f_imag = (const float*)d_in[4];
    const float* lam    = (const float*)d_in[5];
    const float* gama   = (const float*)d_in[6];
    const float* mmu    = (const float*)d_in[7];
    const float* prelu  = (const float*)d_in[8];
    float* out = (float*)d_out;

    void *pCA, *pCB, *pU, *pMASKT, *pF0T, *pG;
    void *pDX, *pDY, *pBX, *pBY;
    void *pWL, *pBWL, *pWH, *pBWH;
    void *pLOT, *pHIT;
    cudaGetSymbolAddress(&pCA, g_CA);       cudaGetSymbolAddress(&pCB, g_CB);
    cudaGetSymbolAddress(&pU, g_U);         cudaGetSymbolAddress(&pG, g_G);
    cudaGetSymbolAddress(&pMASKT, g_MASKT); cudaGetSymbolAddress(&pF0T, g_F0T);
    cudaGetSymbolAddress(&pDX, g_DX);       cudaGetSymbolAddress(&pDY, g_DY);
    cudaGetSymbolAddress(&pBX, g_BX);       cudaGetSymbolAddress(&pBY, g_BY);
    cudaGetSymbolAddress(&pWL, g_WL);       cudaGetSymbolAddress(&pBWL, g_BWL);
    cudaGetSymbolAddress(&pWH, g_WH);       cudaGetSymbolAddress(&pBWH, g_BWH);
    cudaGetSymbolAddress(&pLOT, g_LOT);     cudaGetSymbolAddress(&pHIT, g_HIT);

    dim3 tb(32, 8), tg(32, 32, NB);
    const int FFTG = NB*FN;

    // ----- init -----
    k_twinit<<<4, 256>>>();
    k_transpose_r<<<tg, tb>>>(uvMask, (float*)pMASKT);
    k_make_f0T<<<tg, tb>>>(f_real, f_imag, (float2*)pF0T);
    cudaMemsetAsync(pDX, 0, (size_t)TOT*4, 0);
    cudaMemsetAsync(pDY, 0, (size_t)TOT*4, 0);
    cudaMemsetAsync(pBX, 0, (size_t)TOT*4, 0);
    cudaMemsetAsync(pBY, 0, (size_t)TOT*4, 0);
    cudaMemsetAsync(pBWL, 0, (size_t)SLL*4, 0);
    cudaMemsetAsync(pBWH, 0, (size_t)(3*SLL)*4, 0);

    // dwt2(u_in) -> WL, WH
    k_afb_w<<<eb(NB*FN*WD), 256>>>(u_in, (float*)pLOT, (float*)pHIT);
    k_afb_h<<<eb(SLL), 256>>>((float*)pLOT, (float*)pWL, (float*)pWH);
    k_afb_h<<<eb(SLL), 256>>>((float*)pHIT, (float*)pWH + (size_t)SLL,
                              (float*)pWH + (size_t)2*SLL);

    // ----- iterations -----
    for (int it = 0; it < 2; ++it) {
        k_sfb_h2<<<eb(2*NB*FN*WD), 256>>>();

        // rhs (spatial part, inline row-IDWT) -> fwd rows
        k_fft4<0><<<FFTG, 256>>>(pCA, pCB, 0, 0, 1.f, prelu, 4, 0, lam, gama);
        k_transpose_c<<<tg, tb>>>((float2*)pCB, (float2*)pCA);          // [p][y]
        if (it == 0)
            k_fftsolve<1><<<FFTG, 256>>>((float2*)pCA, (float2*)pCB, 1.f/FN,
                                         mmu, lam, gama);
        else
            k_fftsolve<0><<<FFTG, 256>>>((float2*)pCA, (float2*)pCB, 1.f/FN,
                                         mmu, lam, gama);
        k_transpose_c<<<tg, tb>>>((float2*)pCB, (float2*)pCA);          // [y][p]
        void* udst = (it == 0) ? pU : (void*)out;
        k_fft4<1><<<FFTG, 256>>>(pCA, udst, 0, 1, 1.f/FN, prelu, 0, 0, lam, gama);

        if (it == 0) {
            k_shrinkbxy<<<eb(TOT), 256>>>(lam, prelu);
            k_afb_w<<<eb(NB*FN*WD), 256>>>((float*)pU, (float*)pLOT, (float*)pHIT);
            k_afb_h_w<<<eb(SLL), 256>>>((float*)pLOT,
                                        (float*)pBWL, (float*)pWL,
                                        (float*)pBWH, (float*)pWH, gama, prelu);
            k_afb_h_w<<<eb(SLL), 256>>>((float*)pHIT,
                                        (float*)pBWH + (size_t)SLL,
                                        (float*)pWH + (size_t)SLL,
                                        (float*)pBWH + (size_t)2*SLL,
                                        (float*)pWH + (size_t)2*SLL, gama, prelu);
            // G' = maskT*(2*F0T - maskT*FU): fft2(u) with G' store epilogue
            k_fft4<0><<<FFTG, 256>>>(pU, pCA, 1, 0, 1.f, prelu, 0, 0, lam, gama);
            k_transpose_c<<<tg, tb>>>((float2*)pCA, (float2*)pCB);      // [p][y]
            k_fft4<0><<<FFTG, 256>>>(pCB, pG, 0, 0, 1.f, prelu, 0, 2, lam, gama);
        }
    }
    (void)in_sizes; (void)n_in; (void)out_size;
}

// round 13
// speedup vs baseline: 2.4656x; 1.0612x over previous
#include <cuda_runtime.h>
#include <math.h>

#define FN   1024
#define NB   4
#define FNN  (FN*FN)
#define TOT  (NB*FNN)
#define WD   518
#define SLL  (NB*WD*WD)
#define SLW  (NB*FN*WD)
#define PIF  3.14159265358979323846f

#define DP(i) ((i) + ((i)>>2))
#define TP(i) ((i) + ((i)>>4))

// ---------------- static device scratch ----------------
__device__ float2 g_CA[TOT];
__device__ float2 g_CB[TOT];
__device__ float2 g_F0T[TOT];    // [p][q]
__device__ float2 g_G[TOT];      // spectral mask*f, [p][q]
__device__ float2 g_TW[FN];
__device__ float4 g_TRIG[FN];

__device__ float g_U[TOT];
__device__ float g_DX[TOT];
__device__ float g_DY[TOT];
__device__ float g_BX[TOT];
__device__ float g_BY[TOT];
__device__ float g_MASKT[TOT];

__device__ float g_WL[SLL];
__device__ float g_BWL[SLL];
__device__ float g_WH[3*SLL];
__device__ float g_BWH[3*SLL];
__device__ float g_LOT[SLW];
__device__ float g_HIT[SLW];
__device__ float g_LOS[SLW];
__device__ float g_HIS[SLW];

// ---------------- wavelet filters (db7, L=14) ----------------
__constant__ float cH0A[14] = {
    0.010268176708511255f, 0.004010244871533663f, -0.10780823770381774f,
   -0.14004724044296152f, 0.2886296317515146f, 0.767764317003164f,
    0.5361019170917628f, 0.017441255086855827f, -0.049552834937127255f,
    0.0678926935013727f, 0.03051551316596357f, -0.01263630340325193f,
   -0.0010473848886829163f, 0.002681814568257878f };
__constant__ float cH1A[14] = {
    0.002681814568257878f, 0.0010473848886829163f, -0.01263630340325193f,
   -0.03051551316596357f, 0.0678926935013727f, 0.049552834937127255f,
    0.017441255086855827f, -0.5361019170917628f, 0.767764317003164f,
   -0.2886296317515146f, -0.14004724044296152f, 0.10780823770381774f,
    0.004010244871533663f, -0.010268176708511255f };
__constant__ float cG0[14] = {
    0.002681814568257878f, -0.0010473848886829163f, -0.01263630340325193f,
    0.03051551316596357f, 0.0678926935013727f, -0.049552834937127255f,
    0.017441255086855827f, 0.5361019170917628f, 0.767764317003164f,
    0.2886296317515146f, -0.14004724044296152f, -0.10780823770381774f,
    0.004010244871533663f, 0.010268176708511255f };
__constant__ float cG1[14] = {
   -0.010268176708511255f, 0.004010244871533663f, 0.10780823770381774f,
   -0.14004724044296152f, -0.2886296317515146f, 0.767764317003164f,
   -0.5361019170917628f, 0.017441255086855827f, 0.049552834937127255f,
    0.0678926935013727f, -0.03051551316596357f, -0.01263630340325193f,
    0.0010473848886829163f, 0.002681814568257878f };

__device__ __forceinline__ float2 cmulf(float2 a, float2 b) {
    return make_float2(a.x*b.x - a.y*b.y, a.x*b.y + a.y*b.x);
}

__global__ void k_twinit()
{
    int j = blockIdx.x*blockDim.x + threadIdx.x;
    if (j >= FN) return;
    float th = 2.f*PIF*(float)j/(float)FN;
    float sv, cv; sincosf(-th, &sv, &cv);
    g_TW[j] = make_float2(cv, sv);
    float s1, c1, s2, c2;
    sincosf(th, &s1, &c1);
    sincosf(2.f*th, &s2, &c2);
    g_TRIG[j] = make_float4(c1, s1, c2, s2);
}

template<int INV>
__device__ __forceinline__ void r4stage(const float2* __restrict__ X,
                                        float2* __restrict__ Y,
                                        const float2* __restrict__ tw,
                                        int t, int s)
{
    int ns = 1 << (2*s);
    int k  = t & (ns - 1);
    int j  = ((t - k) << 2) + k;
    int sh = 8 - 2*s;
    float2 c0 = X[DP(t)], c1 = X[DP(t+256)], c2 = X[DP(t+512)], c3 = X[DP(t+768)];
    float2 w1 = tw[TP(k << sh)];
    float2 w2 = tw[TP((2*k) << sh)];
    float2 w3 = tw[TP((3*k) << sh)];
    if (INV) { w1.y = -w1.y; w2.y = -w2.y; w3.y = -w3.y; }
    c1 = cmulf(c1, w1); c2 = cmulf(c2, w2); c3 = cmulf(c3, w3);
    float2 t0 = make_float2(c0.x+c2.x, c0.y+c2.y);
    float2 t1 = make_float2(c0.x-c2.x, c0.y-c2.y);
    float2 t2 = make_float2(c1.x+c3.x, c1.y+c3.y);
    float2 dd = make_float2(c1.x-c3.x, c1.y-c3.y);
    float2 t3 = INV ? make_float2(-dd.y, dd.x) : make_float2(dd.y, -dd.x);
    Y[DP(j)]      = make_float2(t0.x+t2.x, t0.y+t2.y);
    Y[DP(j+ns)]   = make_float2(t1.x+t3.x, t1.y+t3.y);
    Y[DP(j+2*ns)] = make_float2(t0.x-t2.x, t0.y-t2.y);
    Y[DP(j+3*ns)] = make_float2(t1.x-t3.x, t1.y-t3.y);
}

// rhs value for (row base, x, y)
__device__ __forceinline__ float rhs_val(size_t base, int x, int y,
                                         float lv, float gv,
                                         const float* __restrict__ lrow,
                                         const float* __restrict__ hrow)
{
    size_t i = base + x;
    float dxt = 0.f;
    if (x >= 1) {
        int xn = (x == FN-1) ? 1 : x+1;
        dxt = (g_DX[i] - g_BX[i]) - (g_DX[base+xn] - g_BX[base+xn]);
    }
    float dyt = 0.f;
    if (y >= 1) {
        int yn = (y == FN-1) ? 1 : y+1;
        size_t jj = i + (size_t)(yn - y)*FN;
        dyt = (g_DY[i] - g_BY[i]) - (g_DY[jj] - g_BY[jj]);
    }
    float idwt = 0.f;
    int k0 = (x + 1) & 1;
#pragma unroll
    for (int kk = 0; kk < 7; ++kk) {
        int k = k0 + 2*kk;
        int mm = (x + k - 1) >> 1;
        idwt += lrow[mm] * cG0[k] + hrow[mm] * cG1[k];
    }
    return lv*(dxt + dyt) + gv*idwt;
}

// ---- forward 2-for-1: two REAL rows (2r, 2r+1) per block -> two full spectra
// PRE: 0 = load real rows from srcv; 4 = rhs inline (srcv ignored)
template<int PRE>
__global__ __launch_bounds__(256) void k_fwd2(const float* __restrict__ srcv,
                                              float2* __restrict__ dst,
                                              const float* __restrict__ lam,
                                              const float* __restrict__ gama)
{
    __shared__ float2 sA[1280];
    __shared__ float2 sB[1280];
    __shared__ float2 tw[1088];
    int t = threadIdx.x;
    int r0 = 2*blockIdx.x;
    size_t base0 = (size_t)r0*FN;
    size_t base1 = base0 + FN;
    for (int j = t; j < FN; j += 256) tw[TP(j)] = g_TW[j];
    if (PRE == 0) {
        const float* s0 = srcv + base0;
        const float* s1 = srcv + base1;
#pragma unroll
        for (int m = 0; m < 4; ++m) {
            int x = t + 256*m;
            sA[DP(x)] = make_float2(s0[x], s1[x]);
        }
    } else {
        int y0 = r0 & (FN-1);
        float lv = lam[0], gv = gama[0];
        const float* l0 = g_LOS + (size_t)r0*WD;
        const float* h0 = g_HIS + (size_t)r0*WD;
        const float* l1 = l0 + WD;
        const float* h1 = h0 + WD;
#pragma unroll
        for (int m = 0; m < 4; ++m) {
            int x = t + 256*m;
            float a = rhs_val(base0, x, y0,     lv, gv, l0, h0);
            float b = rhs_val(base1, x, y0 + 1, lv, gv, l1, h1);
            sA[DP(x)] = make_float2(a, b);
        }
    }
    __syncthreads();
    float2* X = sA; float2* Y = sB;
#pragma unroll
    for (int s = 0; s < 5; ++s) {
        r4stage<0>(X, Y, tw, t, s);
        __syncthreads();
        float2* tmp = X; X = Y; Y = tmp;
    }
    float2* d0 = dst + base0;
    float2* d1 = dst + base1;
#pragma unroll
    for (int m = 0; m < 4; ++m) {
        int k  = t + 256*m;
        int kk = (FN - k) & (FN-1);
        float2 Zk = X[DP(k)];
        float2 Zm = X[DP(kk)];
        d0[k] = make_float2(0.5f*(Zk.x + Zm.x), 0.5f*(Zk.y - Zm.y));
        d1[k] = make_float2(0.5f*(Zk.y + Zm.y), 0.5f*(Zm.x - Zk.x));
    }
}

// ---- inverse 2-for-1 with SYMMETRIZATION (exact Re of non-symmetric spectra):
// T(k) = Ssym1(k) + i*Ssym2(k), Ssym(k) = (S(k)+conj(S(-k)))/2
// ifft(T).x = Re(ifft S1) -> row0 ; .y = Re(ifft S2) -> row1 ; + srelu
__global__ __launch_bounds__(256) void k_inv2r(const float2* __restrict__ src,
                                               float* __restrict__ dst,
                                               float scale,
                                               const float* __restrict__ prelu)
{
    __shared__ float2 sA[1280];
    __shared__ float2 sB[1280];
    __shared__ float2 tw[1088];
    int t = threadIdx.x;
    int r0 = 2*blockIdx.x;
    size_t base0 = (size_t)r0*FN;
    size_t base1 = base0 + FN;
    for (int j = t; j < FN; j += 256) tw[TP(j)] = g_TW[j];
    const float2* s0 = src + base0;
    const float2* s1 = src + base1;
#pragma unroll
    for (int m = 0; m < 4; ++m) {
        int x = t + 256*m;
        int xr = (FN - x) & (FN-1);
        float2 a  = s0[x],  b  = s1[x];
        float2 ar = s0[xr], br = s1[xr];
        sA[DP(x)] = make_float2(0.5f*(a.x + ar.x - b.y + br.y),
                                0.5f*(a.y - ar.y + b.x + br.x));
    }
    __syncthreads();
    float2* X = sA; float2* Y = sB;
#pragma unroll
    for (int s = 0; s < 5; ++s) {
        r4stage<1>(X, Y, tw, t, s);
        __syncthreads();
        float2* tmp = X; X = Y; Y = tmp;
    }
    float a = prelu[0];
    float* d0 = dst + base0;
    float* d1 = dst + base1;
#pragma unroll
    for (int m = 0; m < 4; ++m) {
        int x = t + 256*m;
        float2 z = X[DP(x)];
        float v0 = z.x*scale;
        float v1 = z.y*scale;
        d0[x] = (v0 >= 0.f) ? v0 : a*v0;
        d1[x] = (v1 >= 0.f) ? v1 : a*v1;
    }
}

// ---- complex-in FFT (direction INV), postOp: 0 none; 2 store G' ----
template<int INV>
__global__ __launch_bounds__(256) void k_fft4(const float2* __restrict__ src,
                                              float2* __restrict__ dst,
                                              float scale, int postOp)
{
    __shared__ float2 sA[1280];
    __shared__ float2 sB[1280];
    __shared__ float2 tw[1088];
    int t = threadIdx.x;
    size_t base = (size_t)blockIdx.x*FN;
    for (int j = t; j < FN; j += 256) tw[TP(j)] = g_TW[j];
    const float2* s = src + base;
#pragma unroll
    for (int m = 0; m < 4; ++m) sA[DP(t+256*m)] = s[t+256*m];
    __syncthreads();
    float2* X = sA; float2* Y = sB;
#pragma unroll
    for (int st = 0; st < 5; ++st) {
        r4stage<INV>(X, Y, tw, t, st);
        __syncthreads();
        float2* tmp = X; X = Y; Y = tmp;
    }
    float2* d = dst + base;
#pragma unroll
    for (int m = 0; m < 4; ++m) {
        int idx = t + 256*m;
        float2 v = X[DP(idx)];
        v.x *= scale; v.y *= scale;
        if (postOp == 2) {
            float mk = g_MASKT[base + idx];
            float2 f0 = g_F0T[base + idx];
            v = make_float2(mk*(2.f*f0.x - mk*v.x), mk*(2.f*f0.y - mk*v.y));
        }
        d[idx] = v;
    }
}

// fused fwd FFT -> (v += mmu*G ; v /= UKER inline) -> inv FFT
template<int IT0>
__global__ __launch_bounds__(256) void k_fftsolve(const float2* __restrict__ src,
                                                  float2* __restrict__ dst,
                                                  float scale,
                                                  const float* __restrict__ mmu,
                                                  const float* __restrict__ lam,
                                                  const float* __restrict__ gama)
{
    __shared__ float2 sA[1280];
    __shared__ float2 sB[1280];
    __shared__ float2 tw[1088];
    int t = threadIdx.x;
    size_t base = (size_t)blockIdx.x*FN;
    int p = blockIdx.x & (FN-1);
    for (int j = t; j < FN; j += 256) tw[TP(j)] = g_TW[j];
    const float2* s = src + base;
#pragma unroll
    for (int m = 0; m < 4; ++m) sA[DP(t+256*m)] = s[t+256*m];
    __syncthreads();
    float2* X = sA; float2* Y = sB;
#pragma unroll
    for (int st = 0; st < 5; ++st) {
        r4stage<0>(X, Y, tw, t, st);
        __syncthreads();
        float2* tmp = X; X = Y; Y = tmp;
    }
    float mv = mmu[0], lv = lam[0], gv = gama[0];
    float4 tp = g_TRIG[p];
#pragma unroll
    for (int m = 0; m < 4; ++m) {
        int q = t + 256*m;
        size_t i = base + q;
        float2 v = X[DP(q)];
        float mk = g_MASKT[i];
        float2 g;
        if (IT0) { float2 f0 = g_F0T[i]; g = make_float2(mk*f0.x, mk*f0.y); }
        else      g = g_G[i];
        v.x += mv*g.x;  v.y += mv*g.y;
        float4 tq = g_TRIG[q];
        float Br = 4.f - tp.x - tq.x - tp.z - tq.z;
        float Bi = tp.y + tq.y - tp.w - tq.w;
        float cf = tp.x*tq.x - tp.y*tq.y;
        float sf = tp.y*tq.x + tp.x*tq.y;
        float2 w = make_float2(mv*mk*mk + gv + lv*(Br*cf + Bi*sf),
                               lv*(Bi*cf - Br*sf));
        float d = 1.f/(w.x*w.x + w.y*w.y);
        X[DP(q)] = make_float2((v.x*w.x + v.y*w.y)*d, (v.y*w.x - v.x*w.y)*d);
    }
    __syncthreads();
#pragma unroll
    for (int st = 0; st < 5; ++st) {
        r4stage<1>(X, Y, tw, t, st);
        __syncthreads();
        float2* tmp = X; X = Y; Y = tmp;
    }
    float2* d = dst + base;
#pragma unroll
    for (int m = 0; m < 4; ++m) {
        float2 v = X[DP(t+256*m)];
        d[t+256*m] = make_float2(v.x*scale, v.y*scale);
    }
}

// ---------------- transposes ----------------
__global__ void k_transpose_c(const float2* __restrict__ src, float2* __restrict__ dst)
{
    __shared__ float2 tile[32][33];
    int b = blockIdx.z;
    const float2* s = src + (size_t)b*FNN;
    float2* d = dst + (size_t)b*FNN;
    int x  = blockIdx.x*32 + threadIdx.x;
    int y0 = blockIdx.y*32 + threadIdx.y;
#pragma unroll
    for (int i = 0; i < 32; i += 8)
        tile[threadIdx.y+i][threadIdx.x] = s[(size_t)(y0+i)*FN + x];
    __syncthreads();
    int x2 = blockIdx.y*32 + threadIdx.x;
    int y2 = blockIdx.x*32 + threadIdx.y;
#pragma unroll
    for (int i = 0; i < 32; i += 8)
        d[(size_t)(y2+i)*FN + x2] = tile[threadIdx.x][threadIdx.y+i];
}

__global__ void k_transpose_r(const float* __restrict__ src, float* __restrict__ dst)
{
    __shared__ float tile[32][33];
    int b = blockIdx.z;
    const float* s = src + (size_t)b*FNN;
    float* d = dst + (size_t)b*FNN;
    int x  = blockIdx.x*32 + threadIdx.x;
    int y0 = blockIdx.y*32 + threadIdx.y;
#pragma unroll
    for (int i = 0; i < 32; i += 8)
        tile[threadIdx.y+i][threadIdx.x] = s[(size_t)(y0+i)*FN + x];
    __syncthreads();
    int x2 = blockIdx.y*32 + threadIdx.x;
    int y2 = blockIdx.x*32 + threadIdx.y;
#pragma unroll
    for (int i = 0; i < 32; i += 8)
        d[(size_t)(y2+i)*FN + x2] = tile[threadIdx.x][threadIdx.y+i];
}

__global__ void k_make_f0T(const float* __restrict__ fr, const float* __restrict__ fi,
                           float2* __restrict__ dst)
{
    __shared__ float tr[32][33];
    __shared__ float ti[32][33];
    int b = blockIdx.z;
    const float* sr = fr + (size_t)b*FNN;
    const float* si = fi + (size_t)b*FNN;
    float2* d = dst + (size_t)b*FNN;
    int x  = blockIdx.x*32 + threadIdx.x;
    int y0 = blockIdx.y*32 + threadIdx.y;
#pragma unroll
    for (int i = 0; i < 32; i += 8) {
        tr[threadIdx.y+i][threadIdx.x] = sr[(size_t)(y0+i)*FN + x];
        ti[threadIdx.y+i][threadIdx.x] = si[(size_t)(y0+i)*FN + x];
    }
    __syncthreads();
    int x2 = blockIdx.y*32 + threadIdx.x;
    int y2 = blockIdx.x*32 + threadIdx.y;
#pragma unroll
    for (int i = 0; i < 32; i += 8)
        d[(size_t)(y2+i)*FN + x2] =
            make_float2(tr[threadIdx.x][threadIdx.y+i], ti[threadIdx.x][threadIdx.y+i]);
}

// ---------------- fused shrink + b-update ----------------
__global__ void k_shrinkbxy(const float* __restrict__ lam,
                            const float* __restrict__ prelu)
{
    int i = blockIdx.x*blockDim.x + threadIdx.x;
    if (i >= TOT) return;
    float a  = prelu[0];
    float il = 1.f/lam[0];
    float dx = g_DX[i], dy = g_DY[i], bx = g_BX[i], by = g_BY[i];
    float vx = dx + bx;
    float vy = dy + by;
    float s = sqrtf(vx*vx + vy*vy);
    float nx = vx - s*il;
    float ny = vy - s*il;
    nx = (nx >= 0.f) ? nx : a*nx;
    ny = (ny >= 0.f) ? ny : a*ny;
    int x = i & (FN-1);
    int y = (i >> 10) & (FN-1);
    int rowb = i - x;
    float dxu = 0.f;
    if (x >= 1) {
        int xm = (x == 1) ? FN-1 : x-1;
        dxu = g_U[i] - g_U[rowb + xm];
    }
    float dyu = 0.f;
    if (y >= 1) {
        int ym = (y == 1) ? FN-1 : y-1;
        dyu = g_U[i] - g_U[i + (ym - y)*FN];
    }
    g_DX[i] = nx;  g_DY[i] = ny;
    g_BX[i] = bx + dxu - nx;
    g_BY[i] = by + dyu - ny;
}

// ---------------- DWT row analysis (smem tiled, block per row) ----------------
__global__ __launch_bounds__(256) void k_afb_w(const float* __restrict__ src,
                                               float* __restrict__ lo,
                                               float* __restrict__ hi)
{
    __shared__ float rs[FN];
    int t = threadIdx.x;
    int r = blockIdx.x;
    const float* row = src + (size_t)r*FN;
#pragma unroll
    for (int m = 0; m < 4; ++m) rs[t+256*m] = row[t+256*m];
    __syncthreads();
    size_t ob = (size_t)r*WD;
    for (int o = t; o < WD; o += 256) {
        float l = 0.f, h = 0.f;
#pragma unroll
        for (int k = 0; k < 14; ++k) {
            int j = 2*o + k - 12;
            j = (j < 0) ? -j : ((j >= FN) ? (2*FN - 2 - j) : j);
            float v = rs[j];
            l += v * cH0A[k];
            h += v * cH1A[k];
        }
        lo[ob + o] = l;
        hi[ob + o] = h;
    }
}

// column DWT (plain)
__global__ void k_afb_h(const float* __restrict__ src, float* __restrict__ lo,
                        float* __restrict__ hi)
{
    int i = blockIdx.x*blockDim.x + threadIdx.x;
    if (i >= SLL) return;
    int w = i % WD;
    int o = (i / WD) % WD;
    int b = i / (WD*WD);
    const float* base = src + (size_t)b*FN*WD;
    float l = 0.f, h = 0.f;
#pragma unroll
    for (int k = 0; k < 14; ++k) {
        int j = 2*o + k - 12;
        j = (j < 0) ? -j : ((j >= FN) ? (2*FN - 2 - j) : j);
        float v = base[(size_t)j*WD + w];
        l += v * cH0A[k];
        h += v * cH1A[k];
    }
    lo[i] = l;
    hi[i] = h;
}

// column DWT fused with w/b update
__global__ void k_afb_h_w(const float* __restrict__ src,
                          float* __restrict__ bwLo, float* __restrict__ wLo,
                          float* __restrict__ bwHi, float* __restrict__ wHi,
                          const float* __restrict__ gama,
                          const float* __restrict__ prelu)
{
    int i = blockIdx.x*blockDim.x + threadIdx.x;
    if (i >= SLL) return;
    int w = i % WD;
    int o = (i / WD) % WD;
    int b = i / (WD*WD);
    const float* base = src + (size_t)b*FN*WD;
    float l = 0.f, h = 0.f;
#pragma unroll
    for (int k = 0; k < 14; ++k) {
        int j = 2*o + k - 12;
        j = (j < 0) ? -j : ((j >= FN) ? (2*FN - 2 - j) : j);
        float v = base[(size_t)j*WD + w];
        l += v * cH0A[k];
        h += v * cH1A[k];
    }
    float a  = prelu[0];
    float ig = 1.f/gama[0];
    float bv = bwLo[i];
    float t  = l + bv - ig;
    float wv = (t >= 0.f) ? t : a*t;
    wLo[i]  = wv;
    bwLo[i] = bv + l - wv;
    bv = bwHi[i];
    t  = h + bv - ig;
    wv = (t >= 0.f) ? t : a*t;
    wHi[i]  = wv;
    bwHi[i] = bv + h - wv;
}

// ---------------- IDWT column synthesis (both halves, one launch) ----------
__global__ void k_sfb_h2()
{
    int half = NB*FN*WD;
    int i = blockIdx.x*blockDim.x + threadIdx.x;
    if (i >= 2*half) return;
    const float *lA, *lB, *hA, *hB;
    float* out;
    int ii = i;
    if (i < half) {
        lA = g_WL;  lB = g_BWL;
        hA = g_WH;  hB = g_BWH;
        out = g_LOS;
    } else {
        ii -= half;
        lA = g_WH + (size_t)SLL;    lB = g_BWH + (size_t)SLL;
        hA = g_WH + (size_t)2*SLL;  hB = g_BWH + (size_t)2*SLL;
        out = g_HIS;
    }
    int w = ii % WD;
    int o = (ii / WD) % FN;
    int b = ii / (FN*WD);
    size_t bb = (size_t)b*WD*WD;
    float acc = 0.f;
    int k0 = (o + 1) & 1;
#pragma unroll
    for (int kk = 0; kk < 7; ++kk) {
        int k = k0 + 2*kk;
        int m = (o + k - 1) >> 1;
        size_t idx = bb + (size_t)m*WD + w;
        float lo = lA[idx] - lB[idx];
        float hi = hA[idx] - hB[idx];
        acc += lo * cG0[k] + hi * cG1[k];
    }
    out[ii] = acc;
}

// ---------------- host orchestration ----------------
static inline int eb(int n) { return (n + 255) / 256; }

extern "C" void kernel_launch(void* const* d_in, const int* in_sizes, int n_in,
                              void* d_out, int out_size)
{
    const float* u_in   = (const float*)d_in[0];
    const float* uvMask = (const float*)d_in[1];
    const float* f_real = (const float*)d_in[3];
    const float* f_imag = (const float*)d_in[4];
    const float* lam    = (const float*)d_in[5];
    const float* gama   = (const float*)d_in[6];
    const float* mmu    = (const float*)d_in[7];
    const float* prelu  = (const float*)d_in[8];
    float* out = (float*)d_out;

    void *pCA, *pCB, *pU, *pMASKT, *pF0T, *pG;
    void *pDX, *pDY, *pBX, *pBY;
    void *pWL, *pBWL, *pWH, *pBWH;
    void *pLOT, *pHIT;
    cudaGetSymbolAddress(&pCA, g_CA);       cudaGetSymbolAddress(&pCB, g_CB);
    cudaGetSymbolAddress(&pU, g_U);         cudaGetSymbolAddress(&pG, g_G);
    cudaGetSymbolAddress(&pMASKT, g_MASKT); cudaGetSymbolAddress(&pF0T, g_F0T);
    cudaGetSymbolAddress(&pDX, g_DX);       cudaGetSymbolAddress(&pDY, g_DY);
    cudaGetSymbolAddress(&pBX, g_BX);       cudaGetSymbolAddress(&pBY, g_BY);
    cudaGetSymbolAddress(&pWL, g_WL);       cudaGetSymbolAddress(&pBWL, g_BWL);
    cudaGetSymbolAddress(&pWH, g_WH);       cudaGetSymbolAddress(&pBWH, g_BWH);
    cudaGetSymbolAddress(&pLOT, g_LOT);     cudaGetSymbolAddress(&pHIT, g_HIT);

    dim3 tb(32, 8), tg(32, 32, NB);
    const int FFTG = NB*FN;
    const int FFTG2 = NB*FN/2;

    // ----- init -----
    k_twinit<<<4, 256>>>();
    k_transpose_r<<<tg, tb>>>(uvMask, (float*)pMASKT);
    k_make_f0T<<<tg, tb>>>(f_real, f_imag, (float2*)pF0T);
    cudaMemsetAsync(pDX, 0, (size_t)TOT*4, 0);
    cudaMemsetAsync(pDY, 0, (size_t)TOT*4, 0);
    cudaMemsetAsync(pBX, 0, (size_t)TOT*4, 0);
    cudaMemsetAsync(pBY, 0, (size_t)TOT*4, 0);
    cudaMemsetAsync(pBWL, 0, (size_t)SLL*4, 0);
    cudaMemsetAsync(pBWH, 0, (size_t)(3*SLL)*4, 0);

    // dwt2(u_in) -> WL, WH
    k_afb_w<<<NB*FN, 256>>>(u_in, (float*)pLOT, (float*)pHIT);
    k_afb_h<<<eb(SLL), 256>>>((float*)pLOT, (float*)pWL, (float*)pWH);
    k_afb_h<<<eb(SLL), 256>>>((float*)pHIT, (float*)pWH + (size_t)SLL,
                              (float*)pWH + (size_t)2*SLL);

    // ----- iterations -----
    for (int it = 0; it < 2; ++it) {
        k_sfb_h2<<<eb(2*NB*FN*WD), 256>>>();

        // rhs (real 2-for-1 forward)
        k_fwd2<4><<<FFTG2, 256>>>(nullptr, (float2*)pCB, lam, gama);
        k_transpose_c<<<tg, tb>>>((float2*)pCB, (float2*)pCA);          // [p][y]
        if (it == 0)
            k_fftsolve<1><<<FFTG, 256>>>((float2*)pCA, (float2*)pCB, 1.f/FN,
                                         mmu, lam, gama);
        else
            k_fftsolve<0><<<FFTG, 256>>>((float2*)pCA, (float2*)pCB, 1.f/FN,
                                         mmu, lam, gama);
        k_transpose_c<<<tg, tb>>>((float2*)pCB, (float2*)pCA);          // [y][p]
        float* udst = (it == 0) ? (float*)pU : out;
        k_inv2r<<<FFTG2, 256>>>((float2*)pCA, udst, 1.f/FN, prelu);

        if (it == 0) {
            k_shrinkbxy<<<eb(TOT), 256>>>(lam, prelu);
            k_afb_w<<<NB*FN, 256>>>((float*)pU, (float*)pLOT, (float*)pHIT);
            k_afb_h_w<<<eb(SLL), 256>>>((float*)pLOT,
                                        (float*)pBWL, (float*)pWL,
                                        (float*)pBWH, (float*)pWH, gama, prelu);
            k_afb_h_w<<<eb(SLL), 256>>>((float*)pHIT,
                                        (float*)pBWH + (size_t)SLL,
                                        (float*)pWH + (size_t)SLL,
                                        (float*)pBWH + (size_t)2*SLL,
                                        (float*)pWH + (size_t)2*SLL, gama, prelu);
            // G' = maskT*(2*F0T - maskT*FU)
            k_fwd2<0><<<FFTG2, 256>>>((float*)pU, (float2*)pCA, lam, gama);
            k_transpose_c<<<tg, tb>>>((float2*)pCA, (float2*)pCB);      // [p][y]
            k_fft4<0><<<FFTG, 256>>>((float2*)pCB, (float2*)pG, 1.f, 2);
        }
    }
    (void)in_sizes; (void)n_in; (void)out_size;
}

// round 14
// speedup vs baseline: 2.5158x; 1.0203x over previous
#include <cuda_runtime.h>
#include <math.h>

#define FN   1024
#define NB   4
#define FNN  (FN*FN)
#define TOT  (NB*FNN)
#define WD   518
#define SLL  (NB*WD*WD)
#define SLW  (NB*FN*WD)
#define PIF  3.14159265358979323846f

#define DP(i) ((i) + ((i)>>2))
#define TP(i) ((i) + ((i)>>4))

// ---------------- static device scratch ----------------
__device__ float2 g_CA[TOT];
__device__ float2 g_CB[TOT];
__device__ float2 g_F0T[TOT];
__device__ float2 g_G[TOT];
__device__ float2 g_TW[FN];
__device__ float4 g_TRIG[FN];

__device__ float g_U[TOT];
__device__ float g_DX[TOT];
__device__ float g_DY[TOT];
__device__ float g_BX[TOT];
__device__ float g_BY[TOT];
__device__ float g_MASKT[TOT];

__device__ float g_WL[SLL];
__device__ float g_BWL[SLL];
__device__ float g_WH[3*SLL];
__device__ float g_BWH[3*SLL];
__device__ float g_LOT[SLW];
__device__ float g_HIT[SLW];
__device__ float g_LOS[SLW];
__device__ float g_HIS[SLW];

// ---------------- wavelet filters (db7, L=14) ----------------
__constant__ float cH0A[14] = {
    0.010268176708511255f, 0.004010244871533663f, -0.10780823770381774f,
   -0.14004724044296152f, 0.2886296317515146f, 0.767764317003164f,
    0.5361019170917628f, 0.017441255086855827f, -0.049552834937127255f,
    0.0678926935013727f, 0.03051551316596357f, -0.01263630340325193f,
   -0.0010473848886829163f, 0.002681814568257878f };
__constant__ float cH1A[14] = {
    0.002681814568257878f, 0.0010473848886829163f, -0.01263630340325193f,
   -0.03051551316596357f, 0.0678926935013727f, 0.049552834937127255f,
    0.017441255086855827f, -0.5361019170917628f, 0.767764317003164f,
   -0.2886296317515146f, -0.14004724044296152f, 0.10780823770381774f,
    0.004010244871533663f, -0.010268176708511255f };
__constant__ float cG0[14] = {
    0.002681814568257878f, -0.0010473848886829163f, -0.01263630340325193f,
    0.03051551316596357f, 0.0678926935013727f, -0.049552834937127255f,
    0.017441255086855827f, 0.5361019170917628f, 0.767764317003164f,
    0.2886296317515146f, -0.14004724044296152f, -0.10780823770381774f,
    0.004010244871533663f, 0.010268176708511255f };
__constant__ float cG1[14] = {
   -0.010268176708511255f, 0.004010244871533663f, 0.10780823770381774f,
   -0.14004724044296152f, -0.2886296317515146f, 0.767764317003164f,
   -0.5361019170917628f, 0.017441255086855827f, 0.049552834937127255f,
    0.0678926935013727f, -0.03051551316596357f, -0.01263630340325193f,
    0.0010473848886829163f, 0.002681814568257878f };

__device__ __forceinline__ float2 cmulf(float2 a, float2 b) {
    return make_float2(a.x*b.x - a.y*b.y, a.x*b.y + a.y*b.x);
}

__global__ void k_twinit()
{
    int j = blockIdx.x*blockDim.x + threadIdx.x;
    if (j >= FN) return;
    float th = 2.f*PIF*(float)j/(float)FN;
    float sv, cv; sincosf(-th, &sv, &cv);
    g_TW[j] = make_float2(cv, sv);
    float s1, c1, s2, c2;
    sincosf(th, &s1, &c1);
    sincosf(2.f*th, &s2, &c2);
    g_TRIG[j] = make_float4(c1, s1, c2, s2);
}

template<int INV>
__device__ __forceinline__ void r4stage(const float2* __restrict__ X,
                                        float2* __restrict__ Y,
                                        const float2* __restrict__ tw,
                                        int t, int s)
{
    int ns = 1 << (2*s);
    int k  = t & (ns - 1);
    int j  = ((t - k) << 2) + k;
    int sh = 8 - 2*s;
    float2 c0 = X[DP(t)], c1 = X[DP(t+256)], c2 = X[DP(t+512)], c3 = X[DP(t+768)];
    float2 w1 = tw[TP(k << sh)];
    float2 w2 = tw[TP((2*k) << sh)];
    float2 w3 = tw[TP((3*k) << sh)];
    if (INV) { w1.y = -w1.y; w2.y = -w2.y; w3.y = -w3.y; }
    c1 = cmulf(c1, w1); c2 = cmulf(c2, w2); c3 = cmulf(c3, w3);
    float2 t0 = make_float2(c0.x+c2.x, c0.y+c2.y);
    float2 t1 = make_float2(c0.x-c2.x, c0.y-c2.y);
    float2 t2 = make_float2(c1.x+c3.x, c1.y+c3.y);
    float2 dd = make_float2(c1.x-c3.x, c1.y-c3.y);
    float2 t3 = INV ? make_float2(-dd.y, dd.x) : make_float2(dd.y, -dd.x);
    Y[DP(j)]      = make_float2(t0.x+t2.x, t0.y+t2.y);
    Y[DP(j+ns)]   = make_float2(t1.x+t3.x, t1.y+t3.y);
    Y[DP(j+2*ns)] = make_float2(t0.x-t2.x, t0.y-t2.y);
    Y[DP(j+3*ns)] = make_float2(t1.x-t3.x, t1.y-t3.y);
}

// rhs value for (row base, x, y)
__device__ __forceinline__ float rhs_val(size_t base, int x, int y,
                                         float lv, float gv,
                                         const float* __restrict__ lrow,
                                         const float* __restrict__ hrow)
{
    size_t i = base + x;
    float dxt = 0.f;
    if (x >= 1) {
        int xn = (x == FN-1) ? 1 : x+1;
        dxt = (g_DX[i] - g_BX[i]) - (g_DX[base+xn] - g_BX[base+xn]);
    }
    float dyt = 0.f;
    if (y >= 1) {
        int yn = (y == FN-1) ? 1 : y+1;
        size_t jj = i + (size_t)(yn - y)*FN;
        dyt = (g_DY[i] - g_BY[i]) - (g_DY[jj] - g_BY[jj]);
    }
    float idwt = 0.f;
    int k0 = (x + 1) & 1;
#pragma unroll
    for (int kk = 0; kk < 7; ++kk) {
        int k = k0 + 2*kk;
        int mm = (x + k - 1) >> 1;
        idwt += lrow[mm] * cG0[k] + hrow[mm] * cG1[k];
    }
    return lv*(dxt + dyt) + gv*idwt;
}

// ---- forward 2-for-1: two REAL rows per block -> two full spectra
// PRE: 0 = load real rows; 4 = rhs inline
template<int PRE>
__global__ __launch_bounds__(256) void k_fwd2(const float* __restrict__ srcv,
                                              float2* __restrict__ dst,
                                              const float* __restrict__ lam,
                                              const float* __restrict__ gama)
{
    __shared__ float2 sA[1280];
    __shared__ float2 sB[1280];
    __shared__ float2 tw[1088];
    int t = threadIdx.x;
    int r0 = 2*blockIdx.x;
    size_t base0 = (size_t)r0*FN;
    size_t base1 = base0 + FN;
    for (int j = t; j < FN; j += 256) tw[TP(j)] = g_TW[j];
    if (PRE == 0) {
        const float* s0 = srcv + base0;
        const float* s1 = srcv + base1;
#pragma unroll
        for (int m = 0; m < 4; ++m) {
            int x = t + 256*m;
            sA[DP(x)] = make_float2(s0[x], s1[x]);
        }
    } else {
        int y0 = r0 & (FN-1);
        float lv = lam[0], gv = gama[0];
        const float* l0 = g_LOS + (size_t)r0*WD;
        const float* h0 = g_HIS + (size_t)r0*WD;
        const float* l1 = l0 + WD;
        const float* h1 = h0 + WD;
#pragma unroll
        for (int m = 0; m < 4; ++m) {
            int x = t + 256*m;
            float a = rhs_val(base0, x, y0,     lv, gv, l0, h0);
            float b = rhs_val(base1, x, y0 + 1, lv, gv, l1, h1);
            sA[DP(x)] = make_float2(a, b);
        }
    }
    __syncthreads();
    float2* X = sA; float2* Y = sB;
#pragma unroll
    for (int s = 0; s < 5; ++s) {
        r4stage<0>(X, Y, tw, t, s);
        __syncthreads();
        float2* tmp = X; X = Y; Y = tmp;
    }
    float2* d0 = dst + base0;
    float2* d1 = dst + base1;
#pragma unroll
    for (int m = 0; m < 4; ++m) {
        int k  = t + 256*m;
        int kk = (FN - k) & (FN-1);
        float2 Zk = X[DP(k)];
        float2 Zm = X[DP(kk)];
        d0[k] = make_float2(0.5f*(Zk.x + Zm.x), 0.5f*(Zk.y - Zm.y));
        d1[k] = make_float2(0.5f*(Zk.y + Zm.y), 0.5f*(Zm.x - Zk.x));
    }
}

// ---- inverse 2-for-1 w/ symmetrization -> real rows + srelu (it=1 path) ----
__global__ __launch_bounds__(256) void k_inv2r(const float2* __restrict__ src,
                                               float* __restrict__ dst,
                                               float scale,
                                               const float* __restrict__ prelu)
{
    __shared__ float2 sA[1280];
    __shared__ float2 sB[1280];
    __shared__ float2 tw[1088];
    int t = threadIdx.x;
    int r0 = 2*blockIdx.x;
    size_t base0 = (size_t)r0*FN;
    size_t base1 = base0 + FN;
    for (int j = t; j < FN; j += 256) tw[TP(j)] = g_TW[j];
    const float2* s0 = src + base0;
    const float2* s1 = src + base1;
#pragma unroll
    for (int m = 0; m < 4; ++m) {
        int x = t + 256*m;
        int xr = (FN - x) & (FN-1);
        float2 a  = s0[x],  b  = s1[x];
        float2 ar = s0[xr], br = s1[xr];
        sA[DP(x)] = make_float2(0.5f*(a.x + ar.x - b.y + br.y),
                                0.5f*(a.y - ar.y + b.x + br.x));
    }
    __syncthreads();
    float2* X = sA; float2* Y = sB;
#pragma unroll
    for (int s = 0; s < 5; ++s) {
        r4stage<1>(X, Y, tw, t, s);
        __syncthreads();
        float2* tmp = X; X = Y; Y = tmp;
    }
    float a = prelu[0];
    float* d0 = dst + base0;
    float* d1 = dst + base1;
#pragma unroll
    for (int m = 0; m < 4; ++m) {
        int x = t + 256*m;
        float2 z = X[DP(x)];
        float v0 = z.x*scale;
        float v1 = z.y*scale;
        d0[x] = (v0 >= 0.f) ? v0 : a*v0;
        d1[x] = (v1 >= 0.f) ? v1 : a*v1;
    }
}

// ---- it0 mega-kernel: inv FFT -> srelu -> store u -> row-DWT -> fwd FFT -> spectra
__global__ __launch_bounds__(256) void k_invfwd(const float2* __restrict__ src,
                                                float2* __restrict__ dstspec,
                                                float* __restrict__ uout,
                                                float* __restrict__ lo,
                                                float* __restrict__ hi,
                                                float scale,
                                                const float* __restrict__ prelu)
{
    __shared__ float2 sA[1280];
    __shared__ float2 sB[1280];
    __shared__ float2 tw[1088];
    int t = threadIdx.x;
    int r0 = 2*blockIdx.x;
    size_t base0 = (size_t)r0*FN;
    size_t base1 = base0 + FN;
    for (int j = t; j < FN; j += 256) tw[TP(j)] = g_TW[j];
    const float2* s0 = src + base0;
    const float2* s1 = src + base1;
#pragma unroll
    for (int m = 0; m < 4; ++m) {
        int x = t + 256*m;
        int xr = (FN - x) & (FN-1);
        float2 a  = s0[x],  b  = s1[x];
        float2 ar = s0[xr], br = s1[xr];
        sA[DP(x)] = make_float2(0.5f*(a.x + ar.x - b.y + br.y),
                                0.5f*(a.y - ar.y + b.x + br.x));
    }
    __syncthreads();
    float2* X = sA; float2* Y = sB;
#pragma unroll
    for (int s = 0; s < 5; ++s) {
        r4stage<1>(X, Y, tw, t, s);
        __syncthreads();
        float2* tmp = X; X = Y; Y = tmp;
    }
    // srelu in place + store u
    {
        float a = prelu[0];
        float* d0 = uout + base0;
        float* d1 = uout + base1;
#pragma unroll
        for (int m = 0; m < 4; ++m) {
            int x = t + 256*m;
            float2 z = X[DP(x)];
            float v0 = z.x*scale;
            float v1 = z.y*scale;
            v0 = (v0 >= 0.f) ? v0 : a*v0;
            v1 = (v1 >= 0.f) ? v1 : a*v1;
            d0[x] = v0;
            d1[x] = v1;
            X[DP(x)] = make_float2(v0, v1);
        }
    }
    __syncthreads();
    // row DWT for both rows from smem
    {
        size_t ob0 = (size_t)r0*WD;
        size_t ob1 = ob0 + WD;
        for (int o = t; o < WD; o += 256) {
            float l0 = 0.f, h0 = 0.f, l1 = 0.f, h1 = 0.f;
            if (o >= 6 && o <= 505) {
                int j0 = 2*o - 12;
#pragma unroll
                for (int k = 0; k < 14; ++k) {
                    float2 v = X[DP(j0 + k)];
                    l0 += v.x * cH0A[k];  h0 += v.x * cH1A[k];
                    l1 += v.y * cH0A[k];  h1 += v.y * cH1A[k];
                }
            } else {
#pragma unroll
                for (int k = 0; k < 14; ++k) {
                    int j = 2*o + k - 12;
                    j = (j < 0) ? -j : ((j >= FN) ? (2*FN - 2 - j) : j);
                    float2 v = X[DP(j)];
                    l0 += v.x * cH0A[k];  h0 += v.x * cH1A[k];
                    l1 += v.y * cH0A[k];  h1 += v.y * cH1A[k];
                }
            }
            lo[ob0 + o] = l0;  hi[ob0 + o] = h0;
            lo[ob1 + o] = l1;  hi[ob1 + o] = h1;
        }
    }
    __syncthreads();
    // forward FFT on packed srelu'd rows
#pragma unroll
    for (int s = 0; s < 5; ++s) {
        r4stage<0>(X, Y, tw, t, s);
        __syncthreads();
        float2* tmp = X; X = Y; Y = tmp;
    }
    float2* d0 = dstspec + base0;
    float2* d1 = dstspec + base1;
#pragma unroll
    for (int m = 0; m < 4; ++m) {
        int k  = t + 256*m;
        int kk = (FN - k) & (FN-1);
        float2 Zk = X[DP(k)];
        float2 Zm = X[DP(kk)];
        d0[k] = make_float2(0.5f*(Zk.x + Zm.x), 0.5f*(Zk.y - Zm.y));
        d1[k] = make_float2(0.5f*(Zk.y + Zm.y), 0.5f*(Zm.x - Zk.x));
    }
}

// ---- complex-in FFT, postOp 2 = store G' ----
template<int INV>
__global__ __launch_bounds__(256) void k_fft4(const float2* __restrict__ src,
                                              float2* __restrict__ dst,
                                              float scale, int postOp)
{
    __shared__ float2 sA[1280];
    __shared__ float2 sB[1280];
    __shared__ float2 tw[1088];
    int t = threadIdx.x;
    size_t base = (size_t)blockIdx.x*FN;
    for (int j = t; j < FN; j += 256) tw[TP(j)] = g_TW[j];
    const float2* s = src + base;
#pragma unroll
    for (int m = 0; m < 4; ++m) sA[DP(t+256*m)] = s[t+256*m];
    __syncthreads();
    float2* X = sA; float2* Y = sB;
#pragma unroll
    for (int st = 0; st < 5; ++st) {
        r4stage<INV>(X, Y, tw, t, st);
        __syncthreads();
        float2* tmp = X; X = Y; Y = tmp;
    }
    float2* d = dst + base;
#pragma unroll
    for (int m = 0; m < 4; ++m) {
        int idx = t + 256*m;
        float2 v = X[DP(idx)];
        v.x *= scale; v.y *= scale;
        if (postOp == 2) {
            float mk = g_MASKT[base + idx];
            float2 f0 = g_F0T[base + idx];
            v = make_float2(mk*(2.f*f0.x - mk*v.x), mk*(2.f*f0.y - mk*v.y));
        }
        d[idx] = v;
    }
}

// fused fwd FFT -> (v += mmu*G ; v /= UKER inline) -> inv FFT
template<int IT0>
__global__ __launch_bounds__(256) void k_fftsolve(const float2* __restrict__ src,
                                                  float2* __restrict__ dst,
                                                  float scale,
                                                  const float* __restrict__ mmu,
                                                  const float* __restrict__ lam,
                                                  const float* __restrict__ gama)
{
    __shared__ float2 sA[1280];
    __shared__ float2 sB[1280];
    __shared__ float2 tw[1088];
    int t = threadIdx.x;
    size_t base = (size_t)blockIdx.x*FN;
    int p = blockIdx.x & (FN-1);
    for (int j = t; j < FN; j += 256) tw[TP(j)] = g_TW[j];
    const float2* s = src + base;
#pragma unroll
    for (int m = 0; m < 4; ++m) sA[DP(t+256*m)] = s[t+256*m];
    __syncthreads();
    float2* X = sA; float2* Y = sB;
#pragma unroll
    for (int st = 0; st < 5; ++st) {
        r4stage<0>(X, Y, tw, t, st);
        __syncthreads();
        float2* tmp = X; X = Y; Y = tmp;
    }
    float mv = mmu[0], lv = lam[0], gv = gama[0];
    float4 tp = g_TRIG[p];
#pragma unroll
    for (int m = 0; m < 4; ++m) {
        int q = t + 256*m;
        size_t i = base + q;
        float2 v = X[DP(q)];
        float mk = g_MASKT[i];
        float2 g;
        if (IT0) { float2 f0 = g_F0T[i]; g = make_float2(mk*f0.x, mk*f0.y); }
        else      g = g_G[i];
        v.x += mv*g.x;  v.y += mv*g.y;
        float4 tq = g_TRIG[q];
        float Br = 4.f - tp.x - tq.x - tp.z - tq.z;
        float Bi = tp.y + tq.y - tp.w - tq.w;
        float cf = tp.x*tq.x - tp.y*tq.y;
        float sf = tp.y*tq.x + tp.x*tq.y;
        float2 w = make_float2(mv*mk*mk + gv + lv*(Br*cf + Bi*sf),
                               lv*(Bi*cf - Br*sf));
        float d = 1.f/(w.x*w.x + w.y*w.y);
        X[DP(q)] = make_float2((v.x*w.x + v.y*w.y)*d, (v.y*w.x - v.x*w.y)*d);
    }
    __syncthreads();
#pragma unroll
    for (int st = 0; st < 5; ++st) {
        r4stage<1>(X, Y, tw, t, st);
        __syncthreads();
        float2* tmp = X; X = Y; Y = tmp;
    }
    float2* d = dst + base;
#pragma unroll
    for (int m = 0; m < 4; ++m) {
        float2 v = X[DP(t+256*m)];
        d[t+256*m] = make_float2(v.x*scale, v.y*scale);
    }
}

// ---------------- transposes ----------------
__global__ void k_transpose_c(const float2* __restrict__ src, float2* __restrict__ dst)
{
    __shared__ float2 tile[32][33];
    int b = blockIdx.z;
    const float2* s = src + (size_t)b*FNN;
    float2* d = dst + (size_t)b*FNN;
    int x  = blockIdx.x*32 + threadIdx.x;
    int y0 = blockIdx.y*32 + threadIdx.y;
#pragma unroll
    for (int i = 0; i < 32; i += 8)
        tile[threadIdx.y+i][threadIdx.x] = s[(size_t)(y0+i)*FN + x];
    __syncthreads();
    int x2 = blockIdx.y*32 + threadIdx.x;
    int y2 = blockIdx.x*32 + threadIdx.y;
#pragma unroll
    for (int i = 0; i < 32; i += 8)
        d[(size_t)(y2+i)*FN + x2] = tile[threadIdx.x][threadIdx.y+i];
}

__global__ void k_transpose_r(const float* __restrict__ src, float* __restrict__ dst)
{
    __shared__ float tile[32][33];
    int b = blockIdx.z;
    const float* s = src + (size_t)b*FNN;
    float* d = dst + (size_t)b*FNN;
    int x  = blockIdx.x*32 + threadIdx.x;
    int y0 = blockIdx.y*32 + threadIdx.y;
#pragma unroll
    for (int i = 0; i < 32; i += 8)
        tile[threadIdx.y+i][threadIdx.x] = s[(size_t)(y0+i)*FN + x];
    __syncthreads();
    int x2 = blockIdx.y*32 + threadIdx.x;
    int y2 = blockIdx.x*32 + threadIdx.y;
#pragma unroll
    for (int i = 0; i < 32; i += 8)
        d[(size_t)(y2+i)*FN + x2] = tile[threadIdx.x][threadIdx.y+i];
}

__global__ void k_make_f0T(const float* __restrict__ fr, const float* __restrict__ fi,
                           float2* __restrict__ dst)
{
    __shared__ float tr[32][33];
    __shared__ float ti[32][33];
    int b = blockIdx.z;
    const float* sr = fr + (size_t)b*FNN;
    const float* si = fi + (size_t)b*FNN;
    float2* d = dst + (size_t)b*FNN;
    int x  = blockIdx.x*32 + threadIdx.x;
    int y0 = blockIdx.y*32 + threadIdx.y;
#pragma unroll
    for (int i = 0; i < 32; i += 8) {
        tr[threadIdx.y+i][threadIdx.x] = sr[(size_t)(y0+i)*FN + x];
        ti[threadIdx.y+i][threadIdx.x] = si[(size_t)(y0+i)*FN + x];
    }
    __syncthreads();
    int x2 = blockIdx.y*32 + threadIdx.x;
    int y2 = blockIdx.x*32 + threadIdx.y;
#pragma unroll
    for (int i = 0; i < 32; i += 8)
        d[(size_t)(y2+i)*FN + x2] =
            make_float2(tr[threadIdx.x][threadIdx.y+i], ti[threadIdx.x][threadIdx.y+i]);
}

// ---------------- fused shrink + b-update ----------------
__global__ void k_shrinkbxy(const float* __restrict__ lam,
                            const float* __restrict__ prelu)
{
    int i = blockIdx.x*blockDim.x + threadIdx.x;
    if (i >= TOT) return;
    float a  = prelu[0];
    float il = 1.f/lam[0];
    float dx = g_DX[i], dy = g_DY[i], bx = g_BX[i], by = g_BY[i];
    float vx = dx + bx;
    float vy = dy + by;
    float s = sqrtf(vx*vx + vy*vy);
    float nx = vx - s*il;
    float ny = vy - s*il;
    nx = (nx >= 0.f) ? nx : a*nx;
    ny = (ny >= 0.f) ? ny : a*ny;
    int x = i & (FN-1);
    int y = (i >> 10) & (FN-1);
    int rowb = i - x;
    float dxu = 0.f;
    if (x >= 1) {
        int xm = (x == 1) ? FN-1 : x-1;
        dxu = g_U[i] - g_U[rowb + xm];
    }
    float dyu = 0.f;
    if (y >= 1) {
        int ym = (y == 1) ? FN-1 : y-1;
        dyu = g_U[i] - g_U[i + (ym - y)*FN];
    }
    g_DX[i] = nx;  g_DY[i] = ny;
    g_BX[i] = bx + dxu - nx;
    g_BY[i] = by + dyu - ny;
}

// ---------------- DWT row analysis (smem tiled, fast interior path) ----------
__global__ __launch_bounds__(256) void k_afb_w(const float* __restrict__ src,
                                               float* __restrict__ lo,
                                               float* __restrict__ hi)
{
    __shared__ float rs[FN];
    int t = threadIdx.x;
    int r = blockIdx.x;
    const float* row = src + (size_t)r*FN;
#pragma unroll
    for (int m = 0; m < 4; ++m) rs[t+256*m] = row[t+256*m];
    __syncthreads();
    size_t ob = (size_t)r*WD;
    for (int o = t; o < WD; o += 256) {
        float l = 0.f, h = 0.f;
        if (o >= 6 && o <= 505) {
            int j0 = 2*o - 12;
#pragma unroll
            for (int k = 0; k < 14; ++k) {
                float v = rs[j0 + k];
                l += v * cH0A[k];
                h += v * cH1A[k];
            }
        } else {
#pragma unroll
            for (int k = 0; k < 14; ++k) {
                int j = 2*o + k - 12;
                j = (j < 0) ? -j : ((j >= FN) ? (2*FN - 2 - j) : j);
                float v = rs[j];
                l += v * cH0A[k];
                h += v * cH1A[k];
            }
        }
        lo[ob + o] = l;
        hi[ob + o] = h;
    }
}

// column DWT for init: both halves (LOT->WL/WH0, HIT->WH1/WH2) in one launch
__global__ void k_afb_h2()
{
    int i = blockIdx.x*blockDim.x + threadIdx.x;
    if (i >= 2*SLL) return;
    const float* src;
    float *lo, *hi;
    int ii = i;
    if (i < SLL) {
        src = g_LOT; lo = g_WL; hi = g_WH;
    } else {
        ii -= SLL;
        src = g_HIT; lo = g_WH + (size_t)SLL; hi = g_WH + (size_t)2*SLL;
    }
    int w = ii % WD;
    int o = (ii / WD) % WD;
    int b = ii / (WD*WD);
    const float* base = src + (size_t)b*FN*WD;
    float l = 0.f, h = 0.f;
    if (o >= 6 && o <= 505) {
        const float* pp = base + (size_t)(2*o - 12)*WD + w;
#pragma unroll
        for (int k = 0; k < 14; ++k) {
            float v = pp[(size_t)k*WD];
            l += v * cH0A[k];
            h += v * cH1A[k];
        }
    } else {
#pragma unroll
        for (int k = 0; k < 14; ++k) {
            int j = 2*o + k - 12;
            j = (j < 0) ? -j : ((j >= FN) ? (2*FN - 2 - j) : j);
            float v = base[(size_t)j*WD + w];
            l += v * cH0A[k];
            h += v * cH1A[k];
        }
    }
    lo[ii] = l;
    hi[ii] = h;
}

// column DWT + w/b update: both halves in one launch
__global__ void k_afb_h_w2(const float* __restrict__ gama,
                           const float* __restrict__ prelu)
{
    int i = blockIdx.x*blockDim.x + threadIdx.x;
    if (i >= 2*SLL) return;
    const float* src;
    float *bwLo, *wLo, *bwHi, *wHi;
    int ii = i;
    if (i < SLL) {
        src = g_LOT;
        bwLo = g_BWL; wLo = g_WL;
        bwHi = g_BWH; wHi = g_WH;
    } else {
        ii -= SLL;
        src = g_HIT;
        bwLo = g_BWH + (size_t)SLL;   wLo = g_WH + (size_t)SLL;
        bwHi = g_BWH + (size_t)2*SLL; wHi = g_WH + (size_t)2*SLL;
    }
    int w = ii % WD;
    int o = (ii / WD) % WD;
    int b = ii / (WD*WD);
    const float* base = src + (size_t)b*FN*WD;
    float l = 0.f, h = 0.f;
    if (o >= 6 && o <= 505) {
        const float* pp = base + (size_t)(2*o - 12)*WD + w;
#pragma unroll
        for (int k = 0; k < 14; ++k) {
            float v = pp[(size_t)k*WD];
            l += v * cH0A[k];
            h += v * cH1A[k];
        }
    } else {
#pragma unroll
        for (int k = 0; k < 14; ++k) {
            int j = 2*o + k - 12;
            j = (j < 0) ? -j : ((j >= FN) ? (2*FN - 2 - j) : j);
            float v = base[(size_t)j*WD + w];
            l += v * cH0A[k];
            h += v * cH1A[k];
        }
    }
    float a  = prelu[0];
    float ig = 1.f/gama[0];
    float bv = bwLo[ii];
    float t  = l + bv - ig;
    float wv = (t >= 0.f) ? t : a*t;
    wLo[ii]  = wv;
    bwLo[ii] = bv + l - wv;
    bv = bwHi[ii];
    t  = h + bv - ig;
    wv = (t >= 0.f) ? t : a*t;
    wHi[ii]  = wv;
    bwHi[ii] = bv + h - wv;
}

// ---------------- IDWT column synthesis (both halves, one launch) ----------
__global__ void k_sfb_h2()
{
    int half = NB*FN*WD;
    int i = blockIdx.x*blockDim.x + threadIdx.x;
    if (i >= 2*half) return;
    const float *lA, *lB, *hA, *hB;
    float* out;
    int ii = i;
    if (i < half) {
        lA = g_WL;  lB = g_BWL;
        hA = g_WH;  hB = g_BWH;
        out = g_LOS;
    } else {
        ii -= half;
        lA = g_WH + (size_t)SLL;    lB = g_BWH + (size_t)SLL;
        hA = g_WH + (size_t)2*SLL;  hB = g_BWH + (size_t)2*SLL;
        out = g_HIS;
    }
    int w = ii % WD;
    int o = (ii / WD) % FN;
    int b = ii / (FN*WD);
    size_t bb = (size_t)b*WD*WD;
    float acc = 0.f;
    int k0 = (o + 1) & 1;
#pragma unroll
    for (int kk = 0; kk < 7; ++kk) {
        int k = k0 + 2*kk;
        int m = (o + k - 1) >> 1;
        size_t idx = bb + (size_t)m*WD + w;
        float lo = lA[idx] - lB[idx];
        float hi = hA[idx] - hB[idx];
        acc += lo * cG0[k] + hi * cG1[k];
    }
    out[ii] = acc;
}

// ---------------- host orchestration ----------------
static inline int eb(int n) { return (n + 255) / 256; }

extern "C" void kernel_launch(void* const* d_in, const int* in_sizes, int n_in,
                              void* d_out, int out_size)
{
    const float* u_in   = (const float*)d_in[0];
    const float* uvMask = (const float*)d_in[1];
    const float* f_real = (const float*)d_in[3];
    const float* f_imag = (const float*)d_in[4];
    const float* lam    = (const float*)d_in[5];
    const float* gama   = (const float*)d_in[6];
    const float* mmu    = (const float*)d_in[7];
    const float* prelu  = (const float*)d_in[8];
    float* out = (float*)d_out;

    void *pCA, *pCB, *pU, *pMASKT, *pF0T, *pG;
    void *pDX, *pDY, *pBX, *pBY;
    void *pBWL, *pBWH;
    void *pLOT, *pHIT;
    cudaGetSymbolAddress(&pCA, g_CA);       cudaGetSymbolAddress(&pCB, g_CB);
    cudaGetSymbolAddress(&pU, g_U);         cudaGetSymbolAddress(&pG, g_G);
    cudaGetSymbolAddress(&pMASKT, g_MASKT); cudaGetSymbolAddress(&pF0T, g_F0T);
    cudaGetSymbolAddress(&pDX, g_DX);       cudaGetSymbolAddress(&pDY, g_DY);
    cudaGetSymbolAddress(&pBX, g_BX);       cudaGetSymbolAddress(&pBY, g_BY);
    cudaGetSymbolAddress(&pBWL, g_BWL);     cudaGetSymbolAddress(&pBWH, g_BWH);
    cudaGetSymbolAddress(&pLOT, g_LOT);     cudaGetSymbolAddress(&pHIT, g_HIT);

    dim3 tb(32, 8), tg(32, 32, NB);
    const int FFTG = NB*FN;
    const int FFTG2 = NB*FN/2;

    // ----- init -----
    k_twinit<<<4, 256>>>();
    k_transpose_r<<<tg, tb>>>(uvMask, (float*)pMASKT);
    k_make_f0T<<<tg, tb>>>(f_real, f_imag, (float2*)pF0T);
    cudaMemsetAsync(pDX, 0, (size_t)TOT*4, 0);
    cudaMemsetAsync(pDY, 0, (size_t)TOT*4, 0);
    cudaMemsetAsync(pBX, 0, (size_t)TOT*4, 0);
    cudaMemsetAsync(pBY, 0, (size_t)TOT*4, 0);
    cudaMemsetAsync(pBWL, 0, (size_t)SLL*4, 0);
    cudaMemsetAsync(pBWH, 0, (size_t)(3*SLL)*4, 0);

    // dwt2(u_in) -> WL, WH
    k_afb_w<<<NB*FN, 256>>>(u_in, (float*)pLOT, (float*)pHIT);
    k_afb_h2<<<eb(2*SLL), 256>>>();

    // ----- iterations -----
    for (int it = 0; it < 2; ++it) {
        k_sfb_h2<<<eb(2*NB*FN*WD), 256>>>();

        k_fwd2<4><<<FFTG2, 256>>>(nullptr, (float2*)pCB, lam, gama);
        k_transpose_c<<<tg, tb>>>((float2*)pCB, (float2*)pCA);          // [p][y]
        if (it == 0)
            k_fftsolve<1><<<FFTG, 256>>>((float2*)pCA, (float2*)pCB, 1.f/FN,
                                         mmu, lam, gama);
        else
            k_fftsolve<0><<<FFTG, 256>>>((float2*)pCA, (float2*)pCB, 1.f/FN,
                                         mmu, lam, gama);
        k_transpose_c<<<tg, tb>>>((float2*)pCB, (float2*)pCA);          // [y][p]

        if (it == 0) {
            // inv FFT + srelu + u + row-DWT + fwd FFT (spectra -> CB)
            k_invfwd<<<FFTG2, 256>>>((float2*)pCA, (float2*)pCB, (float*)pU,
                                     (float*)pLOT, (float*)pHIT, 1.f/FN, prelu);
            k_shrinkbxy<<<eb(TOT), 256>>>(lam, prelu);
            k_afb_h_w2<<<eb(2*SLL), 256>>>(gama, prelu);
            // G' path: transpose spectra, column FFT with postOp2 -> G
            k_transpose_c<<<tg, tb>>>((float2*)pCB, (float2*)pCA);      // [p][y]
            k_fft4<0><<<FFTG, 256>>>((float2*)pCA, (float2*)pG, 1.f, 2);
        } else {
            k_inv2r<<<FFTG2, 256>>>((float2*)pCA, out, 1.f/FN, prelu);
        }
    }
    (void)in_sizes; (void)n_in; (void)out_size;
}

// round 15
// speedup vs baseline: 2.9859x; 1.1869x over previous
#include <cuda_runtime.h>
#include <math.h>

#define FN   1024
#define NB   4
#define FNN  (FN*FN)
#define TOT  (NB*FNN)
#define WD   518
#define SLL  (NB*WD*WD)
#define SLW  (NB*FN*WD)
#define PIF  3.14159265358979323846f

#define DP(i) ((i) + ((i)>>2))
#define TP(i) ((i) + ((i)>>4))

// ---------------- static device scratch ----------------
__device__ float2 g_CA[TOT];
__device__ float2 g_CB[TOT];
__device__ float2 g_F0T[TOT];
__device__ float2 g_G[TOT];
__device__ float2 g_TW[FN];
__device__ float4 g_TRIG[FN];

__device__ float g_U[TOT];
__device__ float g_DX[TOT];
__device__ float g_DY[TOT];
__device__ float g_BX[TOT];
__device__ float g_BY[TOT];
__device__ float g_MASKT[TOT];

__device__ float g_WL[SLL];
__device__ float g_BWL[SLL];
__device__ float g_WH[3*SLL];
__device__ float g_BWH[3*SLL];
__device__ float g_LOT[SLW];
__device__ float g_HIT[SLW];
__device__ float g_LOS[SLW];
__device__ float g_HIS[SLW];

// ---------------- wavelet filters (db7, L=14) ----------------
__constant__ float cH0A[14] = {
    0.010268176708511255f, 0.004010244871533663f, -0.10780823770381774f,
   -0.14004724044296152f, 0.2886296317515146f, 0.767764317003164f,
    0.5361019170917628f, 0.017441255086855827f, -0.049552834937127255f,
    0.0678926935013727f, 0.03051551316596357f, -0.01263630340325193f,
   -0.0010473848886829163f, 0.002681814568257878f };
__constant__ float cH1A[14] = {
    0.002681814568257878f, 0.0010473848886829163f, -0.01263630340325193f,
   -0.03051551316596357f, 0.0678926935013727f, 0.049552834937127255f,
    0.017441255086855827f, -0.5361019170917628f, 0.767764317003164f,
   -0.2886296317515146f, -0.14004724044296152f, 0.10780823770381774f,
    0.004010244871533663f, -0.010268176708511255f };
__constant__ float cG0[14] = {
    0.002681814568257878f, -0.0010473848886829163f, -0.01263630340325193f,
    0.03051551316596357f, 0.0678926935013727f, -0.049552834937127255f,
    0.017441255086855827f, 0.5361019170917628f, 0.767764317003164f,
    0.2886296317515146f, -0.14004724044296152f, -0.10780823770381774f,
    0.004010244871533663f, 0.010268176708511255f };
__constant__ float cG1[14] = {
   -0.010268176708511255f, 0.004010244871533663f, 0.10780823770381774f,
   -0.14004724044296152f, -0.2886296317515146f, 0.767764317003164f,
   -0.5361019170917628f, 0.017441255086855827f, 0.049552834937127255f,
    0.0678926935013727f, -0.03051551316596357f, -0.01263630340325193f,
    0.0010473848886829163f, 0.002681814568257878f };

__device__ __forceinline__ float2 cmulf(float2 a, float2 b) {
    return make_float2(a.x*b.x - a.y*b.y, a.x*b.y + a.y*b.x);
}

__global__ void k_twinit()
{
    int j = blockIdx.x*blockDim.x + threadIdx.x;
    if (j >= FN) return;
    float th = 2.f*PIF*(float)j/(float)FN;
    float sv, cv; sincosf(-th, &sv, &cv);
    g_TW[j] = make_float2(cv, sv);
    float s1, c1, s2, c2;
    sincosf(th, &s1, &c1);
    sincosf(2.f*th, &s2, &c2);
    g_TRIG[j] = make_float4(c1, s1, c2, s2);
}

template<int INV>
__device__ __forceinline__ void r4stage(const float2* __restrict__ X,
                                        float2* __restrict__ Y,
                                        const float2* __restrict__ tw,
                                        int t, int s)
{
    int ns = 1 << (2*s);
    int k  = t & (ns - 1);
    int j  = ((t - k) << 2) + k;
    int sh = 8 - 2*s;
    float2 c0 = X[DP(t)], c1 = X[DP(t+256)], c2 = X[DP(t+512)], c3 = X[DP(t+768)];
    float2 w1 = tw[TP(k << sh)];
    float2 w2 = tw[TP((2*k) << sh)];
    float2 w3 = tw[TP((3*k) << sh)];
    if (INV) { w1.y = -w1.y; w2.y = -w2.y; w3.y = -w3.y; }
    c1 = cmulf(c1, w1); c2 = cmulf(c2, w2); c3 = cmulf(c3, w3);
    float2 t0 = make_float2(c0.x+c2.x, c0.y+c2.y);
    float2 t1 = make_float2(c0.x-c2.x, c0.y-c2.y);
    float2 t2 = make_float2(c1.x+c3.x, c1.y+c3.y);
    float2 dd = make_float2(c1.x-c3.x, c1.y-c3.y);
    float2 t3 = INV ? make_float2(-dd.y, dd.x) : make_float2(dd.y, -dd.x);
    Y[DP(j)]      = make_float2(t0.x+t2.x, t0.y+t2.y);
    Y[DP(j+ns)]   = make_float2(t1.x+t3.x, t1.y+t3.y);
    Y[DP(j+2*ns)] = make_float2(t0.x-t2.x, t0.y-t2.y);
    Y[DP(j+3*ns)] = make_float2(t1.x-t3.x, t1.y-t3.y);
}

template<int INV>
__device__ __forceinline__ void fft5(float2*& X, float2*& Y,
                                     const float2* __restrict__ tw, int t)
{
#pragma unroll
    for (int s = 0; s < 5; ++s) {
        r4stage<INV>(X, Y, tw, t, s);
        __syncthreads();
        float2* tmp = X; X = Y; Y = tmp;
    }
}

// inline UKER division
__device__ __forceinline__ float2 uker_div(float2 v, float4 tp, float4 tq,
                                           float mk, float mv, float lv, float gv)
{
    float Br = 4.f - tp.x - tq.x - tp.z - tq.z;
    float Bi = tp.y + tq.y - tp.w - tq.w;
    float cf = tp.x*tq.x - tp.y*tq.y;
    float sf = tp.y*tq.x + tp.x*tq.y;
    float2 w = make_float2(mv*mk*mk + gv + lv*(Br*cf + Bi*sf),
                           lv*(Bi*cf - Br*sf));
    float d = 1.f/(w.x*w.x + w.y*w.y);
    return make_float2((v.x*w.x + v.y*w.y)*d, (v.y*w.x - v.x*w.y)*d);
}

// rhs value for (row base, x, y); GRAD=0 skips gradient terms (it0: all zero)
template<int GRAD>
__device__ __forceinline__ float rhs_val(size_t base, int x, int y,
                                         float lv, float gv,
                                         const float* __restrict__ lrow,
                                         const float* __restrict__ hrow)
{
    float grad = 0.f;
    if (GRAD) {
        size_t i = base + x;
        float dxt = 0.f;
        if (x >= 1) {
            int xn = (x == FN-1) ? 1 : x+1;
            dxt = (g_DX[i] - g_BX[i]) - (g_DX[base+xn] - g_BX[base+xn]);
        }
        float dyt = 0.f;
        if (y >= 1) {
            int yn = (y == FN-1) ? 1 : y+1;
            size_t jj = i + (size_t)(yn - y)*FN;
            dyt = (g_DY[i] - g_BY[i]) - (g_DY[jj] - g_BY[jj]);
        }
        grad = lv*(dxt + dyt);
    }
    float idwt = 0.f;
    int k0 = (x + 1) & 1;
#pragma unroll
    for (int kk = 0; kk < 7; ++kk) {
        int k = k0 + 2*kk;
        int mm = (x + k - 1) >> 1;
        idwt += lrow[mm] * cG0[k] + hrow[mm] * cG1[k];
    }
    return grad + gv*idwt;
}

// ---- forward 2-for-1: two REAL rows per block -> two full spectra
// PRE: 0 = load real rows; 4 = rhs w/ gradients; 5 = rhs it0 (idwt only)
template<int PRE>
__global__ __launch_bounds__(256) void k_fwd2(const float* __restrict__ srcv,
                                              float2* __restrict__ dst,
                                              const float* __restrict__ lam,
                                              const float* __restrict__ gama)
{
    __shared__ float2 sA[1280];
    __shared__ float2 sB[1280];
    __shared__ float2 tw[1088];
    int t = threadIdx.x;
    int r0 = 2*blockIdx.x;
    size_t base0 = (size_t)r0*FN;
    size_t base1 = base0 + FN;
    for (int j = t; j < FN; j += 256) tw[TP(j)] = g_TW[j];
    if (PRE == 0) {
        const float* s0 = srcv + base0;
        const float* s1 = srcv + base1;
#pragma unroll
        for (int m = 0; m < 4; ++m) {
            int x = t + 256*m;
            sA[DP(x)] = make_float2(s0[x], s1[x]);
        }
    } else {
        int y0 = r0 & (FN-1);
        float lv = lam[0], gv = gama[0];
        const float* l0 = g_LOS + (size_t)r0*WD;
        const float* h0 = g_HIS + (size_t)r0*WD;
        const float* l1 = l0 + WD;
        const float* h1 = h0 + WD;
#pragma unroll
        for (int m = 0; m < 4; ++m) {
            int x = t + 256*m;
            float a, b;
            if (PRE == 4) {
                a = rhs_val<1>(base0, x, y0,     lv, gv, l0, h0);
                b = rhs_val<1>(base1, x, y0 + 1, lv, gv, l1, h1);
            } else {
                a = rhs_val<0>(base0, x, y0,     lv, gv, l0, h0);
                b = rhs_val<0>(base1, x, y0 + 1, lv, gv, l1, h1);
            }
            sA[DP(x)] = make_float2(a, b);
        }
    }
    __syncthreads();
    float2* X = sA; float2* Y = sB;
    fft5<0>(X, Y, tw, t);
    float2* d0 = dst + base0;
    float2* d1 = dst + base1;
#pragma unroll
    for (int m = 0; m < 4; ++m) {
        int k  = t + 256*m;
        int kk = (FN - k) & (FN-1);
        float2 Zk = X[DP(k)];
        float2 Zm = X[DP(kk)];
        d0[k] = make_float2(0.5f*(Zk.x + Zm.x), 0.5f*(Zk.y - Zm.y));
        d1[k] = make_float2(0.5f*(Zk.y + Zm.y), 0.5f*(Zm.x - Zk.x));
    }
}

// ---- inverse 2-for-1 w/ symmetrization -> real rows + srelu (it=1 path) ----
__global__ __launch_bounds__(256) void k_inv2r(const float2* __restrict__ src,
                                               float* __restrict__ dst,
                                               float scale,
                                               const float* __restrict__ prelu)
{
    __shared__ float2 sA[1280];
    __shared__ float2 sB[1280];
    __shared__ float2 tw[1088];
    int t = threadIdx.x;
    int r0 = 2*blockIdx.x;
    size_t base0 = (size_t)r0*FN;
    size_t base1 = base0 + FN;
    for (int j = t; j < FN; j += 256) tw[TP(j)] = g_TW[j];
    const float2* s0 = src + base0;
    const float2* s1 = src + base1;
#pragma unroll
    for (int m = 0; m < 4; ++m) {
        int x = t + 256*m;
        int xr = (FN - x) & (FN-1);
        float2 a  = s0[x],  b  = s1[x];
        float2 ar = s0[xr], br = s1[xr];
        sA[DP(x)] = make_float2(0.5f*(a.x + ar.x - b.y + br.y),
                                0.5f*(a.y - ar.y + b.x + br.x));
    }
    __syncthreads();
    float2* X = sA; float2* Y = sB;
    fft5<1>(X, Y, tw, t);
    float a = prelu[0];
    float* d0 = dst + base0;
    float* d1 = dst + base1;
#pragma unroll
    for (int m = 0; m < 4; ++m) {
        int x = t + 256*m;
        float2 z = X[DP(x)];
        float v0 = z.x*scale;
        float v1 = z.y*scale;
        d0[x] = (v0 >= 0.f) ? v0 : a*v0;
        d1[x] = (v1 >= 0.f) ? v1 : a*v1;
    }
}

// ---- it0 mega-kernel: inv FFT -> srelu -> u -> row-DWT -> fwd FFT -> spectra
__global__ __launch_bounds__(256) void k_invfwd(const float2* __restrict__ src,
                                                float2* __restrict__ dstspec,
                                                float* __restrict__ uout,
                                                float* __restrict__ lo,
                                                float* __restrict__ hi,
                                                float scale,
                                                const float* __restrict__ prelu)
{
    __shared__ float2 sA[1280];
    __shared__ float2 sB[1280];
    __shared__ float2 tw[1088];
    int t = threadIdx.x;
    int r0 = 2*blockIdx.x;
    size_t base0 = (size_t)r0*FN;
    size_t base1 = base0 + FN;
    for (int j = t; j < FN; j += 256) tw[TP(j)] = g_TW[j];
    const float2* s0 = src + base0;
    const float2* s1 = src + base1;
#pragma unroll
    for (int m = 0; m < 4; ++m) {
        int x = t + 256*m;
        int xr = (FN - x) & (FN-1);
        float2 a  = s0[x],  b  = s1[x];
        float2 ar = s0[xr], br = s1[xr];
        sA[DP(x)] = make_float2(0.5f*(a.x + ar.x - b.y + br.y),
                                0.5f*(a.y - ar.y + b.x + br.x));
    }
    __syncthreads();
    float2* X = sA; float2* Y = sB;
    fft5<1>(X, Y, tw, t);
    {
        float a = prelu[0];
        float* d0 = uout + base0;
        float* d1 = uout + base1;
#pragma unroll
        for (int m = 0; m < 4; ++m) {
            int x = t + 256*m;
            float2 z = X[DP(x)];
            float v0 = z.x*scale;
            float v1 = z.y*scale;
            v0 = (v0 >= 0.f) ? v0 : a*v0;
            v1 = (v1 >= 0.f) ? v1 : a*v1;
            d0[x] = v0;
            d1[x] = v1;
            X[DP(x)] = make_float2(v0, v1);
        }
    }
    __syncthreads();
    {
        size_t ob0 = (size_t)r0*WD;
        size_t ob1 = ob0 + WD;
        for (int o = t; o < WD; o += 256) {
            float l0 = 0.f, h0 = 0.f, l1 = 0.f, h1 = 0.f;
            if (o >= 6 && o <= 505) {
                int j0 = 2*o - 12;
#pragma unroll
                for (int k = 0; k < 14; ++k) {
                    float2 v = X[DP(j0 + k)];
                    l0 += v.x * cH0A[k];  h0 += v.x * cH1A[k];
                    l1 += v.y * cH0A[k];  h1 += v.y * cH1A[k];
                }
            } else {
#pragma unroll
                for (int k = 0; k < 14; ++k) {
                    int j = 2*o + k - 12;
                    j = (j < 0) ? -j : ((j >= FN) ? (2*FN - 2 - j) : j);
                    float2 v = X[DP(j)];
                    l0 += v.x * cH0A[k];  h0 += v.x * cH1A[k];
                    l1 += v.y * cH0A[k];  h1 += v.y * cH1A[k];
                }
            }
            lo[ob0 + o] = l0;  hi[ob0 + o] = h0;
            lo[ob1 + o] = l1;  hi[ob1 + o] = h1;
        }
    }
    __syncthreads();
    fft5<0>(X, Y, tw, t);
    float2* d0 = dstspec + base0;
    float2* d1 = dstspec + base1;
#pragma unroll
    for (int m = 0; m < 4; ++m) {
        int k  = t + 256*m;
        int kk = (FN - k) & (FN-1);
        float2 Zk = X[DP(k)];
        float2 Zm = X[DP(kk)];
        d0[k] = make_float2(0.5f*(Zk.x + Zm.x), 0.5f*(Zk.y - Zm.y));
        d1[k] = make_float2(0.5f*(Zk.y + Zm.y), 0.5f*(Zm.x - Zk.x));
    }
}

// ---- complex-in FFT, postOp 2 = store G' ----
template<int INV>
__global__ __launch_bounds__(256) void k_fft4(const float2* __restrict__ src,
                                              float2* __restrict__ dst,
                                              float scale, int postOp)
{
    __shared__ float2 sA[1280];
    __shared__ float2 sB[1280];
    __shared__ float2 tw[1088];
    int t = threadIdx.x;
    size_t base = (size_t)blockIdx.x*FN;
    for (int j = t; j < FN; j += 256) tw[TP(j)] = g_TW[j];
    const float2* s = src + base;
#pragma unroll
    for (int m = 0; m < 4; ++m) sA[DP(t+256*m)] = s[t+256*m];
    __syncthreads();
    float2* X = sA; float2* Y = sB;
    fft5<INV>(X, Y, tw, t);
    float2* d = dst + base;
#pragma unroll
    for (int m = 0; m < 4; ++m) {
        int idx = t + 256*m;
        float2 v = X[DP(idx)];
        v.x *= scale; v.y *= scale;
        if (postOp == 2) {
            float mk = g_MASKT[base + idx];
            float2 f0 = g_F0T[base + idx];
            v = make_float2(mk*(2.f*f0.x - mk*v.x), mk*(2.f*f0.y - mk*v.y));
        }
        d[idx] = v;
    }
}

// ---- conjugate-pair column solve: fwd (half work) + div + inv ----
// grid = NB*513: j=0/512 standalone; j=1..511 pair (j, FN-j)
template<int IT0>
__global__ __launch_bounds__(256) void k_fftsolve(const float2* __restrict__ src,
                                                  float2* __restrict__ dst,
                                                  float scale,
                                                  const float* __restrict__ mmu,
                                                  const float* __restrict__ lam,
                                                  const float* __restrict__ gama)
{
    __shared__ float2 sA[1280];
    __shared__ float2 sB[1280];
    __shared__ float2 tw[1088];
    int t = threadIdx.x;
    int j = blockIdx.x % 513;
    int batch = blockIdx.x / 513;
    for (int i = t; i < FN; i += 256) tw[TP(i)] = g_TW[i];
    float mv = mmu[0], lv = lam[0], gv = gama[0];

    if (j == 0 || j == 512) {
        int p = j;
        size_t base = ((size_t)batch*FN + p)*FN;
        const float2* s = src + base;
#pragma unroll
        for (int m = 0; m < 4; ++m) sA[DP(t+256*m)] = s[t+256*m];
        __syncthreads();
        float2* X = sA; float2* Y = sB;
        fft5<0>(X, Y, tw, t);
        float4 tp = g_TRIG[p];
#pragma unroll
        for (int m = 0; m < 4; ++m) {
            int q = t + 256*m;
            size_t i = base + q;
            float2 v = X[DP(q)];
            float mk = g_MASKT[i];
            float2 g;
            if (IT0) { float2 f0 = g_F0T[i]; g = make_float2(mk*f0.x, mk*f0.y); }
            else      g = g_G[i];
            v.x += mv*g.x;  v.y += mv*g.y;
            X[DP(q)] = uker_div(v, tp, g_TRIG[q], mk, mv, lv, gv);
        }
        __syncthreads();
        fft5<1>(X, Y, tw, t);
        float2* d = dst + base;
#pragma unroll
        for (int m = 0; m < 4; ++m) {
            float2 v = X[DP(t+256*m)];
            d[t+256*m] = make_float2(v.x*scale, v.y*scale);
        }
    } else {
        int p1 = j, p2 = FN - j;
        size_t base1 = ((size_t)batch*FN + p1)*FN;
        size_t base2 = ((size_t)batch*FN + p2)*FN;
        const float2* s = src + base1;
#pragma unroll
        for (int m = 0; m < 4; ++m) sA[DP(t+256*m)] = s[t+256*m];
        __syncthreads();
        float2* X = sA; float2* Y = sB;
        fft5<0>(X, Y, tw, t);        // X = F2 of column p1 (natural order)
        float4 tp1 = g_TRIG[p1];
        float4 tp2 = g_TRIG[p2];
        float2 stash[4];
#pragma unroll
        for (int m = 0; m < 4; ++m) {
            int q = t + 256*m;
            float4 tq = g_TRIG[q];
            // column p1
            {
                size_t i = base1 + q;
                float2 v = X[DP(q)];
                float mk = g_MASKT[i];
                float2 g;
                if (IT0) { float2 f0 = g_F0T[i]; g = make_float2(mk*f0.x, mk*f0.y); }
                else      g = g_G[i];
                v.x += mv*g.x;  v.y += mv*g.y;
                stash[m] = uker_div(v, tp1, tq, mk, mv, lv, gv);
            }
            // column p2: F2[p2][q] = conj(F2[p1][(FN-q)&1023])
            {
                int qr = (FN - q) & (FN-1);
                float2 v = X[DP(qr)];
                v.y = -v.y;
                size_t i = base2 + q;
                float mk = g_MASKT[i];
                float2 g;
                if (IT0) { float2 f0 = g_F0T[i]; g = make_float2(mk*f0.x, mk*f0.y); }
                else      g = g_G[i];
                v.x += mv*g.x;  v.y += mv*g.y;
                Y[DP(q)] = uker_div(v, tp2, tq, mk, mv, lv, gv);
            }
        }
        __syncthreads();
        // inverse column p2 (data currently in Y)
        {
            float2* Xi = Y; float2* Yi = X;
            fft5<1>(Xi, Yi, tw, t);
            float2* d = dst + base2;
#pragma unroll
            for (int m = 0; m < 4; ++m) {
                float2 v = Xi[DP(t+256*m)];
                d[t+256*m] = make_float2(v.x*scale, v.y*scale);
            }
        }
        __syncthreads();
        // inverse column p1 from register stash
#pragma unroll
        for (int m = 0; m < 4; ++m) sA[DP(t+256*m)] = stash[m];
        __syncthreads();
        {
            float2* Xi = sA; float2* Yi = sB;
            fft5<1>(Xi, Yi, tw, t);
            float2* d = dst + base1;
#pragma unroll
            for (int m = 0; m < 4; ++m) {
                float2 v = Xi[DP(t+256*m)];
                d[t+256*m] = make_float2(v.x*scale, v.y*scale);
            }
        }
    }
}

// ---------------- transposes ----------------
__global__ void k_transpose_c(const float2* __restrict__ src, float2* __restrict__ dst)
{
    __shared__ float2 tile[32][33];
    int b = blockIdx.z;
    const float2* s = src + (size_t)b*FNN;
    float2* d = dst + (size_t)b*FNN;
    int x  = blockIdx.x*32 + threadIdx.x;
    int y0 = blockIdx.y*32 + threadIdx.y;
#pragma unroll
    for (int i = 0; i < 32; i += 8)
        tile[threadIdx.y+i][threadIdx.x] = s[(size_t)(y0+i)*FN + x];
    __syncthreads();
    int x2 = blockIdx.y*32 + threadIdx.x;
    int y2 = blockIdx.x*32 + threadIdx.y;
#pragma unroll
    for (int i = 0; i < 32; i += 8)
        d[(size_t)(y2+i)*FN + x2] = tile[threadIdx.x][threadIdx.y+i];
}

__global__ void k_transpose_r(const float* __restrict__ src, float* __restrict__ dst)
{
    __shared__ float tile[32][33];
    int b = blockIdx.z;
    const float* s = src + (size_t)b*FNN;
    float* d = dst + (size_t)b*FNN;
    int x  = blockIdx.x*32 + threadIdx.x;
    int y0 = blockIdx.y*32 + threadIdx.y;
#pragma unroll
    for (int i = 0; i < 32; i += 8)
        tile[threadIdx.y+i][threadIdx.x] = s[(size_t)(y0+i)*FN + x];
    __syncthreads();
    int x2 = blockIdx.y*32 + threadIdx.x;
    int y2 = blockIdx.x*32 + threadIdx.y;
#pragma unroll
    for (int i = 0; i < 32; i += 8)
        d[(size_t)(y2+i)*FN + x2] = tile[threadIdx.x][threadIdx.y+i];
}

__global__ void k_make_f0T(const float* __restrict__ fr, const float* __restrict__ fi,
                           float2* __restrict__ dst)
{
    __shared__ float tr[32][33];
    __shared__ float ti[32][33];
    int b = blockIdx.z;
    const float* sr = fr + (size_t)b*FNN;
    const float* si = fi + (size_t)b*FNN;
    float2* d = dst + (size_t)b*FNN;
    int x  = blockIdx.x*32 + threadIdx.x;
    int y0 = blockIdx.y*32 + threadIdx.y;
#pragma unroll
    for (int i = 0; i < 32; i += 8) {
        tr[threadIdx.y+i][threadIdx.x] = sr[(size_t)(y0+i)*FN + x];
        ti[threadIdx.y+i][threadIdx.x] = si[(size_t)(y0+i)*FN + x];
    }
    __syncthreads();
    int x2 = blockIdx.y*32 + threadIdx.x;
    int y2 = blockIdx.x*32 + threadIdx.y;
#pragma unroll
    for (int i = 0; i < 32; i += 8)
        d[(size_t)(y2+i)*FN + x2] =
            make_float2(tr[threadIdx.x][threadIdx.y+i], ti[threadIdx.x][threadIdx.y+i]);
}

// ---------------- it0 b-update (dx=bx=dy=by=0 going in) ----------------
__global__ void k_shrinkbxy0()
{
    int i = blockIdx.x*blockDim.x + threadIdx.x;
    if (i >= TOT) return;
    int x = i & (FN-1);
    int y = (i >> 10) & (FN-1);
    int rowb = i - x;
    float dxu = 0.f;
    if (x >= 1) {
        int xm = (x == 1) ? FN-1 : x-1;
        dxu = g_U[i] - g_U[rowb + xm];
    }
    float dyu = 0.f;
    if (y >= 1) {
        int ym = (y == 1) ? FN-1 : y-1;
        dyu = g_U[i] - g_U[i + (ym - y)*FN];
    }
    g_DX[i] = 0.f;  g_DY[i] = 0.f;
    g_BX[i] = dxu;  g_BY[i] = dyu;
}

// ---------------- DWT row analysis (smem tiled, fast interior path) ----------
__global__ __launch_bounds__(256) void k_afb_w(const float* __restrict__ src,
                                               float* __restrict__ lo,
                                               float* __restrict__ hi)
{
    __shared__ float rs[FN];
    int t = threadIdx.x;
    int r = blockIdx.x;
    const float* row = src + (size_t)r*FN;
#pragma unroll
    for (int m = 0; m < 4; ++m) rs[t+256*m] = row[t+256*m];
    __syncthreads();
    size_t ob = (size_t)r*WD;
    for (int o = t; o < WD; o += 256) {
        float l = 0.f, h = 0.f;
        if (o >= 6 && o <= 505) {
            int j0 = 2*o - 12;
#pragma unroll
            for (int k = 0; k < 14; ++k) {
                float v = rs[j0 + k];
                l += v * cH0A[k];
                h += v * cH1A[k];
            }
        } else {
#pragma unroll
            for (int k = 0; k < 14; ++k) {
                int j = 2*o + k - 12;
                j = (j < 0) ? -j : ((j >= FN) ? (2*FN - 2 - j) : j);
                float v = rs[j];
                l += v * cH0A[k];
                h += v * cH1A[k];
            }
        }
        lo[ob + o] = l;
        hi[ob + o] = h;
    }
}

// column DWT for init: both halves in one launch
__global__ void k_afb_h2()
{
    int i = blockIdx.x*blockDim.x + threadIdx.x;
    if (i >= 2*SLL) return;
    const float* src;
    float *lo, *hi;
    int ii = i;
    if (i < SLL) {
        src = g_LOT; lo = g_WL; hi = g_WH;
    } else {
        ii -= SLL;
        src = g_HIT; lo = g_WH + (size_t)SLL; hi = g_WH + (size_t)2*SLL;
    }
    int w = ii % WD;
    int o = (ii / WD) % WD;
    int b = ii / (WD*WD);
    const float* base = src + (size_t)b*FN*WD;
    float l = 0.f, h = 0.f;
    if (o >= 6 && o <= 505) {
        const float* pp = base + (size_t)(2*o - 12)*WD + w;
#pragma unroll
        for (int k = 0; k < 14; ++k) {
            float v = pp[(size_t)k*WD];
            l += v * cH0A[k];
            h += v * cH1A[k];
        }
    } else {
#pragma unroll
        for (int k = 0; k < 14; ++k) {
            int j = 2*o + k - 12;
            j = (j < 0) ? -j : ((j >= FN) ? (2*FN - 2 - j) : j);
            float v = base[(size_t)j*WD + w];
            l += v * cH0A[k];
            h += v * cH1A[k];
        }
    }
    lo[ii] = l;
    hi[ii] = h;
}

// column DWT + w/b update (it0 only: old bw = 0)
__global__ void k_afb_h_w2(const float* __restrict__ gama,
                           const float* __restrict__ prelu)
{
    int i = blockIdx.x*blockDim.x + threadIdx.x;
    if (i >= 2*SLL) return;
    const float* src;
    float *bwLo, *wLo, *bwHi, *wHi;
    int ii = i;
    if (i < SLL) {
        src = g_LOT;
        bwLo = g_BWL; wLo = g_WL;
        bwHi = g_BWH; wHi = g_WH;
    } else {
        ii -= SLL;
        src = g_HIT;
        bwLo = g_BWH + (size_t)SLL;   wLo = g_WH + (size_t)SLL;
        bwHi = g_BWH + (size_t)2*SLL; wHi = g_WH + (size_t)2*SLL;
    }
    int w = ii % WD;
    int o = (ii / WD) % WD;
    int b = ii / (WD*WD);
    const float* base = src + (size_t)b*FN*WD;
    float l = 0.f, h = 0.f;
    if (o >= 6 && o <= 505) {
        const float* pp = base + (size_t)(2*o - 12)*WD + w;
#pragma unroll
        for (int k = 0; k < 14; ++k) {
            float v = pp[(size_t)k*WD];
            l += v * cH0A[k];
            h += v * cH1A[k];
        }
    } else {
#pragma unroll
        for (int k = 0; k < 14; ++k) {
            int j = 2*o + k - 12;
            j = (j < 0) ? -j : ((j >= FN) ? (2*FN - 2 - j) : j);
            float v = base[(size_t)j*WD + w];
            l += v * cH0A[k];
            h += v * cH1A[k];
        }
    }
    float a  = prelu[0];
    float ig = 1.f/gama[0];
    float t  = l - ig;                       // old bw = 0
    float wv = (t >= 0.f) ? t : a*t;
    wLo[ii]  = wv;
    bwLo[ii] = l - wv;
    t  = h - ig;
    wv = (t >= 0.f) ? t : a*t;
    wHi[ii]  = wv;
    bwHi[ii] = h - wv;
}

// ---- IDWT column synthesis, both halves; IT0=1 skips (zero) B reads ----
template<int IT0>
__global__ void k_sfb_h2()
{
    int half = NB*FN*WD;
    int i = blockIdx.x*blockDim.x + threadIdx.x;
    if (i >= 2*half) return;
    const float *lA, *lB, *hA, *hB;
    float* out;
    int ii = i;
    if (i < half) {
        lA = g_WL;  lB = g_BWL;
        hA = g_WH;  hB = g_BWH;
        out = g_LOS;
    } else {
        ii -= half;
        lA = g_WH + (size_t)SLL;    lB = g_BWH + (size_t)SLL;
        hA = g_WH + (size_t)2*SLL;  hB = g_BWH + (size_t)2*SLL;
        out = g_HIS;
    }
    int w = ii % WD;
    int o = (ii / WD) % FN;
    int b = ii / (FN*WD);
    size_t bb = (size_t)b*WD*WD;
    float acc = 0.f;
    int k0 = (o + 1) & 1;
#pragma unroll
    for (int kk = 0; kk < 7; ++kk) {
        int k = k0 + 2*kk;
        int m = (o + k - 1) >> 1;
        size_t idx = bb + (size_t)m*WD + w;
        float lo = IT0 ? lA[idx] : (lA[idx] - lB[idx]);
        float hi = IT0 ? hA[idx] : (hA[idx] - hB[idx]);
        acc += lo * cG0[k] + hi * cG1[k];
    }
    out[ii] = acc;
}

// ---------------- host orchestration ----------------
static inline int eb(int n) { return (n + 255) / 256; }

extern "C" void kernel_launch(void* const* d_in, const int* in_sizes, int n_in,
                              void* d_out, int out_size)
{
    const float* u_in   = (const float*)d_in[0];
    const float* uvMask = (const float*)d_in[1];
    const float* f_real = (const float*)d_in[3];
    const float* f_imag = (const float*)d_in[4];
    const float* lam    = (const float*)d_in[5];
    const float* gama   = (const float*)d_in[6];
    const float* mmu    = (const float*)d_in[7];
    const float* prelu  = (const float*)d_in[8];
    float* out = (float*)d_out;

    void *pCA, *pCB, *pU, *pMASKT, *pF0T, *pG;
    void *pLOT, *pHIT;
    cudaGetSymbolAddress(&pCA, g_CA);       cudaGetSymbolAddress(&pCB, g_CB);
    cudaGetSymbolAddress(&pU, g_U);         cudaGetSymbolAddress(&pG, g_G);
    cudaGetSymbolAddress(&pMASKT, g_MASKT); cudaGetSymbolAddress(&pF0T, g_F0T);
    cudaGetSymbolAddress(&pLOT, g_LOT);     cudaGetSymbolAddress(&pHIT, g_HIT);

    dim3 tb(32, 8), tg(32, 32, NB);
    const int SOLV = NB*513;
    const int FFTG = NB*FN;
    const int FFTG2 = NB*FN/2;

    // ----- init -----
    k_twinit<<<4, 256>>>();
    k_transpose_r<<<tg, tb>>>(uvMask, (float*)pMASKT);
    k_make_f0T<<<tg, tb>>>(f_real, f_imag, (float2*)pF0T);

    // dwt2(u_in) -> WL, WH
    k_afb_w<<<NB*FN, 256>>>(u_in, (float*)pLOT, (float*)pHIT);
    k_afb_h2<<<eb(2*SLL), 256>>>();

    // ----- iterations -----
    for (int it = 0; it < 2; ++it) {
        if (it == 0) k_sfb_h2<1><<<eb(2*NB*FN*WD), 256>>>();
        else         k_sfb_h2<0><<<eb(2*NB*FN*WD), 256>>>();

        if (it == 0) k_fwd2<5><<<FFTG2, 256>>>(nullptr, (float2*)pCB, lam, gama);
        else         k_fwd2<4><<<FFTG2, 256>>>(nullptr, (float2*)pCB, lam, gama);
        k_transpose_c<<<tg, tb>>>((float2*)pCB, (float2*)pCA);          // [p][y]
        if (it == 0)
            k_fftsolve<1><<<SOLV, 256>>>((float2*)pCA, (float2*)pCB, 1.f/FN,
                                         mmu, lam, gama);
        else
            k_fftsolve<0><<<SOLV, 256>>>((float2*)pCA, (float2*)pCB, 1.f/FN,
                                         mmu, lam, gama);
        k_transpose_c<<<tg, tb>>>((float2*)pCB, (float2*)pCA);          // [y][p]

        if (it == 0) {
            k_invfwd<<<FFTG2, 256>>>((float2*)pCA, (float2*)pCB, (float*)pU,
                                     (float*)pLOT, (float*)pHIT, 1.f/FN, prelu);
            k_shrinkbxy0<<<eb(TOT), 256>>>();
            k_afb_h_w2<<<eb(2*SLL), 256>>>(gama, prelu);
            k_transpose_c<<<tg, tb>>>((float2*)pCB, (float2*)pCA);      // [p][y]
            k_fft4<0><<<FFTG, 256>>>((float2*)pCA, (float2*)pG, 1.f, 2);
        } else {
            k_inv2r<<<FFTG2, 256>>>((float2*)pCA, out, 1.f/FN, prelu);
        }
    }
    (void)in_sizes; (void)n_in; (void)out_size;
}

// round 16
// speedup vs baseline: 3.0256x; 1.0133x over previous
#include <cuda_runtime.h>
#include <math.h>

#define FN   1024
#define NB   4
#define FNN  (FN*FN)
#define TOT  (NB*FNN)
#define WD   518
#define SLL  (NB*WD*WD)
#define SLW  (NB*FN*WD)
#define PIF  3.14159265358979323846f

#define DP(i) ((i) + ((i)>>2))
#define TP(i) ((i) + ((i)>>4))

// ---------------- static device scratch ----------------
__device__ float2 g_CA[TOT];
__device__ float2 g_CB[TOT];
__device__ float2 g_F0T[TOT];
__device__ float2 g_G[TOT];
__device__ float2 g_TW[FN];
__device__ float4 g_TRIG[FN];

__device__ float g_U[TOT];
__device__ float g_DX[TOT];
__device__ float g_DY[TOT];
__device__ float g_BX[TOT];
__device__ float g_BY[TOT];
__device__ float g_MASKT[TOT];

__device__ float g_WL[SLL];
__device__ float g_BWL[SLL];
__device__ float g_WH[3*SLL];
__device__ float g_BWH[3*SLL];
__device__ float g_LOT[SLW];
__device__ float g_HIT[SLW];
__device__ float g_LOS[SLW];
__device__ float g_HIS[SLW];

// ---------------- wavelet filters (db7, L=14) ----------------
__constant__ float cH0A[14] = {
    0.010268176708511255f, 0.004010244871533663f, -0.10780823770381774f,
   -0.14004724044296152f, 0.2886296317515146f, 0.767764317003164f,
    0.5361019170917628f, 0.017441255086855827f, -0.049552834937127255f,
    0.0678926935013727f, 0.03051551316596357f, -0.01263630340325193f,
   -0.0010473848886829163f, 0.002681814568257878f };
__constant__ float cH1A[14] = {
    0.002681814568257878f, 0.0010473848886829163f, -0.01263630340325193f,
   -0.03051551316596357f, 0.0678926935013727f, 0.049552834937127255f,
    0.017441255086855827f, -0.5361019170917628f, 0.767764317003164f,
   -0.2886296317515146f, -0.14004724044296152f, 0.10780823770381774f,
    0.004010244871533663f, -0.010268176708511255f };
__constant__ float cG0[14] = {
    0.002681814568257878f, -0.0010473848886829163f, -0.01263630340325193f,
    0.03051551316596357f, 0.0678926935013727f, -0.049552834937127255f,
    0.017441255086855827f, 0.5361019170917628f, 0.767764317003164f,
    0.2886296317515146f, -0.14004724044296152f, -0.10780823770381774f,
    0.004010244871533663f, 0.010268176708511255f };
__constant__ float cG1[14] = {
   -0.010268176708511255f, 0.004010244871533663f, 0.10780823770381774f,
   -0.14004724044296152f, -0.2886296317515146f, 0.767764317003164f,
   -0.5361019170917628f, 0.017441255086855827f, 0.049552834937127255f,
    0.0678926935013727f, -0.03051551316596357f, -0.01263630340325193f,
    0.0010473848886829163f, 0.002681814568257878f };

__device__ __forceinline__ float2 cmulf(float2 a, float2 b) {
    return make_float2(a.x*b.x - a.y*b.y, a.x*b.y + a.y*b.x);
}

__global__ void k_twinit()
{
    int j = blockIdx.x*blockDim.x + threadIdx.x;
    if (j >= FN) return;
    float th = 2.f*PIF*(float)j/(float)FN;
    float sv, cv; sincosf(-th, &sv, &cv);
    g_TW[j] = make_float2(cv, sv);
    float s1, c1, s2, c2;
    sincosf(th, &s1, &c1);
    sincosf(2.f*th, &s2, &c2);
    g_TRIG[j] = make_float4(c1, s1, c2, s2);
}

template<int INV>
__device__ __forceinline__ void r4stage(const float2* __restrict__ X,
                                        float2* __restrict__ Y,
                                        const float2* __restrict__ tw,
                                        int t, int s)
{
    int ns = 1 << (2*s);
    int k  = t & (ns - 1);
    int j  = ((t - k) << 2) + k;
    int sh = 8 - 2*s;
    float2 c0 = X[DP(t)], c1 = X[DP(t+256)], c2 = X[DP(t+512)], c3 = X[DP(t+768)];
    float2 w1 = tw[TP(k << sh)];
    float2 w2 = tw[TP((2*k) << sh)];
    float2 w3 = tw[TP((3*k) << sh)];
    if (INV) { w1.y = -w1.y; w2.y = -w2.y; w3.y = -w3.y; }
    c1 = cmulf(c1, w1); c2 = cmulf(c2, w2); c3 = cmulf(c3, w3);
    float2 t0 = make_float2(c0.x+c2.x, c0.y+c2.y);
    float2 t1 = make_float2(c0.x-c2.x, c0.y-c2.y);
    float2 t2 = make_float2(c1.x+c3.x, c1.y+c3.y);
    float2 dd = make_float2(c1.x-c3.x, c1.y-c3.y);
    float2 t3 = INV ? make_float2(-dd.y, dd.x) : make_float2(dd.y, -dd.x);
    Y[DP(j)]      = make_float2(t0.x+t2.x, t0.y+t2.y);
    Y[DP(j+ns)]   = make_float2(t1.x+t3.x, t1.y+t3.y);
    Y[DP(j+2*ns)] = make_float2(t0.x-t2.x, t0.y-t2.y);
    Y[DP(j+3*ns)] = make_float2(t1.x-t3.x, t1.y-t3.y);
}

template<int INV>
__device__ __forceinline__ void fft5(float2*& X, float2*& Y,
                                     const float2* __restrict__ tw, int t)
{
#pragma unroll
    for (int s = 0; s < 5; ++s) {
        r4stage<INV>(X, Y, tw, t, s);
        __syncthreads();
        float2* tmp = X; X = Y; Y = tmp;
    }
}

__device__ __forceinline__ float2 uker_div(float2 v, float4 tp, float4 tq,
                                           float mk, float mv, float lv, float gv)
{
    float Br = 4.f - tp.x - tq.x - tp.z - tq.z;
    float Bi = tp.y + tq.y - tp.w - tq.w;
    float cf = tp.x*tq.x - tp.y*tq.y;
    float sf = tp.y*tq.x + tp.x*tq.y;
    float2 w = make_float2(mv*mk*mk + gv + lv*(Br*cf + Bi*sf),
                           lv*(Bi*cf - Br*sf));
    float d = 1.f/(w.x*w.x + w.y*w.y);
    return make_float2((v.x*w.x + v.y*w.y)*d, (v.y*w.x - v.x*w.y)*d);
}

template<int GRAD>
__device__ __forceinline__ float rhs_val(size_t base, int x, int y,
                                         float lv, float gv,
                                         const float* __restrict__ lrow,
                                         const float* __restrict__ hrow)
{
    float grad = 0.f;
    if (GRAD) {
        size_t i = base + x;
        float dxt = 0.f;
        if (x >= 1) {
            int xn = (x == FN-1) ? 1 : x+1;
            dxt = (g_DX[i] - g_BX[i]) - (g_DX[base+xn] - g_BX[base+xn]);
        }
        float dyt = 0.f;
        if (y >= 1) {
            int yn = (y == FN-1) ? 1 : y+1;
            size_t jj = i + (size_t)(yn - y)*FN;
            dyt = (g_DY[i] - g_BY[i]) - (g_DY[jj] - g_BY[jj]);
        }
        grad = lv*(dxt + dyt);
    }
    float idwt = 0.f;
    int k0 = (x + 1) & 1;
#pragma unroll
    for (int kk = 0; kk < 7; ++kk) {
        int k = k0 + 2*kk;
        int mm = (x + k - 1) >> 1;
        idwt += lrow[mm] * cG0[k] + hrow[mm] * cG1[k];
    }
    return grad + gv*idwt;
}

// ---- forward 2-for-1: two REAL rows per block -> two full spectra
// PRE: 0 = load real rows; 4 = rhs w/ gradients; 5 = rhs it0 (idwt only)
template<int PRE>
__global__ __launch_bounds__(256) void k_fwd2(const float* __restrict__ srcv,
                                              float2* __restrict__ dst,
                                              const float* __restrict__ lam,
                                              const float* __restrict__ gama)
{
    __shared__ float2 sA[1280];
    __shared__ float2 sB[1280];
    __shared__ float2 tw[1088];
    int t = threadIdx.x;
    int r0 = 2*blockIdx.x;
    size_t base0 = (size_t)r0*FN;
    size_t base1 = base0 + FN;
    for (int j = t; j < FN; j += 256) tw[TP(j)] = g_TW[j];
    if (PRE == 0) {
        const float* s0 = srcv + base0;
        const float* s1 = srcv + base1;
#pragma unroll
        for (int m = 0; m < 4; ++m) {
            int x = t + 256*m;
            sA[DP(x)] = make_float2(s0[x], s1[x]);
        }
    } else {
        int y0 = r0 & (FN-1);
        float lv = lam[0], gv = gama[0];
        const float* l0 = g_LOS + (size_t)r0*WD;
        const float* h0 = g_HIS + (size_t)r0*WD;
        const float* l1 = l0 + WD;
        const float* h1 = h0 + WD;
#pragma unroll
        for (int m = 0; m < 4; ++m) {
            int x = t + 256*m;
            float a, b;
            if (PRE == 4) {
                a = rhs_val<1>(base0, x, y0,     lv, gv, l0, h0);
                b = rhs_val<1>(base1, x, y0 + 1, lv, gv, l1, h1);
            } else {
                a = rhs_val<0>(base0, x, y0,     lv, gv, l0, h0);
                b = rhs_val<0>(base1, x, y0 + 1, lv, gv, l1, h1);
            }
            sA[DP(x)] = make_float2(a, b);
        }
    }
    __syncthreads();
    float2* X = sA; float2* Y = sB;
    fft5<0>(X, Y, tw, t);
    float2* d0 = dst + base0;
    float2* d1 = dst + base1;
#pragma unroll
    for (int m = 0; m < 4; ++m) {
        int k  = t + 256*m;
        int kk = (FN - k) & (FN-1);
        float2 Zk = X[DP(k)];
        float2 Zm = X[DP(kk)];
        d0[k] = make_float2(0.5f*(Zk.x + Zm.x), 0.5f*(Zk.y - Zm.y));
        d1[k] = make_float2(0.5f*(Zk.y + Zm.y), 0.5f*(Zm.x - Zk.x));
    }
}

// ---- inverse 2-for-1 w/ symmetrization -> real rows + srelu (it=1 path) ----
__global__ __launch_bounds__(256) void k_inv2r(const float2* __restrict__ src,
                                               float* __restrict__ dst,
                                               float scale,
                                               const float* __restrict__ prelu)
{
    __shared__ float2 sA[1280];
    __shared__ float2 sB[1280];
    __shared__ float2 tw[1088];
    int t = threadIdx.x;
    int r0 = 2*blockIdx.x;
    size_t base0 = (size_t)r0*FN;
    size_t base1 = base0 + FN;
    for (int j = t; j < FN; j += 256) tw[TP(j)] = g_TW[j];
    const float2* s0 = src + base0;
    const float2* s1 = src + base1;
#pragma unroll
    for (int m = 0; m < 4; ++m) {
        int x = t + 256*m;
        int xr = (FN - x) & (FN-1);
        float2 a  = s0[x],  b  = s1[x];
        float2 ar = s0[xr], br = s1[xr];
        sA[DP(x)] = make_float2(0.5f*(a.x + ar.x - b.y + br.y),
                                0.5f*(a.y - ar.y + b.x + br.x));
    }
    __syncthreads();
    float2* X = sA; float2* Y = sB;
    fft5<1>(X, Y, tw, t);
    float a = prelu[0];
    float* d0 = dst + base0;
    float* d1 = dst + base1;
#pragma unroll
    for (int m = 0; m < 4; ++m) {
        int x = t + 256*m;
        float2 z = X[DP(x)];
        float v0 = z.x*scale;
        float v1 = z.y*scale;
        d0[x] = (v0 >= 0.f) ? v0 : a*v0;
        d1[x] = (v1 >= 0.f) ? v1 : a*v1;
    }
}

// ---- it0 mega-kernel: inv FFT -> srelu -> u -> row-DWT -> fwd FFT -> spectra
__global__ __launch_bounds__(256) void k_invfwd(const float2* __restrict__ src,
                                                float2* __restrict__ dstspec,
                                                float* __restrict__ uout,
                                                float* __restrict__ lo,
                                                float* __restrict__ hi,
                                                float scale,
                                                const float* __restrict__ prelu)
{
    __shared__ float2 sA[1280];
    __shared__ float2 sB[1280];
    __shared__ float2 tw[1088];
    int t = threadIdx.x;
    int r0 = 2*blockIdx.x;
    size_t base0 = (size_t)r0*FN;
    size_t base1 = base0 + FN;
    for (int j = t; j < FN; j += 256) tw[TP(j)] = g_TW[j];
    const float2* s0 = src + base0;
    const float2* s1 = src + base1;
#pragma unroll
    for (int m = 0; m < 4; ++m) {
        int x = t + 256*m;
        int xr = (FN - x) & (FN-1);
        float2 a  = s0[x],  b  = s1[x];
        float2 ar = s0[xr], br = s1[xr];
        sA[DP(x)] = make_float2(0.5f*(a.x + ar.x - b.y + br.y),
                                0.5f*(a.y - ar.y + b.x + br.x));
    }
    __syncthreads();
    float2* X = sA; float2* Y = sB;
    fft5<1>(X, Y, tw, t);
    {
        float a = prelu[0];
        float* d0 = uout + base0;
        float* d1 = uout + base1;
#pragma unroll
        for (int m = 0; m < 4; ++m) {
            int x = t + 256*m;
            float2 z = X[DP(x)];
            float v0 = z.x*scale;
            float v1 = z.y*scale;
            v0 = (v0 >= 0.f) ? v0 : a*v0;
            v1 = (v1 >= 0.f) ? v1 : a*v1;
            d0[x] = v0;
            d1[x] = v1;
            X[DP(x)] = make_float2(v0, v1);
        }
    }
    __syncthreads();
    {
        size_t ob0 = (size_t)r0*WD;
        size_t ob1 = ob0 + WD;
        for (int o = t; o < WD; o += 256) {
            float l0 = 0.f, h0 = 0.f, l1 = 0.f, h1 = 0.f;
            if (o >= 6 && o <= 505) {
                int j0 = 2*o - 12;
#pragma unroll
                for (int k = 0; k < 14; ++k) {
                    float2 v = X[DP(j0 + k)];
                    l0 += v.x * cH0A[k];  h0 += v.x * cH1A[k];
                    l1 += v.y * cH0A[k];  h1 += v.y * cH1A[k];
                }
            } else {
#pragma unroll
                for (int k = 0; k < 14; ++k) {
                    int j = 2*o + k - 12;
                    j = (j < 0) ? -j : ((j >= FN) ? (2*FN - 2 - j) : j);
                    float2 v = X[DP(j)];
                    l0 += v.x * cH0A[k];  h0 += v.x * cH1A[k];
                    l1 += v.y * cH0A[k];  h1 += v.y * cH1A[k];
                }
            }
            lo[ob0 + o] = l0;  hi[ob0 + o] = h0;
            lo[ob1 + o] = l1;  hi[ob1 + o] = h1;
        }
    }
    __syncthreads();
    fft5<0>(X, Y, tw, t);
    float2* d0 = dstspec + base0;
    float2* d1 = dstspec + base1;
#pragma unroll
    for (int m = 0; m < 4; ++m) {
        int k  = t + 256*m;
        int kk = (FN - k) & (FN-1);
        float2 Zk = X[DP(k)];
        float2 Zm = X[DP(kk)];
        d0[k] = make_float2(0.5f*(Zk.x + Zm.x), 0.5f*(Zk.y - Zm.y));
        d1[k] = make_float2(0.5f*(Zk.y + Zm.y), 0.5f*(Zm.x - Zk.x));
    }
}

// ---- conjugate-pair G' pass: column fwd FFT (half work) + G' epilogue ----
// src = [p][y] row-spectra of real u; FU[p2][q] = conj(FU[p1][(FN-q)&1023])
__global__ __launch_bounds__(256) void k_gpair(const float2* __restrict__ src)
{
    __shared__ float2 sA[1280];
    __shared__ float2 sB[1280];
    __shared__ float2 tw[1088];
    int t = threadIdx.x;
    int j = blockIdx.x % 513;
    int batch = blockIdx.x / 513;
    for (int i = t; i < FN; i += 256) tw[TP(i)] = g_TW[i];

    int p1 = j;
    size_t base1 = ((size_t)batch*FN + p1)*FN;
    const float2* s = src + base1;
#pragma unroll
    for (int m = 0; m < 4; ++m) sA[DP(t+256*m)] = s[t+256*m];
    __syncthreads();
    float2* X = sA; float2* Y = sB;
    fft5<0>(X, Y, tw, t);
#pragma unroll
    for (int m = 0; m < 4; ++m) {
        int q = t + 256*m;
        size_t i = base1 + q;
        float2 v = X[DP(q)];
        float mk = g_MASKT[i];
        float2 f0 = g_F0T[i];
        g_G[i] = make_float2(mk*(2.f*f0.x - mk*v.x), mk*(2.f*f0.y - mk*v.y));
    }
    if (j != 0 && j != 512) {
        int p2 = FN - j;
        size_t base2 = ((size_t)batch*FN + p2)*FN;
#pragma unroll
        for (int m = 0; m < 4; ++m) {
            int q = t + 256*m;
            int qr = (FN - q) & (FN-1);
            float2 v = X[DP(qr)];
            v.y = -v.y;
            size_t i = base2 + q;
            float mk = g_MASKT[i];
            float2 f0 = g_F0T[i];
            g_G[i] = make_float2(mk*(2.f*f0.x - mk*v.x), mk*(2.f*f0.y - mk*v.y));
        }
    }
}

// ---- conjugate-pair column solve ----
template<int IT0>
__global__ __launch_bounds__(256) void k_fftsolve(const float2* __restrict__ src,
                                                  float2* __restrict__ dst,
                                                  float scale,
                                                  const float* __restrict__ mmu,
                                                  const float* __restrict__ lam,
                                                  const float* __restrict__ gama)
{
    __shared__ float2 sA[1280];
    __shared__ float2 sB[1280];
    __shared__ float2 tw[1088];
    int t = threadIdx.x;
    int j = blockIdx.x % 513;
    int batch = blockIdx.x / 513;
    for (int i = t; i < FN; i += 256) tw[TP(i)] = g_TW[i];
    float mv = mmu[0], lv = lam[0], gv = gama[0];

    if (j == 0 || j == 512) {
        int p = j;
        size_t base = ((size_t)batch*FN + p)*FN;
        const float2* s = src + base;
#pragma unroll
        for (int m = 0; m < 4; ++m) sA[DP(t+256*m)] = s[t+256*m];
        __syncthreads();
        float2* X = sA; float2* Y = sB;
        fft5<0>(X, Y, tw, t);
        float4 tp = g_TRIG[p];
#pragma unroll
        for (int m = 0; m < 4; ++m) {
            int q = t + 256*m;
            size_t i = base + q;
            float2 v = X[DP(q)];
            float mk = g_MASKT[i];
            float2 g;
            if (IT0) { float2 f0 = g_F0T[i]; g = make_float2(mk*f0.x, mk*f0.y); }
            else      g = g_G[i];
            v.x += mv*g.x;  v.y += mv*g.y;
            X[DP(q)] = uker_div(v, tp, g_TRIG[q], mk, mv, lv, gv);
        }
        __syncthreads();
        fft5<1>(X, Y, tw, t);
        float2* d = dst + base;
#pragma unroll
        for (int m = 0; m < 4; ++m) {
            float2 v = X[DP(t+256*m)];
            d[t+256*m] = make_float2(v.x*scale, v.y*scale);
        }
    } else {
        int p1 = j, p2 = FN - j;
        size_t base1 = ((size_t)batch*FN + p1)*FN;
        size_t base2 = ((size_t)batch*FN + p2)*FN;
        const float2* s = src + base1;
#pragma unroll
        for (int m = 0; m < 4; ++m) sA[DP(t+256*m)] = s[t+256*m];
        __syncthreads();
        float2* X = sA; float2* Y = sB;
        fft5<0>(X, Y, tw, t);
        float4 tp1 = g_TRIG[p1];
        float4 tp2 = g_TRIG[p2];
        float2 stash[4];
#pragma unroll
        for (int m = 0; m < 4; ++m) {
            int q = t + 256*m;
            float4 tq = g_TRIG[q];
            {
                size_t i = base1 + q;
                float2 v = X[DP(q)];
                float mk = g_MASKT[i];
                float2 g;
                if (IT0) { float2 f0 = g_F0T[i]; g = make_float2(mk*f0.x, mk*f0.y); }
                else      g = g_G[i];
                v.x += mv*g.x;  v.y += mv*g.y;
                stash[m] = uker_div(v, tp1, tq, mk, mv, lv, gv);
            }
            {
                int qr = (FN - q) & (FN-1);
                float2 v = X[DP(qr)];
                v.y = -v.y;
                size_t i = base2 + q;
                float mk = g_MASKT[i];
                float2 g;
                if (IT0) { float2 f0 = g_F0T[i]; g = make_float2(mk*f0.x, mk*f0.y); }
                else      g = g_G[i];
                v.x += mv*g.x;  v.y += mv*g.y;
                Y[DP(q)] = uker_div(v, tp2, tq, mk, mv, lv, gv);
            }
        }
        __syncthreads();
        {
            float2* Xi = Y; float2* Yi = X;
            fft5<1>(Xi, Yi, tw, t);
            float2* d = dst + base2;
#pragma unroll
            for (int m = 0; m < 4; ++m) {
                float2 v = Xi[DP(t+256*m)];
                d[t+256*m] = make_float2(v.x*scale, v.y*scale);
            }
        }
        __syncthreads();
#pragma unroll
        for (int m = 0; m < 4; ++m) sA[DP(t+256*m)] = stash[m];
        __syncthreads();
        {
            float2* Xi = sA; float2* Yi = sB;
            fft5<1>(Xi, Yi, tw, t);
            float2* d = dst + base1;
#pragma unroll
            for (int m = 0; m < 4; ++m) {
                float2 v = Xi[DP(t+256*m)];
                d[t+256*m] = make_float2(v.x*scale, v.y*scale);
            }
        }
    }
}

// ---------------- transposes ----------------
__global__ void k_transpose_c(const float2* __restrict__ src, float2* __restrict__ dst)
{
    __shared__ float2 tile[32][33];
    int b = blockIdx.z;
    const float2* s = src + (size_t)b*FNN;
    float2* d = dst + (size_t)b*FNN;
    int x  = blockIdx.x*32 + threadIdx.x;
    int y0 = blockIdx.y*32 + threadIdx.y;
#pragma unroll
    for (int i = 0; i < 32; i += 8)
        tile[threadIdx.y+i][threadIdx.x] = s[(size_t)(y0+i)*FN + x];
    __syncthreads();
    int x2 = blockIdx.y*32 + threadIdx.x;
    int y2 = blockIdx.x*32 + threadIdx.y;
#pragma unroll
    for (int i = 0; i < 32; i += 8)
        d[(size_t)(y2+i)*FN + x2] = tile[threadIdx.x][threadIdx.y+i];
}

// merged init: maskT + F0T in one launch
__global__ void k_initT(const float* __restrict__ mask,
                        const float* __restrict__ fr, const float* __restrict__ fi)
{
    __shared__ float tm[32][33];
    __shared__ float tr[32][33];
    __shared__ float ti[32][33];
    int b = blockIdx.z;
    const float* sm = mask + (size_t)b*FNN;
    const float* sr = fr + (size_t)b*FNN;
    const float* si = fi + (size_t)b*FNN;
    int x  = blockIdx.x*32 + threadIdx.x;
    int y0 = blockIdx.y*32 + threadIdx.y;
#pragma unroll
    for (int i = 0; i < 32; i += 8) {
        size_t idx = (size_t)(y0+i)*FN + x;
        tm[threadIdx.y+i][threadIdx.x] = sm[idx];
        tr[threadIdx.y+i][threadIdx.x] = sr[idx];
        ti[threadIdx.y+i][threadIdx.x] = si[idx];
    }
    __syncthreads();
    int x2 = blockIdx.y*32 + threadIdx.x;
    int y2 = blockIdx.x*32 + threadIdx.y;
    size_t ob = (size_t)b*FNN;
#pragma unroll
    for (int i = 0; i < 32; i += 8) {
        size_t idx = ob + (size_t)(y2+i)*FN + x2;
        g_MASKT[idx] = tm[threadIdx.x][threadIdx.y+i];
        g_F0T[idx] = make_float2(tr[threadIdx.x][threadIdx.y+i],
                                 ti[threadIdx.x][threadIdx.y+i]);
    }
}

// ---------------- it0 b-update ----------------
__global__ void k_shrinkbxy0()
{
    int i = blockIdx.x*blockDim.x + threadIdx.x;
    if (i >= TOT) return;
    int x = i & (FN-1);
    int y = (i >> 10) & (FN-1);
    int rowb = i - x;
    float dxu = 0.f;
    if (x >= 1) {
        int xm = (x == 1) ? FN-1 : x-1;
        dxu = g_U[i] - g_U[rowb + xm];
    }
    float dyu = 0.f;
    if (y >= 1) {
        int ym = (y == 1) ? FN-1 : y-1;
        dyu = g_U[i] - g_U[i + (ym - y)*FN];
    }
    g_DX[i] = 0.f;  g_DY[i] = 0.f;
    g_BX[i] = dxu;  g_BY[i] = dyu;
}

// ---------------- DWT row analysis ----------------
__global__ __launch_bounds__(256) void k_afb_w(const float* __restrict__ src,
                                               float* __restrict__ lo,
                                               float* __restrict__ hi)
{
    __shared__ float rs[FN];
    int t = threadIdx.x;
    int r = blockIdx.x;
    const float* row = src + (size_t)r*FN;
#pragma unroll
    for (int m = 0; m < 4; ++m) rs[t+256*m] = row[t+256*m];
    __syncthreads();
    size_t ob = (size_t)r*WD;
    for (int o = t; o < WD; o += 256) {
        float l = 0.f, h = 0.f;
        if (o >= 6 && o <= 505) {
            int j0 = 2*o - 12;
#pragma unroll
            for (int k = 0; k < 14; ++k) {
                float v = rs[j0 + k];
                l += v * cH0A[k];
                h += v * cH1A[k];
            }
        } else {
#pragma unroll
            for (int k = 0; k < 14; ++k) {
                int j = 2*o + k - 12;
                j = (j < 0) ? -j : ((j >= FN) ? (2*FN - 2 - j) : j);
                float v = rs[j];
                l += v * cH0A[k];
                h += v * cH1A[k];
            }
        }
        lo[ob + o] = l;
        hi[ob + o] = h;
    }
}

// column DWT for init: both halves in one launch
__global__ void k_afb_h2()
{
    int i = blockIdx.x*blockDim.x + threadIdx.x;
    if (i >= 2*SLL) return;
    const float* src;
    float *lo, *hi;
    int ii = i;
    if (i < SLL) {
        src = g_LOT; lo = g_WL; hi = g_WH;
    } else {
        ii -= SLL;
        src = g_HIT; lo = g_WH + (size_t)SLL; hi = g_WH + (size_t)2*SLL;
    }
    int w = ii % WD;
    int o = (ii / WD) % WD;
    int b = ii / (WD*WD);
    const float* base = src + (size_t)b*FN*WD;
    float l = 0.f, h = 0.f;
    if (o >= 6 && o <= 505) {
        const float* pp = base + (size_t)(2*o - 12)*WD + w;
#pragma unroll
        for (int k = 0; k < 14; ++k) {
            float v = pp[(size_t)k*WD];
            l += v * cH0A[k];
            h += v * cH1A[k];
        }
    } else {
#pragma unroll
        for (int k = 0; k < 14; ++k) {
            int j = 2*o + k - 12;
            j = (j < 0) ? -j : ((j >= FN) ? (2*FN - 2 - j) : j);
            float v = base[(size_t)j*WD + w];
            l += v * cH0A[k];
            h += v * cH1A[k];
        }
    }
    lo[ii] = l;
    hi[ii] = h;
}

// column DWT + w/b update (it0 only: old bw = 0)
__global__ void k_afb_h_w2(const float* __restrict__ gama,
                           const float* __restrict__ prelu)
{
    int i = blockIdx.x*blockDim.x + threadIdx.x;
    if (i >= 2*SLL) return;
    const float* src;
    float *bwLo, *wLo, *bwHi, *wHi;
    int ii = i;
    if (i < SLL) {
        src = g_LOT;
        bwLo = g_BWL; wLo = g_WL;
        bwHi = g_BWH; wHi = g_WH;
    } else {
        ii -= SLL;
        src = g_HIT;
        bwLo = g_BWH + (size_t)SLL;   wLo = g_WH + (size_t)SLL;
        bwHi = g_BWH + (size_t)2*SLL; wHi = g_WH + (size_t)2*SLL;
    }
    int w = ii % WD;
    int o = (ii / WD) % WD;
    int b = ii / (WD*WD);
    const float* base = src + (size_t)b*FN*WD;
    float l = 0.f, h = 0.f;
    if (o >= 6 && o <= 505) {
        const float* pp = base + (size_t)(2*o - 12)*WD + w;
#pragma unroll
        for (int k = 0; k < 14; ++k) {
            float v = pp[(size_t)k*WD];
            l += v * cH0A[k];
            h += v * cH1A[k];
        }
    } else {
#pragma unroll
        for (int k = 0; k < 14; ++k) {
            int j = 2*o + k - 12;
            j = (j < 0) ? -j : ((j >= FN) ? (2*FN - 2 - j) : j);
            float v = base[(size_t)j*WD + w];
            l += v * cH0A[k];
            h += v * cH1A[k];
        }
    }
    float a  = prelu[0];
    float ig = 1.f/gama[0];
    float t  = l - ig;
    float wv = (t >= 0.f) ? t : a*t;
    wLo[ii]  = wv;
    bwLo[ii] = l - wv;
    t  = h - ig;
    wv = (t >= 0.f) ? t : a*t;
    wHi[ii]  = wv;
    bwHi[ii] = h - wv;
}

// ---- IDWT column synthesis, both halves; IT0=1 skips zero B reads ----
template<int IT0>
__global__ void k_sfb_h2()
{
    int half = NB*FN*WD;
    int i = blockIdx.x*blockDim.x + threadIdx.x;
    if (i >= 2*half) return;
    const float *lA, *lB, *hA, *hB;
    float* out;
    int ii = i;
    if (i < half) {
        lA = g_WL;  lB = g_BWL;
        hA = g_WH;  hB = g_BWH;
        out = g_LOS;
    } else {
        ii -= half;
        lA = g_WH + (size_t)SLL;    lB = g_BWH + (size_t)SLL;
        hA = g_WH + (size_t)2*SLL;  hB = g_BWH + (size_t)2*SLL;
        out = g_HIS;
    }
    int w = ii % WD;
    int o = (ii / WD) % FN;
    int b = ii / (FN*WD);
    size_t bb = (size_t)b*WD*WD;
    float acc = 0.f;
    int k0 = (o + 1) & 1;
#pragma unroll
    for (int kk = 0; kk < 7; ++kk) {
        int k = k0 + 2*kk;
        int m = (o + k - 1) >> 1;
        size_t idx = bb + (size_t)m*WD + w;
        float lo = IT0 ? lA[idx] : (lA[idx] - lB[idx]);
        float hi = IT0 ? hA[idx] : (hA[idx] - hB[idx]);
        acc += lo * cG0[k] + hi * cG1[k];
    }
    out[ii] = acc;
}

// ---------------- host orchestration ----------------
static inline int eb(int n) { return (n + 255) / 256; }

extern "C" void kernel_launch(void* const* d_in, const int* in_sizes, int n_in,
                              void* d_out, int out_size)
{
    const float* u_in   = (const float*)d_in[0];
    const float* uvMask = (const float*)d_in[1];
    const float* f_real = (const float*)d_in[3];
    const float* f_imag = (const float*)d_in[4];
    const float* lam    = (const float*)d_in[5];
    const float* gama   = (const float*)d_in[6];
    const float* mmu    = (const float*)d_in[7];
    const float* prelu  = (const float*)d_in[8];
    float* out = (float*)d_out;

    void *pCA, *pCB, *pU, *pLOT, *pHIT;
    cudaGetSymbolAddress(&pCA, g_CA);       cudaGetSymbolAddress(&pCB, g_CB);
    cudaGetSymbolAddress(&pU, g_U);
    cudaGetSymbolAddress(&pLOT, g_LOT);     cudaGetSymbolAddress(&pHIT, g_HIT);

    dim3 tb(32, 8), tg(32, 32, NB);
    const int SOLV = NB*513;
    const int FFTG2 = NB*FN/2;

    // ----- init -----
    k_twinit<<<4, 256>>>();
    k_initT<<<tg, tb>>>(uvMask, f_real, f_imag);

    // dwt2(u_in) -> WL, WH
    k_afb_w<<<NB*FN, 256>>>(u_in, (float*)pLOT, (float*)pHIT);
    k_afb_h2<<<eb(2*SLL), 256>>>();

    // ----- iterations -----
    for (int it = 0; it < 2; ++it) {
        if (it == 0) k_sfb_h2<1><<<eb(2*NB*FN*WD), 256>>>();
        else         k_sfb_h2<0><<<eb(2*NB*FN*WD), 256>>>();

        if (it == 0) k_fwd2<5><<<FFTG2, 256>>>(nullptr, (float2*)pCB, lam, gama);
        else         k_fwd2<4><<<FFTG2, 256>>>(nullptr, (float2*)pCB, lam, gama);
        k_transpose_c<<<tg, tb>>>((float2*)pCB, (float2*)pCA);          // [p][y]
        if (it == 0)
            k_fftsolve<1><<<SOLV, 256>>>((float2*)pCA, (float2*)pCB, 1.f/FN,
                                         mmu, lam, gama);
        else
            k_fftsolve<0><<<SOLV, 256>>>((float2*)pCA, (float2*)pCB, 1.f/FN,
                                         mmu, lam, gama);
        k_transpose_c<<<tg, tb>>>((float2*)pCB, (float2*)pCA);          // [y][p]

        if (it == 0) {
            k_invfwd<<<FFTG2, 256>>>((float2*)pCA, (float2*)pCB, (float*)pU,
                                     (float*)pLOT, (float*)pHIT, 1.f/FN, prelu);
            k_shrinkbxy0<<<eb(TOT), 256>>>();
            k_afb_h_w2<<<eb(2*SLL), 256>>>(gama, prelu);
            k_transpose_c<<<tg, tb>>>((float2*)pCB, (float2*)pCA);      // [p][y]
            k_gpair<<<SOLV, 256>>>((float2*)pCA);
        } else {
            k_inv2r<<<FFTG2, 256>>>((float2*)pCA, out, 1.f/FN, prelu);
        }
    }
    (void)in_sizes; (void)n_in; (void)out_size;
}

// round 17
// speedup vs baseline: 3.1137x; 1.0291x over previous
#include <cuda_runtime.h>
#include <math.h>

#define FN   1024
#define NB   4
#define FNN  (FN*FN)
#define TOT  (NB*FNN)
#define WD   518
#define SLL  (NB*WD*WD)
#define SLW  (NB*FN*WD)
#define PIF  3.14159265358979323846f

#define DP(i) ((i) + ((i)>>2))
#define TP(i) ((i) + ((i)>>4))

// ---------------- static device scratch ----------------
__device__ float2 g_CA[TOT];
__device__ float2 g_CB[TOT];
__device__ float2 g_F0T[TOT];
__device__ float2 g_G[TOT];
__device__ float2 g_TW[FN];
__device__ float4 g_TRIG[FN];

__device__ float g_U[TOT];
__device__ float g_DX[TOT];
__device__ float g_DY[TOT];
__device__ float g_BX[TOT];
__device__ float g_BY[TOT];
__device__ float g_MASKT[TOT];

__device__ float g_WL[SLL];
__device__ float g_BWL[SLL];
__device__ float g_WH[3*SLL];
__device__ float g_BWH[3*SLL];
__device__ float g_LOT[SLW];
__device__ float g_HIT[SLW];
__device__ float g_LOS[SLW];
__device__ float g_HIS[SLW];

// ---------------- wavelet filters (db7, L=14) ----------------
__constant__ float cH0A[14] = {
    0.010268176708511255f, 0.004010244871533663f, -0.10780823770381774f,
   -0.14004724044296152f, 0.2886296317515146f, 0.767764317003164f,
    0.5361019170917628f, 0.017441255086855827f, -0.049552834937127255f,
    0.0678926935013727f, 0.03051551316596357f, -0.01263630340325193f,
   -0.0010473848886829163f, 0.002681814568257878f };
__constant__ float cH1A[14] = {
    0.002681814568257878f, 0.0010473848886829163f, -0.01263630340325193f,
   -0.03051551316596357f, 0.0678926935013727f, 0.049552834937127255f,
    0.017441255086855827f, -0.5361019170917628f, 0.767764317003164f,
   -0.2886296317515146f, -0.14004724044296152f, 0.10780823770381774f,
    0.004010244871533663f, -0.010268176708511255f };
__constant__ float cG0[14] = {
    0.002681814568257878f, -0.0010473848886829163f, -0.01263630340325193f,
    0.03051551316596357f, 0.0678926935013727f, -0.049552834937127255f,
    0.017441255086855827f, 0.5361019170917628f, 0.767764317003164f,
    0.2886296317515146f, -0.14004724044296152f, -0.10780823770381774f,
    0.004010244871533663f, 0.010268176708511255f };
__constant__ float cG1[14] = {
   -0.010268176708511255f, 0.004010244871533663f, 0.10780823770381774f,
   -0.14004724044296152f, -0.2886296317515146f, 0.767764317003164f,
   -0.5361019170917628f, 0.017441255086855827f, 0.049552834937127255f,
    0.0678926935013727f, -0.03051551316596357f, -0.01263630340325193f,
    0.0010473848886829163f, 0.002681814568257878f };

__device__ __forceinline__ float2 cmulf(float2 a, float2 b) {
    return make_float2(a.x*b.x - a.y*b.y, a.x*b.y + a.y*b.x);
}

__global__ void k_twinit()
{
    int j = blockIdx.x*blockDim.x + threadIdx.x;
    if (j >= FN) return;
    float th = 2.f*PIF*(float)j/(float)FN;
    float sv, cv; sincosf(-th, &sv, &cv);
    g_TW[j] = make_float2(cv, sv);
    float s1, c1, s2, c2;
    sincosf(th, &s1, &c1);
    sincosf(2.f*th, &s2, &c2);
    g_TRIG[j] = make_float4(c1, s1, c2, s2);
}

template<int INV>
__device__ __forceinline__ void r4stage(const float2* __restrict__ X,
                                        float2* __restrict__ Y,
                                        const float2* __restrict__ tw,
                                        int t, int s)
{
    int ns = 1 << (2*s);
    int k  = t & (ns - 1);
    int j  = ((t - k) << 2) + k;
    int sh = 8 - 2*s;
    float2 c0 = X[DP(t)], c1 = X[DP(t+256)], c2 = X[DP(t+512)], c3 = X[DP(t+768)];
    float2 w1 = tw[TP(k << sh)];
    float2 w2 = tw[TP((2*k) << sh)];
    float2 w3 = tw[TP((3*k) << sh)];
    if (INV) { w1.y = -w1.y; w2.y = -w2.y; w3.y = -w3.y; }
    c1 = cmulf(c1, w1); c2 = cmulf(c2, w2); c3 = cmulf(c3, w3);
    float2 t0 = make_float2(c0.x+c2.x, c0.y+c2.y);
    float2 t1 = make_float2(c0.x-c2.x, c0.y-c2.y);
    float2 t2 = make_float2(c1.x+c3.x, c1.y+c3.y);
    float2 dd = make_float2(c1.x-c3.x, c1.y-c3.y);
    float2 t3 = INV ? make_float2(-dd.y, dd.x) : make_float2(dd.y, -dd.x);
    Y[DP(j)]      = make_float2(t0.x+t2.x, t0.y+t2.y);
    Y[DP(j+ns)]   = make_float2(t1.x+t3.x, t1.y+t3.y);
    Y[DP(j+2*ns)] = make_float2(t0.x-t2.x, t0.y-t2.y);
    Y[DP(j+3*ns)] = make_float2(t1.x-t3.x, t1.y-t3.y);
}

template<int INV>
__device__ __forceinline__ void fft5(float2*& X, float2*& Y,
                                     const float2* __restrict__ tw, int t)
{
#pragma unroll
    for (int s = 0; s < 5; ++s) {
        r4stage<INV>(X, Y, tw, t, s);
        __syncthreads();
        float2* tmp = X; X = Y; Y = tmp;
    }
}

__device__ __forceinline__ float2 uker_div(float2 v, float4 tp, float4 tq,
                                           float mk, float mv, float lv, float gv)
{
    float Br = 4.f - tp.x - tq.x - tp.z - tq.z;
    float Bi = tp.y + tq.y - tp.w - tq.w;
    float cf = tp.x*tq.x - tp.y*tq.y;
    float sf = tp.y*tq.x + tp.x*tq.y;
    float2 w = make_float2(mv*mk*mk + gv + lv*(Br*cf + Bi*sf),
                           lv*(Bi*cf - Br*sf));
    float d = 1.f/(w.x*w.x + w.y*w.y);
    return make_float2((v.x*w.x + v.y*w.y)*d, (v.y*w.x - v.x*w.y)*d);
}

template<int GRAD>
__device__ __forceinline__ float rhs_val(size_t base, int x, int y,
                                         float lv, float gv,
                                         const float* __restrict__ lrow,
                                         const float* __restrict__ hrow)
{
    float grad = 0.f;
    if (GRAD) {
        size_t i = base + x;
        float dxt = 0.f;
        if (x >= 1) {
            int xn = (x == FN-1) ? 1 : x+1;
            dxt = (g_DX[i] - g_BX[i]) - (g_DX[base+xn] - g_BX[base+xn]);
        }
        float dyt = 0.f;
        if (y >= 1) {
            int yn = (y == FN-1) ? 1 : y+1;
            size_t jj = i + (size_t)(yn - y)*FN;
            dyt = (g_DY[i] - g_BY[i]) - (g_DY[jj] - g_BY[jj]);
        }
        grad = lv*(dxt + dyt);
    }
    float idwt = 0.f;
    int k0 = (x + 1) & 1;
#pragma unroll
    for (int kk = 0; kk < 7; ++kk) {
        int k = k0 + 2*kk;
        int mm = (x + k - 1) >> 1;
        idwt += lrow[mm] * cG0[k] + hrow[mm] * cG1[k];
    }
    return grad + gv*idwt;
}

// ---- forward 2-for-1: two REAL rows per block -> two full spectra
template<int PRE>
__global__ __launch_bounds__(256) void k_fwd2(const float* __restrict__ srcv,
                                              float2* __restrict__ dst,
                                              const float* __restrict__ lam,
                                              const float* __restrict__ gama)
{
    __shared__ float2 sA[1280];
    __shared__ float2 sB[1280];
    __shared__ float2 tw[1088];
    int t = threadIdx.x;
    int r0 = 2*blockIdx.x;
    size_t base0 = (size_t)r0*FN;
    size_t base1 = base0 + FN;
    for (int j = t; j < FN; j += 256) tw[TP(j)] = g_TW[j];
    if (PRE == 0) {
        const float* s0 = srcv + base0;
        const float* s1 = srcv + base1;
#pragma unroll
        for (int m = 0; m < 4; ++m) {
            int x = t + 256*m;
            sA[DP(x)] = make_float2(s0[x], s1[x]);
        }
    } else {
        int y0 = r0 & (FN-1);
        float lv = lam[0], gv = gama[0];
        const float* l0 = g_LOS + (size_t)r0*WD;
        const float* h0 = g_HIS + (size_t)r0*WD;
        const float* l1 = l0 + WD;
        const float* h1 = h0 + WD;
#pragma unroll
        for (int m = 0; m < 4; ++m) {
            int x = t + 256*m;
            float a, b;
            if (PRE == 4) {
                a = rhs_val<1>(base0, x, y0,     lv, gv, l0, h0);
                b = rhs_val<1>(base1, x, y0 + 1, lv, gv, l1, h1);
            } else {
                a = rhs_val<0>(base0, x, y0,     lv, gv, l0, h0);
                b = rhs_val<0>(base1, x, y0 + 1, lv, gv, l1, h1);
            }
            sA[DP(x)] = make_float2(a, b);
        }
    }
    __syncthreads();
    float2* X = sA; float2* Y = sB;
    fft5<0>(X, Y, tw, t);
    float2* d0 = dst + base0;
    float2* d1 = dst + base1;
#pragma unroll
    for (int m = 0; m < 4; ++m) {
        int k  = t + 256*m;
        int kk = (FN - k) & (FN-1);
        float2 Zk = X[DP(k)];
        float2 Zm = X[DP(kk)];
        d0[k] = make_float2(0.5f*(Zk.x + Zm.x), 0.5f*(Zk.y - Zm.y));
        d1[k] = make_float2(0.5f*(Zk.y + Zm.y), 0.5f*(Zm.x - Zk.x));
    }
}

// ---- inverse 2-for-1 w/ symmetrization -> real rows + srelu ----
__global__ __launch_bounds__(256) void k_inv2r(const float2* __restrict__ src,
                                               float* __restrict__ dst,
                                               float scale,
                                               const float* __restrict__ prelu)
{
    __shared__ float2 sA[1280];
    __shared__ float2 sB[1280];
    __shared__ float2 tw[1088];
    int t = threadIdx.x;
    int r0 = 2*blockIdx.x;
    size_t base0 = (size_t)r0*FN;
    size_t base1 = base0 + FN;
    for (int j = t; j < FN; j += 256) tw[TP(j)] = g_TW[j];
    const float2* s0 = src + base0;
    const float2* s1 = src + base1;
#pragma unroll
    for (int m = 0; m < 4; ++m) {
        int x = t + 256*m;
        int xr = (FN - x) & (FN-1);
        float2 a  = s0[x],  b  = s1[x];
        float2 ar = s0[xr], br = s1[xr];
        sA[DP(x)] = make_float2(0.5f*(a.x + ar.x - b.y + br.y),
                                0.5f*(a.y - ar.y + b.x + br.x));
    }
    __syncthreads();
    float2* X = sA; float2* Y = sB;
    fft5<1>(X, Y, tw, t);
    float a = prelu[0];
    float* d0 = dst + base0;
    float* d1 = dst + base1;
#pragma unroll
    for (int m = 0; m < 4; ++m) {
        int x = t + 256*m;
        float2 z = X[DP(x)];
        float v0 = z.x*scale;
        float v1 = z.y*scale;
        d0[x] = (v0 >= 0.f) ? v0 : a*v0;
        d1[x] = (v1 >= 0.f) ? v1 : a*v1;
    }
}

// ---- it0 mega-kernel: inv FFT -> srelu -> u -> row-DWT -> fwd FFT -> spectra
__global__ __launch_bounds__(256) void k_invfwd(const float2* __restrict__ src,
                                                float2* __restrict__ dstspec,
                                                float* __restrict__ uout,
                                                float* __restrict__ lo,
                                                float* __restrict__ hi,
                                                float scale,
                                                const float* __restrict__ prelu)
{
    __shared__ float2 sA[1280];
    __shared__ float2 sB[1280];
    __shared__ float2 tw[1088];
    int t = threadIdx.x;
    int r0 = 2*blockIdx.x;
    size_t base0 = (size_t)r0*FN;
    size_t base1 = base0 + FN;
    for (int j = t; j < FN; j += 256) tw[TP(j)] = g_TW[j];
    const float2* s0 = src + base0;
    const float2* s1 = src + base1;
#pragma unroll
    for (int m = 0; m < 4; ++m) {
        int x = t + 256*m;
        int xr = (FN - x) & (FN-1);
        float2 a  = s0[x],  b  = s1[x];
        float2 ar = s0[xr], br = s1[xr];
        sA[DP(x)] = make_float2(0.5f*(a.x + ar.x - b.y + br.y),
                                0.5f*(a.y - ar.y + b.x + br.x));
    }
    __syncthreads();
    float2* X = sA; float2* Y = sB;
    fft5<1>(X, Y, tw, t);
    {
        float a = prelu[0];
        float* d0 = uout + base0;
        float* d1 = uout + base1;
#pragma unroll
        for (int m = 0; m < 4; ++m) {
            int x = t + 256*m;
            float2 z = X[DP(x)];
            float v0 = z.x*scale;
            float v1 = z.y*scale;
            v0 = (v0 >= 0.f) ? v0 : a*v0;
            v1 = (v1 >= 0.f) ? v1 : a*v1;
            d0[x] = v0;
            d1[x] = v1;
            X[DP(x)] = make_float2(v0, v1);
        }
    }
    __syncthreads();
    {
        size_t ob0 = (size_t)r0*WD;
        size_t ob1 = ob0 + WD;
        for (int o = t; o < WD; o += 256) {
            float l0 = 0.f, h0 = 0.f, l1 = 0.f, h1 = 0.f;
            if (o >= 6 && o <= 505) {
                int j0 = 2*o - 12;
#pragma unroll
                for (int k = 0; k < 14; ++k) {
                    float2 v = X[DP(j0 + k)];
                    l0 += v.x * cH0A[k];  h0 += v.x * cH1A[k];
                    l1 += v.y * cH0A[k];  h1 += v.y * cH1A[k];
                }
            } else {
#pragma unroll
                for (int k = 0; k < 14; ++k) {
                    int j = 2*o + k - 12;
                    j = (j < 0) ? -j : ((j >= FN) ? (2*FN - 2 - j) : j);
                    float2 v = X[DP(j)];
                    l0 += v.x * cH0A[k];  h0 += v.x * cH1A[k];
                    l1 += v.y * cH0A[k];  h1 += v.y * cH1A[k];
                }
            }
            lo[ob0 + o] = l0;  hi[ob0 + o] = h0;
            lo[ob1 + o] = l1;  hi[ob1 + o] = h1;
        }
    }
    __syncthreads();
    fft5<0>(X, Y, tw, t);
    float2* d0 = dstspec + base0;
    float2* d1 = dstspec + base1;
#pragma unroll
    for (int m = 0; m < 4; ++m) {
        int k  = t + 256*m;
        int kk = (FN - k) & (FN-1);
        float2 Zk = X[DP(k)];
        float2 Zm = X[DP(kk)];
        d0[k] = make_float2(0.5f*(Zk.x + Zm.x), 0.5f*(Zk.y - Zm.y));
        d1[k] = make_float2(0.5f*(Zk.y + Zm.y), 0.5f*(Zm.x - Zk.x));
    }
}

// ---- conjugate-pair G' pass ----
__global__ __launch_bounds__(256) void k_gpair(const float2* __restrict__ src)
{
    __shared__ float2 sA[1280];
    __shared__ float2 sB[1280];
    __shared__ float2 tw[1088];
    int t = threadIdx.x;
    int j = blockIdx.x % 513;
    int batch = blockIdx.x / 513;
    for (int i = t; i < FN; i += 256) tw[TP(i)] = g_TW[i];

    int p1 = j;
    size_t base1 = ((size_t)batch*FN + p1)*FN;
    const float2* s = src + base1;
#pragma unroll
    for (int m = 0; m < 4; ++m) sA[DP(t+256*m)] = s[t+256*m];
    __syncthreads();
    float2* X = sA; float2* Y = sB;
    fft5<0>(X, Y, tw, t);
#pragma unroll
    for (int m = 0; m < 4; ++m) {
        int q = t + 256*m;
        size_t i = base1 + q;
        float2 v = X[DP(q)];
        float mk = g_MASKT[i];
        float2 f0 = g_F0T[i];
        g_G[i] = make_float2(mk*(2.f*f0.x - mk*v.x), mk*(2.f*f0.y - mk*v.y));
    }
    if (j != 0 && j != 512) {
        int p2 = FN - j;
        size_t base2 = ((size_t)batch*FN + p2)*FN;
#pragma unroll
        for (int m = 0; m < 4; ++m) {
            int q = t + 256*m;
            int qr = (FN - q) & (FN-1);
            float2 v = X[DP(qr)];
            v.y = -v.y;
            size_t i = base2 + q;
            float mk = g_MASKT[i];
            float2 f0 = g_F0T[i];
            g_G[i] = make_float2(mk*(2.f*f0.x - mk*v.x), mk*(2.f*f0.y - mk*v.y));
        }
    }
}

// ---- conjugate-pair column solve ----
template<int IT0>
__global__ __launch_bounds__(256) void k_fftsolve(const float2* __restrict__ src,
                                                  float2* __restrict__ dst,
                                                  float scale,
                                                  const float* __restrict__ mmu,
                                                  const float* __restrict__ lam,
                                                  const float* __restrict__ gama)
{
    __shared__ float2 sA[1280];
    __shared__ float2 sB[1280];
    __shared__ float2 tw[1088];
    int t = threadIdx.x;
    int j = blockIdx.x % 513;
    int batch = blockIdx.x / 513;
    for (int i = t; i < FN; i += 256) tw[TP(i)] = g_TW[i];
    float mv = mmu[0], lv = lam[0], gv = gama[0];

    if (j == 0 || j == 512) {
        int p = j;
        size_t base = ((size_t)batch*FN + p)*FN;
        const float2* s = src + base;
#pragma unroll
        for (int m = 0; m < 4; ++m) sA[DP(t+256*m)] = s[t+256*m];
        __syncthreads();
        float2* X = sA; float2* Y = sB;
        fft5<0>(X, Y, tw, t);
        float4 tp = g_TRIG[p];
#pragma unroll
        for (int m = 0; m < 4; ++m) {
            int q = t + 256*m;
            size_t i = base + q;
            float2 v = X[DP(q)];
            float mk = g_MASKT[i];
            float2 g;
            if (IT0) { float2 f0 = g_F0T[i]; g = make_float2(mk*f0.x, mk*f0.y); }
            else      g = g_G[i];
            v.x += mv*g.x;  v.y += mv*g.y;
            X[DP(q)] = uker_div(v, tp, g_TRIG[q], mk, mv, lv, gv);
        }
        __syncthreads();
        fft5<1>(X, Y, tw, t);
        float2* d = dst + base;
#pragma unroll
        for (int m = 0; m < 4; ++m) {
            float2 v = X[DP(t+256*m)];
            d[t+256*m] = make_float2(v.x*scale, v.y*scale);
        }
    } else {
        int p1 = j, p2 = FN - j;
        size_t base1 = ((size_t)batch*FN + p1)*FN;
        size_t base2 = ((size_t)batch*FN + p2)*FN;
        const float2* s = src + base1;
#pragma unroll
        for (int m = 0; m < 4; ++m) sA[DP(t+256*m)] = s[t+256*m];
        __syncthreads();
        float2* X = sA; float2* Y = sB;
        fft5<0>(X, Y, tw, t);
        float4 tp1 = g_TRIG[p1];
        float4 tp2 = g_TRIG[p2];
        float2 stash[4];
#pragma unroll
        for (int m = 0; m < 4; ++m) {
            int q = t + 256*m;
            float4 tq = g_TRIG[q];
            {
                size_t i = base1 + q;
                float2 v = X[DP(q)];
                float mk = g_MASKT[i];
                float2 g;
                if (IT0) { float2 f0 = g_F0T[i]; g = make_float2(mk*f0.x, mk*f0.y); }
                else      g = g_G[i];
                v.x += mv*g.x;  v.y += mv*g.y;
                stash[m] = uker_div(v, tp1, tq, mk, mv, lv, gv);
            }
            {
                int qr = (FN - q) & (FN-1);
                float2 v = X[DP(qr)];
                v.y = -v.y;
                size_t i = base2 + q;
                float mk = g_MASKT[i];
                float2 g;
                if (IT0) { float2 f0 = g_F0T[i]; g = make_float2(mk*f0.x, mk*f0.y); }
                else      g = g_G[i];
                v.x += mv*g.x;  v.y += mv*g.y;
                Y[DP(q)] = uker_div(v, tp2, tq, mk, mv, lv, gv);
            }
        }
        __syncthreads();
        {
            float2* Xi = Y; float2* Yi = X;
            fft5<1>(Xi, Yi, tw, t);
            float2* d = dst + base2;
#pragma unroll
            for (int m = 0; m < 4; ++m) {
                float2 v = Xi[DP(t+256*m)];
                d[t+256*m] = make_float2(v.x*scale, v.y*scale);
            }
        }
        __syncthreads();
#pragma unroll
        for (int m = 0; m < 4; ++m) sA[DP(t+256*m)] = stash[m];
        __syncthreads();
        {
            float2* Xi = sA; float2* Yi = sB;
            fft5<1>(Xi, Yi, tw, t);
            float2* d = dst + base1;
#pragma unroll
            for (int m = 0; m < 4; ++m) {
                float2 v = Xi[DP(t+256*m)];
                d[t+256*m] = make_float2(v.x*scale, v.y*scale);
            }
        }
    }
}

// ---------------- transposes ----------------
__global__ void k_transpose_c(const float2* __restrict__ src, float2* __restrict__ dst)
{
    __shared__ float2 tile[32][33];
    int b = blockIdx.z;
    const float2* s = src + (size_t)b*FNN;
    float2* d = dst + (size_t)b*FNN;
    int x  = blockIdx.x*32 + threadIdx.x;
    int y0 = blockIdx.y*32 + threadIdx.y;
#pragma unroll
    for (int i = 0; i < 32; i += 8)
        tile[threadIdx.y+i][threadIdx.x] = s[(size_t)(y0+i)*FN + x];
    __syncthreads();
    int x2 = blockIdx.y*32 + threadIdx.x;
    int y2 = blockIdx.x*32 + threadIdx.y;
#pragma unroll
    for (int i = 0; i < 32; i += 8)
        d[(size_t)(y2+i)*FN + x2] = tile[threadIdx.x][threadIdx.y+i];
}

// merged init: maskT + F0T
__global__ void k_initT(const float* __restrict__ mask,
                        const float* __restrict__ fr, const float* __restrict__ fi)
{
    __shared__ float tm[32][33];
    __shared__ float tr[32][33];
    __shared__ float ti[32][33];
    int b = blockIdx.z;
    const float* sm = mask + (size_t)b*FNN;
    const float* sr = fr + (size_t)b*FNN;
    const float* si = fi + (size_t)b*FNN;
    int x  = blockIdx.x*32 + threadIdx.x;
    int y0 = blockIdx.y*32 + threadIdx.y;
#pragma unroll
    for (int i = 0; i < 32; i += 8) {
        size_t idx = (size_t)(y0+i)*FN + x;
        tm[threadIdx.y+i][threadIdx.x] = sm[idx];
        tr[threadIdx.y+i][threadIdx.x] = sr[idx];
        ti[threadIdx.y+i][threadIdx.x] = si[idx];
    }
    __syncthreads();
    int x2 = blockIdx.y*32 + threadIdx.x;
    int y2 = blockIdx.x*32 + threadIdx.y;
    size_t ob = (size_t)b*FNN;
#pragma unroll
    for (int i = 0; i < 32; i += 8) {
        size_t idx = ob + (size_t)(y2+i)*FN + x2;
        g_MASKT[idx] = tm[threadIdx.x][threadIdx.y+i];
        g_F0T[idx] = make_float2(tr[threadIdx.x][threadIdx.y+i],
                                 ti[threadIdx.x][threadIdx.y+i]);
    }
}

// ---------------- it0 b-update ----------------
__global__ void k_shrinkbxy0()
{
    int i = blockIdx.x*blockDim.x + threadIdx.x;
    if (i >= TOT) return;
    int x = i & (FN-1);
    int y = (i >> 10) & (FN-1);
    int rowb = i - x;
    float dxu = 0.f;
    if (x >= 1) {
        int xm = (x == 1) ? FN-1 : x-1;
        dxu = g_U[i] - g_U[rowb + xm];
    }
    float dyu = 0.f;
    if (y >= 1) {
        int ym = (y == 1) ? FN-1 : y-1;
        dyu = g_U[i] - g_U[i + (ym - y)*FN];
    }
    g_DX[i] = 0.f;  g_DY[i] = 0.f;
    g_BX[i] = dxu;  g_BY[i] = dyu;
}

// ---------------- DWT row analysis ----------------
__global__ __launch_bounds__(256) void k_afb_w(const float* __restrict__ src,
                                               float* __restrict__ lo,
                                               float* __restrict__ hi)
{
    __shared__ float rs[FN];
    int t = threadIdx.x;
    int r = blockIdx.x;
    const float* row = src + (size_t)r*FN;
#pragma unroll
    for (int m = 0; m < 4; ++m) rs[t+256*m] = row[t+256*m];
    __syncthreads();
    size_t ob = (size_t)r*WD;
    for (int o = t; o < WD; o += 256) {
        float l = 0.f, h = 0.f;
        if (o >= 6 && o <= 505) {
            int j0 = 2*o - 12;
#pragma unroll
            for (int k = 0; k < 14; ++k) {
                float v = rs[j0 + k];
                l += v * cH0A[k];
                h += v * cH1A[k];
            }
        } else {
#pragma unroll
            for (int k = 0; k < 14; ++k) {
                int j = 2*o + k - 12;
                j = (j < 0) ? -j : ((j >= FN) ? (2*FN - 2 - j) : j);
                float v = rs[j];
                l += v * cH0A[k];
                h += v * cH1A[k];
            }
        }
        lo[ob + o] = l;
        hi[ob + o] = h;
    }
}

// column DWT for init: both halves
__global__ void k_afb_h2()
{
    int i = blockIdx.x*blockDim.x + threadIdx.x;
    if (i >= 2*SLL) return;
    const float* src;
    float *lo, *hi;
    int ii = i;
    if (i < SLL) {
        src = g_LOT; lo = g_WL; hi = g_WH;
    } else {
        ii -= SLL;
        src = g_HIT; lo = g_WH + (size_t)SLL; hi = g_WH + (size_t)2*SLL;
    }
    int w = ii % WD;
    int o = (ii / WD) % WD;
    int b = ii / (WD*WD);
    const float* base = src + (size_t)b*FN*WD;
    float l = 0.f, h = 0.f;
    if (o >= 6 && o <= 505) {
        const float* pp = base + (size_t)(2*o - 12)*WD + w;
#pragma unroll
        for (int k = 0; k < 14; ++k) {
            float v = pp[(size_t)k*WD];
            l += v * cH0A[k];
            h += v * cH1A[k];
        }
    } else {
#pragma unroll
        for (int k = 0; k < 14; ++k) {
            int j = 2*o + k - 12;
            j = (j < 0) ? -j : ((j >= FN) ? (2*FN - 2 - j) : j);
            float v = base[(size_t)j*WD + w];
            l += v * cH0A[k];
            h += v * cH1A[k];
        }
    }
    lo[ii] = l;
    hi[ii] = h;
}

// column DWT + w/b update (it0 only: old bw = 0)
__global__ void k_afb_h_w2(const float* __restrict__ gama,
                           const float* __restrict__ prelu)
{
    int i = blockIdx.x*blockDim.x + threadIdx.x;
    if (i >= 2*SLL) return;
    const float* src;
    float *bwLo, *wLo, *bwHi, *wHi;
    int ii = i;
    if (i < SLL) {
        src = g_LOT;
        bwLo = g_BWL; wLo = g_WL;
        bwHi = g_BWH; wHi = g_WH;
    } else {
        ii -= SLL;
        src = g_HIT;
        bwLo = g_BWH + (size_t)SLL;   wLo = g_WH + (size_t)SLL;
        bwHi = g_BWH + (size_t)2*SLL; wHi = g_WH + (size_t)2*SLL;
    }
    int w = ii % WD;
    int o = (ii / WD) % WD;
    int b = ii / (WD*WD);
    const float* base = src + (size_t)b*FN*WD;
    float l = 0.f, h = 0.f;
    if (o >= 6 && o <= 505) {
        const float* pp = base + (size_t)(2*o - 12)*WD + w;
#pragma unroll
        for (int k = 0; k < 14; ++k) {
            float v = pp[(size_t)k*WD];
            l += v * cH0A[k];
            h += v * cH1A[k];
        }
    } else {
#pragma unroll
        for (int k = 0; k < 14; ++k) {
            int j = 2*o + k - 12;
            j = (j < 0) ? -j : ((j >= FN) ? (2*FN - 2 - j) : j);
            float v = base[(size_t)j*WD + w];
            l += v * cH0A[k];
            h += v * cH1A[k];
        }
    }
    float a  = prelu[0];
    float ig = 1.f/gama[0];
    float t  = l - ig;
    float wv = (t >= 0.f) ? t : a*t;
    wLo[ii]  = wv;
    bwLo[ii] = l - wv;
    t  = h - ig;
    wv = (t >= 0.f) ? t : a*t;
    wHi[ii]  = wv;
    bwHi[ii] = h - wv;
}

// ---- IDWT column synthesis, both halves; IT0=1 skips zero B reads ----
template<int IT0>
__global__ void k_sfb_h2()
{
    int half = NB*FN*WD;
    int i = blockIdx.x*blockDim.x + threadIdx.x;
    if (i >= 2*half) return;
    const float *lA, *lB, *hA, *hB;
    float* out;
    int ii = i;
    if (i < half) {
        lA = g_WL;  lB = g_BWL;
        hA = g_WH;  hB = g_BWH;
        out = g_LOS;
    } else {
        ii -= half;
        lA = g_WH + (size_t)SLL;    lB = g_BWH + (size_t)SLL;
        hA = g_WH + (size_t)2*SLL;  hB = g_BWH + (size_t)2*SLL;
        out = g_HIS;
    }
    int w = ii % WD;
    int o = (ii / WD) % FN;
    int b = ii / (FN*WD);
    size_t bb = (size_t)b*WD*WD;
    float acc = 0.f;
    int k0 = (o + 1) & 1;
#pragma unroll
    for (int kk = 0; kk < 7; ++kk) {
        int k = k0 + 2*kk;
        int m = (o + k - 1) >> 1;
        size_t idx = bb + (size_t)m*WD + w;
        float lo = IT0 ? lA[idx] : (lA[idx] - lB[idx]);
        float hi = IT0 ? hA[idx] : (hA[idx] - hB[idx]);
        acc += lo * cG0[k] + hi * cG1[k];
    }
    out[ii] = acc;
}

// ---------------- host orchestration ----------------
static inline int eb(int n) { return (n + 255) / 256; }

extern "C" void kernel_launch(void* const* d_in, const int* in_sizes, int n_in,
                              void* d_out, int out_size)
{
    const float* u_in   = (const float*)d_in[0];
    const float* uvMask = (const float*)d_in[1];
    const float* f_real = (const float*)d_in[3];
    const float* f_imag = (const float*)d_in[4];
    const float* lam    = (const float*)d_in[5];
    const float* gama   = (const float*)d_in[6];
    const float* mmu    = (const float*)d_in[7];
    const float* prelu  = (const float*)d_in[8];
    float* out = (float*)d_out;

    void *pCA, *pCB, *pU, *pLOT, *pHIT;
    cudaGetSymbolAddress(&pCA, g_CA);       cudaGetSymbolAddress(&pCB, g_CB);
    cudaGetSymbolAddress(&pU, g_U);
    cudaGetSymbolAddress(&pLOT, g_LOT);     cudaGetSymbolAddress(&pHIT, g_HIT);

    dim3 tb(32, 8), tg(32, 32, NB);
    dim3 tgh(17, 32, NB);                   // partial: dst rows 0..543 only
    const int SOLV = NB*513;
    const int FFTG2 = NB*FN/2;

    // ----- init -----
    k_twinit<<<4, 256>>>();
    k_initT<<<tg, tb>>>(uvMask, f_real, f_imag);

    // dwt2(u_in)
    k_afb_w<<<NB*FN, 256>>>(u_in, (float*)pLOT, (float*)pHIT);
    k_afb_h2<<<eb(2*SLL), 256>>>();

    // ----- iterations -----
    for (int it = 0; it < 2; ++it) {
        if (it == 0) k_sfb_h2<1><<<eb(2*NB*FN*WD), 256>>>();
        else         k_sfb_h2<0><<<eb(2*NB*FN*WD), 256>>>();

        if (it == 0) k_fwd2<5><<<FFTG2, 256>>>(nullptr, (float2*)pCB, lam, gama);
        else         k_fwd2<4><<<FFTG2, 256>>>(nullptr, (float2*)pCB, lam, gama);
        // partial transpose: solve only reads rows p in [0,512]
        k_transpose_c<<<tgh, tb>>>((float2*)pCB, (float2*)pCA);         // [p][y]
        if (it == 0)
            k_fftsolve<1><<<SOLV, 256>>>((float2*)pCA, (float2*)pCB, 1.f/FN,
                                         mmu, lam, gama);
        else
            k_fftsolve<0><<<SOLV, 256>>>((float2*)pCA, (float2*)pCB, 1.f/FN,
                                         mmu, lam, gama);
        k_transpose_c<<<tg, tb>>>((float2*)pCB, (float2*)pCA);          // [y][p] full

        if (it == 0) {
            k_invfwd<<<FFTG2, 256>>>((float2*)pCA, (float2*)pCB, (float*)pU,
                                     (float*)pLOT, (float*)pHIT, 1.f/FN, prelu);
            k_shrinkbxy0<<<eb(TOT), 256>>>();
            k_afb_h_w2<<<eb(2*SLL), 256>>>(gama, prelu);
            // partial transpose: gpair only reads rows p in [0,512]
            k_transpose_c<<<tgh, tb>>>((float2*)pCB, (float2*)pCA);     // [p][y]
            k_gpair<<<SOLV, 256>>>((float2*)pCA);
        } else {
            k_inv2r<<<FFTG2, 256>>>((float2*)pCA, out, 1.f/FN, prelu);
        }
    }
    (void)in_sizes; (void)n_in; (void)out_size;
}